// round 7
// baseline (speedup 1.0000x reference)
#include <cuda_runtime.h>
#include <math.h>

// Problem constants
#define NB   16          // batch
#define HH   512
#define WW   512
#define HWp  (HH*WW)     // 262144
#define NHWp (NB*HWp)    // 4194304

// ---------------- device scratch (static, no allocation) ----------------
static __device__ float  g_t [67108864];   // [16,16,512,512] main scratch (268 MB)
static __device__ float  g_x1[ 8388608];   // [16, 8,256,256]
static __device__ float  g_x2[ 4194304];   // [16,16,128,128]
static __device__ double g_sum1[16], g_sq1[16], g_sum2[16], g_sq2[16];
static __device__ double g_vsum[NB*16], g_vsq[NB*16];
static __device__ double g_usum[24], g_usq[24];
static __device__ float  g_a1[16], g_b1[16], g_a2[16], g_b2[16];
static __device__ float  g_au[24], g_bu[24];
static __device__ int    g_idx[NB*3];

__device__ __forceinline__ float sigm(float x){ return 1.0f/(1.0f+expf(-x)); }

// ---------------- K0: zero stat accumulators ----------------
__global__ void k_zero(){
  int t = threadIdx.x;
  if (t < 16){ g_sum1[t]=0.0; g_sq1[t]=0.0; g_sum2[t]=0.0; g_sq2[t]=0.0; }
  if (t < 24){ g_usum[t]=0.0; g_usq[t]=0.0; }
  if (t < 256){ g_vsum[t]=0.0; g_vsq[t]=0.0; }
}

// ---------------- K1: 1x1 conv (10->16) + BN1 stats ----------------
__global__ void __launch_bounds__(256) k_conv1(const float* __restrict__ x,
                                               const float* __restrict__ w,
                                               const float* __restrict__ bias){
  __shared__ float sw[160], sb[16];
  __shared__ double ssum[16], ssq[16];
  int t = threadIdx.x;
  if (t < 160) sw[t] = w[t];
  if (t < 16){ sb[t] = bias[t]; ssum[t]=0.0; ssq[t]=0.0; }
  __syncthreads();

  float s[16], q[16];
#pragma unroll
  for (int c=0;c<16;c++){ s[c]=0.f; q[c]=0.f; }

  int stride = gridDim.x * blockDim.x;
  for (int p = blockIdx.x*blockDim.x + t; p < NHWp; p += stride){
    int n = p >> 18;
    int pix = p & (HWp-1);
    const float* xp = x + (size_t)n*10*HWp + pix;
    float in[10];
#pragma unroll
    for (int i=0;i<10;i++) in[i] = xp[(size_t)i*HWp];
    float* op = g_t + (size_t)n*16*HWp + pix;
#pragma unroll
    for (int c=0;c<16;c++){
      float v = sb[c];
#pragma unroll
      for (int i=0;i<10;i++) v = fmaf(sw[c*10+i], in[i], v);
      op[(size_t)c*HWp] = v;
      s[c] += v; q[c] += v*v;
    }
  }
#pragma unroll
  for (int c=0;c<16;c++){
    float a=s[c], b=q[c];
#pragma unroll
    for (int o=16;o>0;o>>=1){ a += __shfl_down_sync(0xffffffffu,a,o); b += __shfl_down_sync(0xffffffffu,b,o); }
    if ((t&31)==0){ atomicAdd(&ssum[c],(double)a); atomicAdd(&ssq[c],(double)b); }
  }
  __syncthreads();
  if (t<16){ atomicAdd(&g_sum1[t], ssum[t]); atomicAdd(&g_sq1[t], ssq[t]); }
}

// ---------------- K2/K4: finalize BN scale/shift ----------------
__global__ void k_fin(const float* __restrict__ gamma, const float* __restrict__ beta, int which){
  int c = threadIdx.x; if (c >= 16) return;
  double su = (which==0) ? g_sum1[c] : g_sum2[c];
  double sq = (which==0) ? g_sq1[c]  : g_sq2[c];
  double m  = su / (double)NHWp;
  double v  = sq / (double)NHWp - m*m;
  double a  = (double)gamma[c] / sqrt(v + 1e-5);
  float af = (float)a;
  float bf = (float)((double)beta[c] - a*m);
  if (which==0){ g_a1[c]=af; g_b1[c]=bf; } else { g_a2[c]=af; g_b2[c]=bf; }
}

// ---------------- K3: BN1+sigmoid -> 1x1 conv (16->16) in place + BN2 stats ----------------
__global__ void __launch_bounds__(256) k_stage2(const float* __restrict__ w2,
                                                const float* __restrict__ b2){
  __shared__ float sw[256], sbias[16], sa[16], sb[16];
  __shared__ double ssum[16], ssq[16];
  int t = threadIdx.x;
  if (t < 256) sw[t] = w2[t];
  if (t < 16){ sbias[t]=b2[t]; sa[t]=g_a1[t]; sb[t]=g_b1[t]; ssum[t]=0.0; ssq[t]=0.0; }
  __syncthreads();

  float s[16], q[16];
#pragma unroll
  for (int c=0;c<16;c++){ s[c]=0.f; q[c]=0.f; }

  int stride = gridDim.x * blockDim.x;
  for (int p = blockIdx.x*blockDim.x + t; p < NHWp; p += stride){
    int n = p >> 18;
    int pix = p & (HWp-1);
    float* bp = g_t + (size_t)n*16*HWp + pix;
    float y[16];
#pragma unroll
    for (int c=0;c<16;c++){
      float v = bp[(size_t)c*HWp];
      y[c] = sigm(fmaf(sa[c], v, sb[c]));
    }
#pragma unroll
    for (int o=0;o<16;o++){
      float z = sbias[o];
#pragma unroll
      for (int c=0;c<16;c++) z = fmaf(sw[o*16+c], y[c], z);
      bp[(size_t)o*HWp] = z;
      s[o] += z; q[o] += z*z;
    }
  }
#pragma unroll
  for (int c=0;c<16;c++){
    float a=s[c], b=q[c];
#pragma unroll
    for (int o=16;o>0;o>>=1){ a += __shfl_down_sync(0xffffffffu,a,o); b += __shfl_down_sync(0xffffffffu,b,o); }
    if ((t&31)==0){ atomicAdd(&ssum[c],(double)a); atomicAdd(&ssq[c],(double)b); }
  }
  __syncthreads();
  if (t<16){ atomicAdd(&g_sum2[t], ssum[t]); atomicAdd(&g_sq2[t], ssq[t]); }
}

// ---------------- K5: per-(n,c) variance stats of h2 = sigmoid(BN2(z)) ----------------
__global__ void __launch_bounds__(256) k_varstats(){
  const int BPS = 64;                 // blocks per sample
  int n   = blockIdx.x / BPS;
  int blk = blockIdx.x % BPS;
  __shared__ float sa[16], sb[16];
  __shared__ double ssum[16], ssq[16];
  int t = threadIdx.x;
  if (t < 16){ sa[t]=g_a2[t]; sb[t]=g_b2[t]; ssum[t]=0.0; ssq[t]=0.0; }
  __syncthreads();

  float s[16], q[16];
#pragma unroll
  for (int c=0;c<16;c++){ s[c]=0.f; q[c]=0.f; }

  const int per = HWp / BPS;          // 4096
  const float* base = g_t + (size_t)n*16*HWp;
  for (int pix = blk*per + t; pix < (blk+1)*per; pix += 256){
#pragma unroll
    for (int c=0;c<16;c++){
      float h = sigm(fmaf(sa[c], base[(size_t)c*HWp + pix], sb[c]));
      s[c] += h; q[c] += h*h;
    }
  }
#pragma unroll
  for (int c=0;c<16;c++){
    float a=s[c], b=q[c];
#pragma unroll
    for (int o=16;o>0;o>>=1){ a += __shfl_down_sync(0xffffffffu,a,o); b += __shfl_down_sync(0xffffffffu,b,o); }
    if ((t&31)==0){ atomicAdd(&ssum[c],(double)a); atomicAdd(&ssq[c],(double)b); }
  }
  __syncthreads();
  if (t<16){ atomicAdd(&g_vsum[n*16+t], ssum[t]); atomicAdd(&g_vsq[n*16+t], ssq[t]); }
}

// ---------------- K6: top-3 variance channels (stable, descending) ----------------
__global__ void k_topk(){
  int n = threadIdx.x; if (n >= NB) return;
  double var[16];
  for (int c=0;c<16;c++){
    double s = g_vsum[n*16+c], qq = g_vsq[n*16+c];
    double m = s / (double)HWp;
    var[c] = (qq - s*m) / (double)(HWp - 1);   // ddof=1
  }
  int mask = 0;
  for (int k=0;k<3;k++){
    int best = 0; double bv = -1e300;
    for (int c=0;c<16;c++)
      if (!((mask>>c)&1) && var[c] > bv){ bv = var[c]; best = c; }
    mask |= 1<<best;
    g_idx[n*3+k] = best;
  }
}

// ---------------- K7: conv3x3 (3 selected -> 8) + sigmoid + maxpool2 ----------------
__global__ void __launch_bounds__(256) k_conv3a(const float* __restrict__ wc,
                                                const float* __restrict__ bc){
  __shared__ float sp[3][34][36];
  __shared__ float sw[216], sbias[8];
  __shared__ float sa[3], sbb[3];
  __shared__ int   sch[3];
  int n = blockIdx.z;
  int t = threadIdx.x;
  if (t < 216) sw[t] = wc[t];
  if (t < 8)   sbias[t] = bc[t];
  if (t < 3){ int ch = g_idx[n*3+t]; sch[t]=ch; sa[t]=g_a2[ch]; sbb[t]=g_b2[ch]; }
  __syncthreads();

  int gy0 = blockIdx.y*32 - 1, gx0 = blockIdx.x*32 - 1;
  for (int i=t; i < 3*34*34; i += 256){
    int c = i / 1156, rem = i % 1156;
    int r = rem / 34, col = rem % 34;
    int gy = gy0 + r, gx = gx0 + col;
    float v = 0.f;
    if (gy >= 0 && gy < HH && gx >= 0 && gx < WW)
      v = sigm(fmaf(sa[c], g_t[(size_t)(n*16+sch[c])*HWp + gy*WW + gx], sbb[c]));
    sp[c][r][col] = v;
  }
  __syncthreads();

  int tx = t & 15, ty = t >> 4;
  int by = 2*ty, bx = 2*tx;
  float a00[8], a01[8], a10[8], a11[8];
#pragma unroll
  for (int oc=0;oc<8;oc++){ a00[oc]=a01[oc]=a10[oc]=a11[oc]=sbias[oc]; }
#pragma unroll
  for (int c=0;c<3;c++)
#pragma unroll
    for (int ky=0;ky<3;ky++)
#pragma unroll
      for (int kx=0;kx<3;kx++){
        float v00 = sp[c][by+ky  ][bx+kx  ];
        float v01 = sp[c][by+ky  ][bx+kx+1];
        float v10 = sp[c][by+ky+1][bx+kx  ];
        float v11 = sp[c][by+ky+1][bx+kx+1];
#pragma unroll
        for (int oc=0;oc<8;oc++){
          float wv = sw[oc*27 + c*9 + ky*3 + kx];
          a00[oc]=fmaf(v00,wv,a00[oc]); a01[oc]=fmaf(v01,wv,a01[oc]);
          a10[oc]=fmaf(v10,wv,a10[oc]); a11[oc]=fmaf(v11,wv,a11[oc]);
        }
      }
  int py = blockIdx.y*16 + ty, px = blockIdx.x*16 + tx;
#pragma unroll
  for (int oc=0;oc<8;oc++){
    float mx = fmaxf(fmaxf(a00[oc],a01[oc]), fmaxf(a10[oc],a11[oc]));
    g_x1[(size_t)(n*8+oc)*65536 + py*256 + px] = sigm(mx);  // sigmoid monotone: pool-then-sigmoid
  }
}

// ---------------- K8: conv3x3 (8 -> 16) + sigmoid + maxpool2 ----------------
__global__ void __launch_bounds__(256) k_conv3b(const float* __restrict__ wc,
                                                const float* __restrict__ bc){
  __shared__ float sp[8][34][36];    // 39168 B
  __shared__ float sw[1152], sbias[16];
  int n = blockIdx.z;
  int t = threadIdx.x;
  for (int i=t; i<1152; i+=256) sw[i] = wc[i];
  if (t < 16) sbias[t] = bc[t];
  __syncthreads();

  int gy0 = blockIdx.y*32 - 1, gx0 = blockIdx.x*32 - 1;
  for (int i=t; i < 8*34*34; i += 256){
    int c = i / 1156, rem = i % 1156;
    int r = rem / 34, col = rem % 34;
    int gy = gy0 + r, gx = gx0 + col;
    float v = 0.f;
    if (gy >= 0 && gy < 256 && gx >= 0 && gx < 256)
      v = g_x1[(size_t)(n*8+c)*65536 + gy*256 + gx];
    sp[c][r][col] = v;
  }
  __syncthreads();

  int tx = t & 15, ty = t >> 4;
  int by = 2*ty, bx = 2*tx;
  float a00[16], a01[16], a10[16], a11[16];
#pragma unroll
  for (int oc=0;oc<16;oc++){ a00[oc]=a01[oc]=a10[oc]=a11[oc]=sbias[oc]; }
#pragma unroll
  for (int c=0;c<8;c++)
#pragma unroll
    for (int ky=0;ky<3;ky++)
#pragma unroll
      for (int kx=0;kx<3;kx++){
        float v00 = sp[c][by+ky  ][bx+kx  ];
        float v01 = sp[c][by+ky  ][bx+kx+1];
        float v10 = sp[c][by+ky+1][bx+kx  ];
        float v11 = sp[c][by+ky+1][bx+kx+1];
#pragma unroll
        for (int oc=0;oc<16;oc++){
          float wv = sw[oc*72 + c*9 + ky*3 + kx];
          a00[oc]=fmaf(v00,wv,a00[oc]); a01[oc]=fmaf(v01,wv,a01[oc]);
          a10[oc]=fmaf(v10,wv,a10[oc]); a11[oc]=fmaf(v11,wv,a11[oc]);
        }
      }
  int py = blockIdx.y*16 + ty, px = blockIdx.x*16 + tx;
#pragma unroll
  for (int oc=0;oc<16;oc++){
    float mx = fmaxf(fmaxf(a00[oc],a01[oc]), fmaxf(a10[oc],a11[oc]));
    g_x2[(size_t)(n*16+oc)*16384 + py*128 + px] = sigm(mx);
  }
}

// ---- bilinear helpers (jax.image.resize half-pixel centers, edge-normalized == clamp) ----
__device__ __forceinline__ void idx_up2(int h, int Hin, int& y0, int& y1, float& f){
  y0 = (h >> 1) - ((h & 1) ^ 1);
  f  = (h & 1) ? 0.25f : 0.75f;
  y1 = min(y0 + 1, Hin - 1);
  y0 = max(y0, 0);
}
__device__ __forceinline__ void idx_up4(int h, int Hin, int& y0, int& y1, float& f){
  int m = h & 3;
  y0 = (h >> 2) - (m < 2 ? 1 : 0);
  f  = (m==0) ? 0.625f : (m==1) ? 0.875f : (m==2) ? 0.125f : 0.375f;
  y1 = min(y0 + 1, Hin - 1);
  y0 = max(y0, 0);
}

// ---------------- K9: stats of relu(upsample) for both BN paths ----------------
__global__ void __launch_bounds__(256) k_upstats(){
  __shared__ double ssum[24], ssq[24];
  int t = threadIdx.x;
  if (t < 24){ ssum[t]=0.0; ssq[t]=0.0; }
  __syncthreads();

  float s[24], q[24];
#pragma unroll
  for (int c=0;c<24;c++){ s[c]=0.f; q[c]=0.f; }

  int stride = gridDim.x * blockDim.x;
  for (int p = blockIdx.x*blockDim.x + t; p < NHWp; p += stride){
    int n = p >> 18, pix = p & (HWp-1);
    int h = pix >> 9, w = pix & 511;
    // x1 path: up2 from 256x256, 8 channels
    {
      int y0,y1,x0,x1; float fy,fx;
      idx_up2(h,256,y0,y1,fy); idx_up2(w,256,x0,x1,fx);
      int o00=y0*256+x0, o01=y0*256+x1, o10=y1*256+x0, o11=y1*256+x1;
      const float* bp = g_x1 + (size_t)n*8*65536;
#pragma unroll
      for (int c=0;c<8;c++){
        const float* pc = bp + (size_t)c*65536;
        float v0 = pc[o00] + fx*(pc[o01]-pc[o00]);
        float v1 = pc[o10] + fx*(pc[o11]-pc[o10]);
        float r  = fmaxf(v0 + fy*(v1-v0), 0.f);
        s[c] += r; q[c] += r*r;
      }
    }
    // x2 path: up4 from 128x128, 16 channels
    {
      int y0,y1,x0,x1; float fy,fx;
      idx_up4(h,128,y0,y1,fy); idx_up4(w,128,x0,x1,fx);
      int o00=y0*128+x0, o01=y0*128+x1, o10=y1*128+x0, o11=y1*128+x1;
      const float* bp = g_x2 + (size_t)n*16*16384;
#pragma unroll
      for (int c=0;c<16;c++){
        const float* pc = bp + (size_t)c*16384;
        float v0 = pc[o00] + fx*(pc[o01]-pc[o00]);
        float v1 = pc[o10] + fx*(pc[o11]-pc[o10]);
        float r  = fmaxf(v0 + fy*(v1-v0), 0.f);
        s[8+c] += r; q[8+c] += r*r;
      }
    }
  }
#pragma unroll
  for (int c=0;c<24;c++){
    float a=s[c], b=q[c];
#pragma unroll
    for (int o=16;o>0;o>>=1){ a += __shfl_down_sync(0xffffffffu,a,o); b += __shfl_down_sync(0xffffffffu,b,o); }
    if ((t&31)==0){ atomicAdd(&ssum[c],(double)a); atomicAdd(&ssq[c],(double)b); }
  }
  __syncthreads();
  if (t<24){ atomicAdd(&g_usum[t], ssum[t]); atomicAdd(&g_usq[t], ssq[t]); }
}

// ---------------- K10: finalize upsample BNs (ch 0-7: bn2, ch 8-23: bn1) ----------------
__global__ void k_finup(const float* __restrict__ gbn1, const float* __restrict__ bbn1,
                        const float* __restrict__ gbn2, const float* __restrict__ bbn2){
  int c = threadIdx.x; if (c >= 24) return;
  double m = g_usum[c] / (double)NHWp;
  double v = g_usq[c]  / (double)NHWp - m*m;
  double gamma = (c < 8) ? (double)gbn2[c] : (double)gbn1[c-8];
  double beta  = (c < 8) ? (double)bbn2[c] : (double)bbn1[c-8];
  double a = gamma / sqrt(v + 1e-5);
  g_au[c] = (float)a;
  g_bu[c] = (float)(beta - a*m);
}

// ---------------- K11: up2/up4 + relu + BN + concat + 1x1 conv (24->5) ----------------
__global__ void __launch_bounds__(256) k_final(const float* __restrict__ w1k,
                                               const float* __restrict__ b1k,
                                               float* __restrict__ out){
  __shared__ float sw[120], sb5[5], sa[24], sbb[24];
  int t = threadIdx.x;
  if (t < 120) sw[t] = w1k[t];
  if (t < 5)   sb5[t] = b1k[t];
  if (t < 24){ sa[t] = g_au[t]; sbb[t] = g_bu[t]; }
  __syncthreads();

  int stride = gridDim.x * blockDim.x;
  for (int p = blockIdx.x*blockDim.x + t; p < NHWp; p += stride){
    int n = p >> 18, pix = p & (HWp-1);
    int h = pix >> 9, w = pix & 511;
    float m[24];
    {
      int y0,y1,x0,x1; float fy,fx;
      idx_up2(h,256,y0,y1,fy); idx_up2(w,256,x0,x1,fx);
      int o00=y0*256+x0, o01=y0*256+x1, o10=y1*256+x0, o11=y1*256+x1;
      const float* bp = g_x1 + (size_t)n*8*65536;
#pragma unroll
      for (int c=0;c<8;c++){
        const float* pc = bp + (size_t)c*65536;
        float v0 = pc[o00] + fx*(pc[o01]-pc[o00]);
        float v1 = pc[o10] + fx*(pc[o11]-pc[o10]);
        float v  = v0 + fy*(v1-v0);
        m[c] = fmaf(sa[c], fmaxf(v,0.f), sbb[c]);
      }
    }
    {
      int y0,y1,x0,x1; float fy,fx;
      idx_up4(h,128,y0,y1,fy); idx_up4(w,128,x0,x1,fx);
      int o00=y0*128+x0, o01=y0*128+x1, o10=y1*128+x0, o11=y1*128+x1;
      const float* bp = g_x2 + (size_t)n*16*16384;
#pragma unroll
      for (int c=0;c<16;c++){
        const float* pc = bp + (size_t)c*16384;
        float v0 = pc[o00] + fx*(pc[o01]-pc[o00]);
        float v1 = pc[o10] + fx*(pc[o11]-pc[o10]);
        float v  = v0 + fy*(v1-v0);
        m[8+c] = fmaf(sa[8+c], fmaxf(v,0.f), sbb[8+c]);
      }
    }
#pragma unroll
    for (int k=0;k<5;k++){
      float o = sb5[k];
#pragma unroll
      for (int c=0;c<24;c++) o = fmaf(sw[k*24+c], m[c], o);
      out[(size_t)(n*5+k)*HWp + pix] = o;
    }
  }
}

// ---------------- launch ----------------
extern "C" void kernel_launch(void* const* d_in, const int* in_sizes, int n_in,
                              void* d_out, int out_size){
  (void)in_sizes; (void)n_in; (void)out_size;
  const float* x       = (const float*)d_in[0];
  const float* w_ext1  = (const float*)d_in[1];
  const float* b_ext1  = (const float*)d_in[2];
  const float* g_ebn1  = (const float*)d_in[3];
  const float* be_ebn1 = (const float*)d_in[4];
  const float* w_ext2  = (const float*)d_in[5];
  const float* b_ext2  = (const float*)d_in[6];
  const float* g_ebn2  = (const float*)d_in[7];
  const float* be_ebn2 = (const float*)d_in[8];
  const float* w_c1    = (const float*)d_in[9];
  const float* b_c1    = (const float*)d_in[10];
  const float* w_c2    = (const float*)d_in[11];
  const float* b_c2    = (const float*)d_in[12];
  const float* g_bn1   = (const float*)d_in[13];
  const float* be_bn1  = (const float*)d_in[14];
  const float* g_bn2   = (const float*)d_in[15];
  const float* be_bn2  = (const float*)d_in[16];
  const float* w_1k    = (const float*)d_in[17];
  const float* b_1k    = (const float*)d_in[18];
  float* out = (float*)d_out;

  const int GS = 1184;  // 8 blocks/SM worth of grid-stride blocks

  k_zero<<<1,256>>>();
  k_conv1<<<GS,256>>>(x, w_ext1, b_ext1);
  k_fin<<<1,16>>>(g_ebn1, be_ebn1, 0);
  k_stage2<<<GS,256>>>(w_ext2, b_ext2);
  k_fin<<<1,16>>>(g_ebn2, be_ebn2, 1);
  k_varstats<<<16*64,256>>>();
  k_topk<<<1,16>>>();
  k_conv3a<<<dim3(16,16,16),256>>>(w_c1, b_c1);
  k_conv3b<<<dim3(8,8,16),256>>>(w_c2, b_c2);
  k_upstats<<<GS,256>>>();
  k_finup<<<1,24>>>(g_bn1, be_bn1, g_bn2, be_bn2);
  k_final<<<GS,256>>>(w_1k, b_1k, out);
}

// round 8
// speedup vs baseline: 1.0202x; 1.0202x over previous
#include <cuda_runtime.h>
#include <math.h>

// Problem constants
#define NB   16          // batch
#define HH   512
#define WW   512
#define HWp  (HH*WW)     // 262144
#define NHWp (NB*HWp)    // 4194304

// ---------------- device scratch (static, no allocation) ----------------
static __device__ float  g_t [67108864];   // [16,16,512,512] main scratch (268 MB)
static __device__ float  g_x1[ 8388608];   // [16, 8,256,256]
static __device__ float  g_x2[ 4194304];   // [16,16,128,128]
static __device__ double g_sum1[16], g_sq1[16], g_sum2[16], g_sq2[16];
static __device__ double g_vsum[NB*16], g_vsq[NB*16];
static __device__ double g_usum[24], g_usq[24];
static __device__ float  g_a1[16], g_b1[16], g_a2[16], g_b2[16];
static __device__ float  g_au[24], g_bu[24];
static __device__ int    g_idx[NB*3];

__device__ __forceinline__ float sigm(float x){ return 1.0f/(1.0f+expf(-x)); }

// ---------------- K0: zero stat accumulators ----------------
__global__ void k_zero(){
  int t = threadIdx.x;
  if (t < 16){ g_sum1[t]=0.0; g_sq1[t]=0.0; g_sum2[t]=0.0; g_sq2[t]=0.0; }
  if (t < 24){ g_usum[t]=0.0; g_usq[t]=0.0; }
  if (t < 256){ g_vsum[t]=0.0; g_vsq[t]=0.0; }
}

// ---------------- K1: 1x1 conv (10->16) + BN1 stats ----------------
__global__ void __launch_bounds__(256) k_conv1(const float* __restrict__ x,
                                               const float* __restrict__ w,
                                               const float* __restrict__ bias){
  __shared__ float sw[160], sb[16];
  __shared__ double ssum[16], ssq[16];
  int t = threadIdx.x;
  if (t < 160) sw[t] = w[t];
  if (t < 16){ sb[t] = bias[t]; ssum[t]=0.0; ssq[t]=0.0; }
  __syncthreads();

  float s[16], q[16];
#pragma unroll
  for (int c=0;c<16;c++){ s[c]=0.f; q[c]=0.f; }

  int stride = gridDim.x * blockDim.x;
  for (int p = blockIdx.x*blockDim.x + t; p < NHWp; p += stride){
    int n = p >> 18;
    int pix = p & (HWp-1);
    const float* xp = x + (size_t)n*10*HWp + pix;
    float in[10];
#pragma unroll
    for (int i=0;i<10;i++) in[i] = xp[(size_t)i*HWp];
    float* op = g_t + (size_t)n*16*HWp + pix;
#pragma unroll
    for (int c=0;c<16;c++){
      float v = sb[c];
#pragma unroll
      for (int i=0;i<10;i++) v = fmaf(sw[c*10+i], in[i], v);
      op[(size_t)c*HWp] = v;
      s[c] += v; q[c] += v*v;
    }
  }
#pragma unroll
  for (int c=0;c<16;c++){
    float a=s[c], b=q[c];
#pragma unroll
    for (int o=16;o>0;o>>=1){ a += __shfl_down_sync(0xffffffffu,a,o); b += __shfl_down_sync(0xffffffffu,b,o); }
    if ((t&31)==0){ atomicAdd(&ssum[c],(double)a); atomicAdd(&ssq[c],(double)b); }
  }
  __syncthreads();
  if (t<16){ atomicAdd(&g_sum1[t], ssum[t]); atomicAdd(&g_sq1[t], ssq[t]); }
}

// ---------------- K2/K4: finalize BN scale/shift ----------------
__global__ void k_fin(const float* __restrict__ gamma, const float* __restrict__ beta, int which){
  int c = threadIdx.x; if (c >= 16) return;
  double su = (which==0) ? g_sum1[c] : g_sum2[c];
  double sq = (which==0) ? g_sq1[c]  : g_sq2[c];
  double m  = su / (double)NHWp;
  double v  = sq / (double)NHWp - m*m;
  double a  = (double)gamma[c] / sqrt(v + 1e-5);
  float af = (float)a;
  float bf = (float)((double)beta[c] - a*m);
  if (which==0){ g_a1[c]=af; g_b1[c]=bf; } else { g_a2[c]=af; g_b2[c]=bf; }
}

// ---------------- K3: BN1+sigmoid -> 1x1 conv (16->16) in place + BN2 stats ----------------
__global__ void __launch_bounds__(256) k_stage2(const float* __restrict__ w2,
                                                const float* __restrict__ b2){
  __shared__ float sw[256], sbias[16], sa[16], sb[16];
  __shared__ double ssum[16], ssq[16];
  int t = threadIdx.x;
  if (t < 256) sw[t] = w2[t];
  if (t < 16){ sbias[t]=b2[t]; sa[t]=g_a1[t]; sb[t]=g_b1[t]; ssum[t]=0.0; ssq[t]=0.0; }
  __syncthreads();

  float s[16], q[16];
#pragma unroll
  for (int c=0;c<16;c++){ s[c]=0.f; q[c]=0.f; }

  int stride = gridDim.x * blockDim.x;
  for (int p = blockIdx.x*blockDim.x + t; p < NHWp; p += stride){
    int n = p >> 18;
    int pix = p & (HWp-1);
    float* bp = g_t + (size_t)n*16*HWp + pix;
    float y[16];
#pragma unroll
    for (int c=0;c<16;c++){
      float v = bp[(size_t)c*HWp];
      y[c] = sigm(fmaf(sa[c], v, sb[c]));
    }
#pragma unroll
    for (int o=0;o<16;o++){
      float z = sbias[o];
#pragma unroll
      for (int c=0;c<16;c++) z = fmaf(sw[o*16+c], y[c], z);
      bp[(size_t)o*HWp] = z;
      s[o] += z; q[o] += z*z;
    }
  }
#pragma unroll
  for (int c=0;c<16;c++){
    float a=s[c], b=q[c];
#pragma unroll
    for (int o=16;o>0;o>>=1){ a += __shfl_down_sync(0xffffffffu,a,o); b += __shfl_down_sync(0xffffffffu,b,o); }
    if ((t&31)==0){ atomicAdd(&ssum[c],(double)a); atomicAdd(&ssq[c],(double)b); }
  }
  __syncthreads();
  if (t<16){ atomicAdd(&g_sum2[t], ssum[t]); atomicAdd(&g_sq2[t], ssq[t]); }
}

// ---------------- K5: per-(n,c) variance stats of h2 = sigmoid(BN2(z)) ----------------
__global__ void __launch_bounds__(256) k_varstats(){
  const int BPS = 64;                 // blocks per sample
  int n   = blockIdx.x / BPS;
  int blk = blockIdx.x % BPS;
  __shared__ float sa[16], sb[16];
  __shared__ double ssum[16], ssq[16];
  int t = threadIdx.x;
  if (t < 16){ sa[t]=g_a2[t]; sb[t]=g_b2[t]; ssum[t]=0.0; ssq[t]=0.0; }
  __syncthreads();

  float s[16], q[16];
#pragma unroll
  for (int c=0;c<16;c++){ s[c]=0.f; q[c]=0.f; }

  const int per = HWp / BPS;          // 4096
  const float* base = g_t + (size_t)n*16*HWp;
  for (int pix = blk*per + t; pix < (blk+1)*per; pix += 256){
#pragma unroll
    for (int c=0;c<16;c++){
      float h = sigm(fmaf(sa[c], base[(size_t)c*HWp + pix], sb[c]));
      s[c] += h; q[c] += h*h;
    }
  }
#pragma unroll
  for (int c=0;c<16;c++){
    float a=s[c], b=q[c];
#pragma unroll
    for (int o=16;o>0;o>>=1){ a += __shfl_down_sync(0xffffffffu,a,o); b += __shfl_down_sync(0xffffffffu,b,o); }
    if ((t&31)==0){ atomicAdd(&ssum[c],(double)a); atomicAdd(&ssq[c],(double)b); }
  }
  __syncthreads();
  if (t<16){ atomicAdd(&g_vsum[n*16+t], ssum[t]); atomicAdd(&g_vsq[n*16+t], ssq[t]); }
}

// ---------------- K6: top-3 variance channels (stable, descending) ----------------
__global__ void k_topk(){
  int n = threadIdx.x; if (n >= NB) return;
  double var[16];
  for (int c=0;c<16;c++){
    double s = g_vsum[n*16+c], qq = g_vsq[n*16+c];
    double m = s / (double)HWp;
    var[c] = (qq - s*m) / (double)(HWp - 1);   // ddof=1
  }
  int mask = 0;
  for (int k=0;k<3;k++){
    int best = 0; double bv = -1e300;
    for (int c=0;c<16;c++)
      if (!((mask>>c)&1) && var[c] > bv){ bv = var[c]; best = c; }
    mask |= 1<<best;
    g_idx[n*3+k] = best;
  }
}

// ---------------- K7: conv3x3 (3 selected -> 8) + sigmoid + maxpool2 ----------------
__global__ void __launch_bounds__(256) k_conv3a(const float* __restrict__ wc,
                                                const float* __restrict__ bc){
  __shared__ float sp[3][34][36];
  __shared__ float sw[216], sbias[8];
  __shared__ float sa[3], sbb[3];
  __shared__ int   sch[3];
  int n = blockIdx.z;
  int t = threadIdx.x;
  if (t < 216) sw[t] = wc[t];
  if (t < 8)   sbias[t] = bc[t];
  if (t < 3){ int ch = g_idx[n*3+t]; sch[t]=ch; sa[t]=g_a2[ch]; sbb[t]=g_b2[ch]; }
  __syncthreads();

  int gy0 = blockIdx.y*32 - 1, gx0 = blockIdx.x*32 - 1;
  for (int i=t; i < 3*34*34; i += 256){
    int c = i / 1156, rem = i % 1156;
    int r = rem / 34, col = rem % 34;
    int gy = gy0 + r, gx = gx0 + col;
    float v = 0.f;
    if (gy >= 0 && gy < HH && gx >= 0 && gx < WW)
      v = sigm(fmaf(sa[c], g_t[(size_t)(n*16+sch[c])*HWp + gy*WW + gx], sbb[c]));
    sp[c][r][col] = v;
  }
  __syncthreads();

  int tx = t & 15, ty = t >> 4;
  int by = 2*ty, bx = 2*tx;
  float a00[8], a01[8], a10[8], a11[8];
#pragma unroll
  for (int oc=0;oc<8;oc++){ a00[oc]=a01[oc]=a10[oc]=a11[oc]=sbias[oc]; }
#pragma unroll
  for (int c=0;c<3;c++)
#pragma unroll
    for (int ky=0;ky<3;ky++)
#pragma unroll
      for (int kx=0;kx<3;kx++){
        float v00 = sp[c][by+ky  ][bx+kx  ];
        float v01 = sp[c][by+ky  ][bx+kx+1];
        float v10 = sp[c][by+ky+1][bx+kx  ];
        float v11 = sp[c][by+ky+1][bx+kx+1];
#pragma unroll
        for (int oc=0;oc<8;oc++){
          float wv = sw[oc*27 + c*9 + ky*3 + kx];
          a00[oc]=fmaf(v00,wv,a00[oc]); a01[oc]=fmaf(v01,wv,a01[oc]);
          a10[oc]=fmaf(v10,wv,a10[oc]); a11[oc]=fmaf(v11,wv,a11[oc]);
        }
      }
  int py = blockIdx.y*16 + ty, px = blockIdx.x*16 + tx;
#pragma unroll
  for (int oc=0;oc<8;oc++){
    float mx = fmaxf(fmaxf(a00[oc],a01[oc]), fmaxf(a10[oc],a11[oc]));
    g_x1[(size_t)(n*8+oc)*65536 + py*256 + px] = sigm(mx);  // sigmoid monotone: pool-then-sigmoid
  }
}

// ---------------- K8: conv3x3 (8 -> 16) + sigmoid + maxpool2 ----------------
__global__ void __launch_bounds__(256) k_conv3b(const float* __restrict__ wc,
                                                const float* __restrict__ bc){
  __shared__ float sp[8][34][36];    // 39168 B
  __shared__ float sw[1152], sbias[16];
  int n = blockIdx.z;
  int t = threadIdx.x;
  for (int i=t; i<1152; i+=256) sw[i] = wc[i];
  if (t < 16) sbias[t] = bc[t];
  __syncthreads();

  int gy0 = blockIdx.y*32 - 1, gx0 = blockIdx.x*32 - 1;
  for (int i=t; i < 8*34*34; i += 256){
    int c = i / 1156, rem = i % 1156;
    int r = rem / 34, col = rem % 34;
    int gy = gy0 + r, gx = gx0 + col;
    float v = 0.f;
    if (gy >= 0 && gy < 256 && gx >= 0 && gx < 256)
      v = g_x1[(size_t)(n*8+c)*65536 + gy*256 + gx];
    sp[c][r][col] = v;
  }
  __syncthreads();

  int tx = t & 15, ty = t >> 4;
  int by = 2*ty, bx = 2*tx;
  float a00[16], a01[16], a10[16], a11[16];
#pragma unroll
  for (int oc=0;oc<16;oc++){ a00[oc]=a01[oc]=a10[oc]=a11[oc]=sbias[oc]; }
#pragma unroll
  for (int c=0;c<8;c++)
#pragma unroll
    for (int ky=0;ky<3;ky++)
#pragma unroll
      for (int kx=0;kx<3;kx++){
        float v00 = sp[c][by+ky  ][bx+kx  ];
        float v01 = sp[c][by+ky  ][bx+kx+1];
        float v10 = sp[c][by+ky+1][bx+kx  ];
        float v11 = sp[c][by+ky+1][bx+kx+1];
#pragma unroll
        for (int oc=0;oc<16;oc++){
          float wv = sw[oc*72 + c*9 + ky*3 + kx];
          a00[oc]=fmaf(v00,wv,a00[oc]); a01[oc]=fmaf(v01,wv,a01[oc]);
          a10[oc]=fmaf(v10,wv,a10[oc]); a11[oc]=fmaf(v11,wv,a11[oc]);
        }
      }
  int py = blockIdx.y*16 + ty, px = blockIdx.x*16 + tx;
#pragma unroll
  for (int oc=0;oc<16;oc++){
    float mx = fmaxf(fmaxf(a00[oc],a01[oc]), fmaxf(a10[oc],a11[oc]));
    g_x2[(size_t)(n*16+oc)*16384 + py*128 + px] = sigm(mx);
  }
}

// ---- bilinear helpers (jax.image.resize half-pixel centers, edge-normalized == clamp) ----
__device__ __forceinline__ void idx_up2(int h, int Hin, int& y0, int& y1, float& f){
  y0 = (h >> 1) - ((h & 1) ^ 1);
  f  = (h & 1) ? 0.25f : 0.75f;
  y1 = min(y0 + 1, Hin - 1);
  y0 = max(y0, 0);
}
__device__ __forceinline__ void idx_up4(int h, int Hin, int& y0, int& y1, float& f){
  int m = h & 3;
  y0 = (h >> 2) - (m < 2 ? 1 : 0);
  f  = (m==0) ? 0.625f : (m==1) ? 0.875f : (m==2) ? 0.125f : 0.375f;
  y1 = min(y0 + 1, Hin - 1);
  y0 = max(y0, 0);
}

// ---------------- K9: stats of relu(upsample) for both BN paths ----------------
__global__ void __launch_bounds__(256) k_upstats(){
  __shared__ double ssum[24], ssq[24];
  int t = threadIdx.x;
  if (t < 24){ ssum[t]=0.0; ssq[t]=0.0; }
  __syncthreads();

  float s[24], q[24];
#pragma unroll
  for (int c=0;c<24;c++){ s[c]=0.f; q[c]=0.f; }

  int stride = gridDim.x * blockDim.x;
  for (int p = blockIdx.x*blockDim.x + t; p < NHWp; p += stride){
    int n = p >> 18, pix = p & (HWp-1);
    int h = pix >> 9, w = pix & 511;
    // x1 path: up2 from 256x256, 8 channels
    {
      int y0,y1,x0,x1; float fy,fx;
      idx_up2(h,256,y0,y1,fy); idx_up2(w,256,x0,x1,fx);
      int o00=y0*256+x0, o01=y0*256+x1, o10=y1*256+x0, o11=y1*256+x1;
      const float* bp = g_x1 + (size_t)n*8*65536;
#pragma unroll
      for (int c=0;c<8;c++){
        const float* pc = bp + (size_t)c*65536;
        float v0 = pc[o00] + fx*(pc[o01]-pc[o00]);
        float v1 = pc[o10] + fx*(pc[o11]-pc[o10]);
        float r  = fmaxf(v0 + fy*(v1-v0), 0.f);
        s[c] += r; q[c] += r*r;
      }
    }
    // x2 path: up4 from 128x128, 16 channels
    {
      int y0,y1,x0,x1; float fy,fx;
      idx_up4(h,128,y0,y1,fy); idx_up4(w,128,x0,x1,fx);
      int o00=y0*128+x0, o01=y0*128+x1, o10=y1*128+x0, o11=y1*128+x1;
      const float* bp = g_x2 + (size_t)n*16*16384;
#pragma unroll
      for (int c=0;c<16;c++){
        const float* pc = bp + (size_t)c*16384;
        float v0 = pc[o00] + fx*(pc[o01]-pc[o00]);
        float v1 = pc[o10] + fx*(pc[o11]-pc[o10]);
        float r  = fmaxf(v0 + fy*(v1-v0), 0.f);
        s[8+c] += r; q[8+c] += r*r;
      }
    }
  }
#pragma unroll
  for (int c=0;c<24;c++){
    float a=s[c], b=q[c];
#pragma unroll
    for (int o=16;o>0;o>>=1){ a += __shfl_down_sync(0xffffffffu,a,o); b += __shfl_down_sync(0xffffffffu,b,o); }
    if ((t&31)==0){ atomicAdd(&ssum[c],(double)a); atomicAdd(&ssq[c],(double)b); }
  }
  __syncthreads();
  if (t<24){ atomicAdd(&g_usum[t], ssum[t]); atomicAdd(&g_usq[t], ssq[t]); }
}

// ---------------- K10: finalize upsample BNs (ch 0-7: bn2, ch 8-23: bn1) ----------------
__global__ void k_finup(const float* __restrict__ gbn1, const float* __restrict__ bbn1,
                        const float* __restrict__ gbn2, const float* __restrict__ bbn2){
  int c = threadIdx.x; if (c >= 24) return;
  double m = g_usum[c] / (double)NHWp;
  double v = g_usq[c]  / (double)NHWp - m*m;
  double gamma = (c < 8) ? (double)gbn2[c] : (double)gbn1[c-8];
  double beta  = (c < 8) ? (double)bbn2[c] : (double)bbn1[c-8];
  double a = gamma / sqrt(v + 1e-5);
  g_au[c] = (float)a;
  g_bu[c] = (float)(beta - a*m);
}

// ---------------- K11: up2/up4 + relu + BN + concat + 1x1 conv (24->5) ----------------
__global__ void __launch_bounds__(256) k_final(const float* __restrict__ w1k,
                                               const float* __restrict__ b1k,
                                               float* __restrict__ out){
  __shared__ float sw[120], sb5[5], sa[24], sbb[24];
  int t = threadIdx.x;
  if (t < 120) sw[t] = w1k[t];
  if (t < 5)   sb5[t] = b1k[t];
  if (t < 24){ sa[t] = g_au[t]; sbb[t] = g_bu[t]; }
  __syncthreads();

  int stride = gridDim.x * blockDim.x;
  for (int p = blockIdx.x*blockDim.x + t; p < NHWp; p += stride){
    int n = p >> 18, pix = p & (HWp-1);
    int h = pix >> 9, w = pix & 511;
    float m[24];
    {
      int y0,y1,x0,x1; float fy,fx;
      idx_up2(h,256,y0,y1,fy); idx_up2(w,256,x0,x1,fx);
      int o00=y0*256+x0, o01=y0*256+x1, o10=y1*256+x0, o11=y1*256+x1;
      const float* bp = g_x1 + (size_t)n*8*65536;
#pragma unroll
      for (int c=0;c<8;c++){
        const float* pc = bp + (size_t)c*65536;
        float v0 = pc[o00] + fx*(pc[o01]-pc[o00]);
        float v1 = pc[o10] + fx*(pc[o11]-pc[o10]);
        float v  = v0 + fy*(v1-v0);
        m[c] = fmaf(sa[c], fmaxf(v,0.f), sbb[c]);
      }
    }
    {
      int y0,y1,x0,x1; float fy,fx;
      idx_up4(h,128,y0,y1,fy); idx_up4(w,128,x0,x1,fx);
      int o00=y0*128+x0, o01=y0*128+x1, o10=y1*128+x0, o11=y1*128+x1;
      const float* bp = g_x2 + (size_t)n*16*16384;
#pragma unroll
      for (int c=0;c<16;c++){
        const float* pc = bp + (size_t)c*16384;
        float v0 = pc[o00] + fx*(pc[o01]-pc[o00]);
        float v1 = pc[o10] + fx*(pc[o11]-pc[o10]);
        float v  = v0 + fy*(v1-v0);
        m[8+c] = fmaf(sa[8+c], fmaxf(v,0.f), sbb[8+c]);
      }
    }
#pragma unroll
    for (int k=0;k<5;k++){
      float o = sb5[k];
#pragma unroll
      for (int c=0;c<24;c++) o = fmaf(sw[k*24+c], m[c], o);
      out[(size_t)(n*5+k)*HWp + pix] = o;
    }
  }
}

// ---------------- launch ----------------
extern "C" void kernel_launch(void* const* d_in, const int* in_sizes, int n_in,
                              void* d_out, int out_size){
  (void)in_sizes; (void)n_in; (void)out_size;
  const float* x       = (const float*)d_in[0];
  const float* w_ext1  = (const float*)d_in[1];
  const float* b_ext1  = (const float*)d_in[2];
  const float* g_ebn1  = (const float*)d_in[3];
  const float* be_ebn1 = (const float*)d_in[4];
  const float* w_ext2  = (const float*)d_in[5];
  const float* b_ext2  = (const float*)d_in[6];
  const float* g_ebn2  = (const float*)d_in[7];
  const float* be_ebn2 = (const float*)d_in[8];
  const float* w_c1    = (const float*)d_in[9];
  const float* b_c1    = (const float*)d_in[10];
  const float* w_c2    = (const float*)d_in[11];
  const float* b_c2    = (const float*)d_in[12];
  const float* g_bn1   = (const float*)d_in[13];
  const float* be_bn1  = (const float*)d_in[14];
  const float* g_bn2   = (const float*)d_in[15];
  const float* be_bn2  = (const float*)d_in[16];
  const float* w_1k    = (const float*)d_in[17];
  const float* b_1k    = (const float*)d_in[18];
  float* out = (float*)d_out;

  const int GS = 1184;  // 8 blocks/SM worth of grid-stride blocks

  k_zero<<<1,256>>>();
  k_conv1<<<GS,256>>>(x, w_ext1, b_ext1);
  k_fin<<<1,16>>>(g_ebn1, be_ebn1, 0);
  k_stage2<<<GS,256>>>(w_ext2, b_ext2);
  k_fin<<<1,16>>>(g_ebn2, be_ebn2, 1);
  k_varstats<<<16*64,256>>>();
  k_topk<<<1,16>>>();
  k_conv3a<<<dim3(16,16,16),256>>>(w_c1, b_c1);
  k_conv3b<<<dim3(8,8,16),256>>>(w_c2, b_c2);
  k_upstats<<<GS,256>>>();
  k_finup<<<1,24>>>(g_bn1, be_bn1, g_bn2, be_bn2);
  k_final<<<GS,256>>>(w_1k, b_1k, out);
}

// round 9
// speedup vs baseline: 1.7477x; 1.7130x over previous
#include <cuda_runtime.h>
#include <math.h>

// Problem constants
#define NB   16          // batch
#define HH   512
#define WW   512
#define HWp  (HH*WW)     // 262144
#define HW2  (HWp/2)     // 131072 (float2 units)
#define NHWp (NB*HWp)    // 4194304
#define NHW2 (NB*HW2)    // 2097152

// ---------------- device scratch (static, no allocation) ----------------
static __device__ float  g_t [67108864];   // [16,16,512,512] main scratch (268 MB)
static __device__ float  g_x1[ 8388608];   // [16, 8,256,256]
static __device__ float  g_x2[ 4194304];   // [16,16,128,128]
static __device__ double g_sum1[16], g_sq1[16], g_sum2[16], g_sq2[16];
static __device__ double g_vsum[NB*16], g_vsq[NB*16];
static __device__ double g_usum[24], g_usq[24];
static __device__ float  g_a1[16], g_b1[16], g_a2[16], g_b2[16];
static __device__ float  g_au[24], g_bu[24];
static __device__ int    g_idx[NB*3];

// fast sigmoid: FMUL+MUFU.EX2+FADD+MUFU.RCP+FMUL (rel err ~1e-6 in our range)
__device__ __forceinline__ float sigm(float x){
  return __fdividef(1.0f, 1.0f + __expf(-x));
}

// ---------------- K0: zero stat accumulators ----------------
__global__ void k_zero(){
  int t = threadIdx.x;
  if (t < 16){ g_sum1[t]=0.0; g_sq1[t]=0.0; g_sum2[t]=0.0; g_sq2[t]=0.0; }
  if (t < 24){ g_usum[t]=0.0; g_usq[t]=0.0; }
  if (t < 256){ g_vsum[t]=0.0; g_vsq[t]=0.0; }
}

// ---------------- K1: 1x1 conv (10->16) + BN1 stats (float2) ----------------
__global__ void __launch_bounds__(256,2) k_conv1(const float* __restrict__ x,
                                                 const float* __restrict__ w,
                                                 const float* __restrict__ bias){
  __shared__ float sw[160], sb[16];
  __shared__ double ssum[16], ssq[16];
  int t = threadIdx.x;
  if (t < 160) sw[t] = w[t];
  if (t < 16){ sb[t] = bias[t]; ssum[t]=0.0; ssq[t]=0.0; }
  __syncthreads();

  float s[16], q[16];
#pragma unroll
  for (int c=0;c<16;c++){ s[c]=0.f; q[c]=0.f; }

  const float2* X = (const float2*)x;
  float2* T = (float2*)g_t;
  int stride = gridDim.x * blockDim.x;
  for (int p = blockIdx.x*blockDim.x + t; p < NHW2; p += stride){
    int n = p >> 17;
    int pix = p & (HW2-1);
    const float2* xp = X + (size_t)n*10*HW2 + pix;
    float2 in[10];
#pragma unroll
    for (int i=0;i<10;i++) in[i] = xp[(size_t)i*HW2];
    float2* op = T + (size_t)n*16*HW2 + pix;
#pragma unroll
    for (int c=0;c<16;c++){
      float vx = sb[c], vy = sb[c];
#pragma unroll
      for (int i=0;i<10;i++){ float wv = sw[c*10+i]; vx = fmaf(wv, in[i].x, vx); vy = fmaf(wv, in[i].y, vy); }
      float2 v; v.x = vx; v.y = vy;
      op[(size_t)c*HW2] = v;
      s[c] += vx + vy; q[c] += vx*vx + vy*vy;
    }
  }
#pragma unroll
  for (int c=0;c<16;c++){
    float a=s[c], b=q[c];
#pragma unroll
    for (int o=16;o>0;o>>=1){ a += __shfl_down_sync(0xffffffffu,a,o); b += __shfl_down_sync(0xffffffffu,b,o); }
    if ((t&31)==0){ atomicAdd(&ssum[c],(double)a); atomicAdd(&ssq[c],(double)b); }
  }
  __syncthreads();
  if (t<16){ atomicAdd(&g_sum1[t], ssum[t]); atomicAdd(&g_sq1[t], ssq[t]); }
}

// ---------------- K2/K4: finalize BN scale/shift ----------------
__global__ void k_fin(const float* __restrict__ gamma, const float* __restrict__ beta, int which){
  int c = threadIdx.x; if (c >= 16) return;
  double su = (which==0) ? g_sum1[c] : g_sum2[c];
  double sq = (which==0) ? g_sq1[c]  : g_sq2[c];
  double m  = su / (double)NHWp;
  double v  = sq / (double)NHWp - m*m;
  double a  = (double)gamma[c] / sqrt(v + 1e-5);
  float af = (float)a;
  float bf = (float)((double)beta[c] - a*m);
  if (which==0){ g_a1[c]=af; g_b1[c]=bf; } else { g_a2[c]=af; g_b2[c]=bf; }
}

// ---------------- K3: BN1+sigmoid -> 1x1 conv (16->16) in place + BN2 stats (float2) ----------------
__global__ void __launch_bounds__(256,2) k_stage2(const float* __restrict__ w2,
                                                  const float* __restrict__ b2){
  __shared__ float sw[256], sbias[16], sa[16], sb[16];
  __shared__ double ssum[16], ssq[16];
  int t = threadIdx.x;
  if (t < 256) sw[t] = w2[t];
  if (t < 16){ sbias[t]=b2[t]; sa[t]=g_a1[t]; sb[t]=g_b1[t]; ssum[t]=0.0; ssq[t]=0.0; }
  __syncthreads();

  float s[16], q[16];
#pragma unroll
  for (int c=0;c<16;c++){ s[c]=0.f; q[c]=0.f; }

  float2* T = (float2*)g_t;
  int stride = gridDim.x * blockDim.x;
  for (int p = blockIdx.x*blockDim.x + t; p < NHW2; p += stride){
    int n = p >> 17;
    int pix = p & (HW2-1);
    float2* bp = T + (size_t)n*16*HW2 + pix;
    float2 y[16];
#pragma unroll
    for (int c=0;c<16;c++){
      float2 v = bp[(size_t)c*HW2];
      y[c].x = sigm(fmaf(sa[c], v.x, sb[c]));
      y[c].y = sigm(fmaf(sa[c], v.y, sb[c]));
    }
#pragma unroll
    for (int o=0;o<16;o++){
      float zx = sbias[o], zy = sbias[o];
#pragma unroll
      for (int c=0;c<16;c++){ float wv = sw[o*16+c]; zx = fmaf(wv, y[c].x, zx); zy = fmaf(wv, y[c].y, zy); }
      float2 z; z.x = zx; z.y = zy;
      bp[(size_t)o*HW2] = z;
      s[o] += zx + zy; q[o] += zx*zx + zy*zy;
    }
  }
#pragma unroll
  for (int c=0;c<16;c++){
    float a=s[c], b=q[c];
#pragma unroll
    for (int o=16;o>0;o>>=1){ a += __shfl_down_sync(0xffffffffu,a,o); b += __shfl_down_sync(0xffffffffu,b,o); }
    if ((t&31)==0){ atomicAdd(&ssum[c],(double)a); atomicAdd(&ssq[c],(double)b); }
  }
  __syncthreads();
  if (t<16){ atomicAdd(&g_sum2[t], ssum[t]); atomicAdd(&g_sq2[t], ssq[t]); }
}

// ---------------- K5: per-(n,c) variance stats of h2 = sigmoid(BN2(z)) (float2) ----------------
__global__ void __launch_bounds__(256,2) k_varstats(){
  const int BPS = 64;                 // blocks per sample
  int n   = blockIdx.x / BPS;
  int blk = blockIdx.x % BPS;
  __shared__ float sa[16], sb[16];
  __shared__ double ssum[16], ssq[16];
  int t = threadIdx.x;
  if (t < 16){ sa[t]=g_a2[t]; sb[t]=g_b2[t]; ssum[t]=0.0; ssq[t]=0.0; }
  __syncthreads();

  float s[16], q[16];
#pragma unroll
  for (int c=0;c<16;c++){ s[c]=0.f; q[c]=0.f; }

  const int per = HW2 / BPS;          // 2048 float2 per block
  const float2* base = (const float2*)g_t + (size_t)n*16*HW2;
  for (int pix = blk*per + t; pix < (blk+1)*per; pix += 256){
#pragma unroll
    for (int c=0;c<16;c++){
      float2 v = base[(size_t)c*HW2 + pix];
      float hx = sigm(fmaf(sa[c], v.x, sb[c]));
      float hy = sigm(fmaf(sa[c], v.y, sb[c]));
      s[c] += hx + hy; q[c] += hx*hx + hy*hy;
    }
  }
#pragma unroll
  for (int c=0;c<16;c++){
    float a=s[c], b=q[c];
#pragma unroll
    for (int o=16;o>0;o>>=1){ a += __shfl_down_sync(0xffffffffu,a,o); b += __shfl_down_sync(0xffffffffu,b,o); }
    if ((t&31)==0){ atomicAdd(&ssum[c],(double)a); atomicAdd(&ssq[c],(double)b); }
  }
  __syncthreads();
  if (t<16){ atomicAdd(&g_vsum[n*16+t], ssum[t]); atomicAdd(&g_vsq[n*16+t], ssq[t]); }
}

// ---------------- K6: top-3 variance channels ----------------
__global__ void k_topk(){
  int n = threadIdx.x; if (n >= NB) return;
  double var[16];
  for (int c=0;c<16;c++){
    double s = g_vsum[n*16+c], qq = g_vsq[n*16+c];
    double m = s / (double)HWp;
    var[c] = (qq - s*m) / (double)(HWp - 1);   // ddof=1
  }
  int mask = 0;
  for (int k=0;k<3;k++){
    int best = 0; double bv = -1e300;
    for (int c=0;c<16;c++)
      if (!((mask>>c)&1) && var[c] > bv){ bv = var[c]; best = c; }
    mask |= 1<<best;
    g_idx[n*3+k] = best;
  }
}

// ---------------- K7: conv3x3 (3 selected -> 8) + sigmoid + maxpool2 ----------------
__global__ void __launch_bounds__(256,2) k_conv3a(const float* __restrict__ wc,
                                                  const float* __restrict__ bc){
  __shared__ float sp[3][34][36];
  __shared__ float sw[216], sbias[8];
  __shared__ float sa[3], sbb[3];
  __shared__ int   sch[3];
  int n = blockIdx.z;
  int t = threadIdx.x;
  if (t < 216) sw[t] = wc[t];
  if (t < 8)   sbias[t] = bc[t];
  if (t < 3){ int ch = g_idx[n*3+t]; sch[t]=ch; sa[t]=g_a2[ch]; sbb[t]=g_b2[ch]; }
  __syncthreads();

  int gy0 = blockIdx.y*32 - 1, gx0 = blockIdx.x*32 - 1;
  for (int i=t; i < 3*34*34; i += 256){
    int c = i / 1156, rem = i % 1156;
    int r = rem / 34, col = rem % 34;
    int gy = gy0 + r, gx = gx0 + col;
    float v = 0.f;
    if (gy >= 0 && gy < HH && gx >= 0 && gx < WW)
      v = sigm(fmaf(sa[c], g_t[(size_t)(n*16+sch[c])*HWp + gy*WW + gx], sbb[c]));
    sp[c][r][col] = v;
  }
  __syncthreads();

  int tx = t & 15, ty = t >> 4;
  int by = 2*ty, bx = 2*tx;
  float a00[8], a01[8], a10[8], a11[8];
#pragma unroll
  for (int oc=0;oc<8;oc++){ a00[oc]=a01[oc]=a10[oc]=a11[oc]=sbias[oc]; }
#pragma unroll
  for (int c=0;c<3;c++)
#pragma unroll
    for (int ky=0;ky<3;ky++)
#pragma unroll
      for (int kx=0;kx<3;kx++){
        float v00 = sp[c][by+ky  ][bx+kx  ];
        float v01 = sp[c][by+ky  ][bx+kx+1];
        float v10 = sp[c][by+ky+1][bx+kx  ];
        float v11 = sp[c][by+ky+1][bx+kx+1];
#pragma unroll
        for (int oc=0;oc<8;oc++){
          float wv = sw[oc*27 + c*9 + ky*3 + kx];
          a00[oc]=fmaf(v00,wv,a00[oc]); a01[oc]=fmaf(v01,wv,a01[oc]);
          a10[oc]=fmaf(v10,wv,a10[oc]); a11[oc]=fmaf(v11,wv,a11[oc]);
        }
      }
  int py = blockIdx.y*16 + ty, px = blockIdx.x*16 + tx;
#pragma unroll
  for (int oc=0;oc<8;oc++){
    float mx = fmaxf(fmaxf(a00[oc],a01[oc]), fmaxf(a10[oc],a11[oc]));
    g_x1[(size_t)(n*8+oc)*65536 + py*256 + px] = sigm(mx);  // sigmoid monotone: pool-then-sigmoid
  }
}

// ---------------- K8: conv3x3 (8 -> 16) + sigmoid + maxpool2 ----------------
__global__ void __launch_bounds__(256,2) k_conv3b(const float* __restrict__ wc,
                                                  const float* __restrict__ bc){
  __shared__ float sp[8][34][36];    // 39168 B
  __shared__ float sw[1152], sbias[16];
  int n = blockIdx.z;
  int t = threadIdx.x;
  for (int i=t; i<1152; i+=256) sw[i] = wc[i];
  if (t < 16) sbias[t] = bc[t];
  __syncthreads();

  int gy0 = blockIdx.y*32 - 1, gx0 = blockIdx.x*32 - 1;
  for (int i=t; i < 8*34*34; i += 256){
    int c = i / 1156, rem = i % 1156;
    int r = rem / 34, col = rem % 34;
    int gy = gy0 + r, gx = gx0 + col;
    float v = 0.f;
    if (gy >= 0 && gy < 256 && gx >= 0 && gx < 256)
      v = g_x1[(size_t)(n*8+c)*65536 + gy*256 + gx];
    sp[c][r][col] = v;
  }
  __syncthreads();

  int tx = t & 15, ty = t >> 4;
  int by = 2*ty, bx = 2*tx;
  float a00[16], a01[16], a10[16], a11[16];
#pragma unroll
  for (int oc=0;oc<16;oc++){ a00[oc]=a01[oc]=a10[oc]=a11[oc]=sbias[oc]; }
#pragma unroll
  for (int c=0;c<8;c++)
#pragma unroll
    for (int ky=0;ky<3;ky++)
#pragma unroll
      for (int kx=0;kx<3;kx++){
        float v00 = sp[c][by+ky  ][bx+kx  ];
        float v01 = sp[c][by+ky  ][bx+kx+1];
        float v10 = sp[c][by+ky+1][bx+kx  ];
        float v11 = sp[c][by+ky+1][bx+kx+1];
#pragma unroll
        for (int oc=0;oc<16;oc++){
          float wv = sw[oc*72 + c*9 + ky*3 + kx];
          a00[oc]=fmaf(v00,wv,a00[oc]); a01[oc]=fmaf(v01,wv,a01[oc]);
          a10[oc]=fmaf(v10,wv,a10[oc]); a11[oc]=fmaf(v11,wv,a11[oc]);
        }
      }
  int py = blockIdx.y*16 + ty, px = blockIdx.x*16 + tx;
#pragma unroll
  for (int oc=0;oc<16;oc++){
    float mx = fmaxf(fmaxf(a00[oc],a01[oc]), fmaxf(a10[oc],a11[oc]));
    g_x2[(size_t)(n*16+oc)*16384 + py*128 + px] = sigm(mx);
  }
}

// ---- bilinear helpers (jax.image.resize half-pixel centers, edge-normalized == clamp) ----
__device__ __forceinline__ void idx_up2(int h, int Hin, int& y0, int& y1, float& f){
  y0 = (h >> 1) - ((h & 1) ^ 1);
  f  = (h & 1) ? 0.25f : 0.75f;
  y1 = min(y0 + 1, Hin - 1);
  y0 = max(y0, 0);
}
__device__ __forceinline__ void idx_up4(int h, int Hin, int& y0, int& y1, float& f){
  int m = h & 3;
  y0 = (h >> 2) - (m < 2 ? 1 : 0);
  f  = (m==0) ? 0.625f : (m==1) ? 0.875f : (m==2) ? 0.125f : 0.375f;
  y1 = min(y0 + 1, Hin - 1);
  y0 = max(y0, 0);
}

// ---------------- K9a: stats of relu(up2(x1)) -> g_usum[0..7] ----------------
__global__ void __launch_bounds__(256,2) k_up2stats(){
  __shared__ double ssum[8], ssq[8];
  int t = threadIdx.x;
  if (t < 8){ ssum[t]=0.0; ssq[t]=0.0; }
  __syncthreads();

  float s[8], q[8];
#pragma unroll
  for (int c=0;c<8;c++){ s[c]=0.f; q[c]=0.f; }

  int stride = gridDim.x * blockDim.x;
  for (int p = blockIdx.x*blockDim.x + t; p < NHWp; p += stride){
    int n = p >> 18, pix = p & (HWp-1);
    int h = pix >> 9, w = pix & 511;
    int y0,y1,x0,x1; float fy,fx;
    idx_up2(h,256,y0,y1,fy); idx_up2(w,256,x0,x1,fx);
    int o00=y0*256+x0, o01=y0*256+x1, o10=y1*256+x0, o11=y1*256+x1;
    const float* bp = g_x1 + (size_t)n*8*65536;
#pragma unroll
    for (int c=0;c<8;c++){
      const float* pc = bp + (size_t)c*65536;
      float v0 = pc[o00] + fx*(pc[o01]-pc[o00]);
      float v1 = pc[o10] + fx*(pc[o11]-pc[o10]);
      float r  = fmaxf(v0 + fy*(v1-v0), 0.f);
      s[c] += r; q[c] += r*r;
    }
  }
#pragma unroll
  for (int c=0;c<8;c++){
    float a=s[c], b=q[c];
#pragma unroll
    for (int o=16;o>0;o>>=1){ a += __shfl_down_sync(0xffffffffu,a,o); b += __shfl_down_sync(0xffffffffu,b,o); }
    if ((t&31)==0){ atomicAdd(&ssum[c],(double)a); atomicAdd(&ssq[c],(double)b); }
  }
  __syncthreads();
  if (t<8){ atomicAdd(&g_usum[t], ssum[t]); atomicAdd(&g_usq[t], ssq[t]); }
}

// ---------------- K9b: stats of relu(up4(x2)) -> g_usum[8..23] ----------------
__global__ void __launch_bounds__(256,2) k_up4stats(){
  __shared__ double ssum[16], ssq[16];
  int t = threadIdx.x;
  if (t < 16){ ssum[t]=0.0; ssq[t]=0.0; }
  __syncthreads();

  float s[16], q[16];
#pragma unroll
  for (int c=0;c<16;c++){ s[c]=0.f; q[c]=0.f; }

  int stride = gridDim.x * blockDim.x;
  for (int p = blockIdx.x*blockDim.x + t; p < NHWp; p += stride){
    int n = p >> 18, pix = p & (HWp-1);
    int h = pix >> 9, w = pix & 511;
    int y0,y1,x0,x1; float fy,fx;
    idx_up4(h,128,y0,y1,fy); idx_up4(w,128,x0,x1,fx);
    int o00=y0*128+x0, o01=y0*128+x1, o10=y1*128+x0, o11=y1*128+x1;
    const float* bp = g_x2 + (size_t)n*16*16384;
#pragma unroll
    for (int c=0;c<16;c++){
      const float* pc = bp + (size_t)c*16384;
      float v0 = pc[o00] + fx*(pc[o01]-pc[o00]);
      float v1 = pc[o10] + fx*(pc[o11]-pc[o10]);
      float r  = fmaxf(v0 + fy*(v1-v0), 0.f);
      s[c] += r; q[c] += r*r;
    }
  }
#pragma unroll
  for (int c=0;c<16;c++){
    float a=s[c], b=q[c];
#pragma unroll
    for (int o=16;o>0;o>>=1){ a += __shfl_down_sync(0xffffffffu,a,o); b += __shfl_down_sync(0xffffffffu,b,o); }
    if ((t&31)==0){ atomicAdd(&ssum[c],(double)a); atomicAdd(&ssq[c],(double)b); }
  }
  __syncthreads();
  if (t<16){ atomicAdd(&g_usum[8+t], ssum[t]); atomicAdd(&g_usq[8+t], ssq[t]); }
}

// ---------------- K10: finalize upsample BNs (ch 0-7: bn2, ch 8-23: bn1) ----------------
__global__ void k_finup(const float* __restrict__ gbn1, const float* __restrict__ bbn1,
                        const float* __restrict__ gbn2, const float* __restrict__ bbn2){
  int c = threadIdx.x; if (c >= 24) return;
  double m = g_usum[c] / (double)NHWp;
  double v = g_usq[c]  / (double)NHWp - m*m;
  double gamma = (c < 8) ? (double)gbn2[c] : (double)gbn1[c-8];
  double beta  = (c < 8) ? (double)bbn2[c] : (double)bbn1[c-8];
  double a = gamma / sqrt(v + 1e-5);
  g_au[c] = (float)a;
  g_bu[c] = (float)(beta - a*m);
}

// ---------------- K11: up2/up4 + relu + BN + concat + 1x1 conv (24->5) ----------------
__global__ void __launch_bounds__(256,2) k_final(const float* __restrict__ w1k,
                                                 const float* __restrict__ b1k,
                                                 float* __restrict__ out){
  __shared__ float sw[120], sb5[5], sa[24], sbb[24];
  int t = threadIdx.x;
  if (t < 120) sw[t] = w1k[t];
  if (t < 5)   sb5[t] = b1k[t];
  if (t < 24){ sa[t] = g_au[t]; sbb[t] = g_bu[t]; }
  __syncthreads();

  int stride = gridDim.x * blockDim.x;
  for (int p = blockIdx.x*blockDim.x + t; p < NHWp; p += stride){
    int n = p >> 18, pix = p & (HWp-1);
    int h = pix >> 9, w = pix & 511;
    float acc[5];
#pragma unroll
    for (int k=0;k<5;k++) acc[k] = sb5[k];
    {
      int y0,y1,x0,x1; float fy,fx;
      idx_up2(h,256,y0,y1,fy); idx_up2(w,256,x0,x1,fx);
      int o00=y0*256+x0, o01=y0*256+x1, o10=y1*256+x0, o11=y1*256+x1;
      const float* bp = g_x1 + (size_t)n*8*65536;
#pragma unroll
      for (int c=0;c<8;c++){
        const float* pc = bp + (size_t)c*65536;
        float v0 = pc[o00] + fx*(pc[o01]-pc[o00]);
        float v1 = pc[o10] + fx*(pc[o11]-pc[o10]);
        float v  = v0 + fy*(v1-v0);
        float r  = fmaf(sa[c], fmaxf(v,0.f), sbb[c]);
#pragma unroll
        for (int k=0;k<5;k++) acc[k] = fmaf(sw[k*24+c], r, acc[k]);
      }
    }
    {
      int y0,y1,x0,x1; float fy,fx;
      idx_up4(h,128,y0,y1,fy); idx_up4(w,128,x0,x1,fx);
      int o00=y0*128+x0, o01=y0*128+x1, o10=y1*128+x0, o11=y1*128+x1;
      const float* bp = g_x2 + (size_t)n*16*16384;
#pragma unroll
      for (int c=0;c<16;c++){
        const float* pc = bp + (size_t)c*16384;
        float v0 = pc[o00] + fx*(pc[o01]-pc[o00]);
        float v1 = pc[o10] + fx*(pc[o11]-pc[o10]);
        float v  = v0 + fy*(v1-v0);
        float r  = fmaf(sa[8+c], fmaxf(v,0.f), sbb[8+c]);
#pragma unroll
        for (int k=0;k<5;k++) acc[k] = fmaf(sw[k*24+8+c], r, acc[k]);
      }
    }
#pragma unroll
    for (int k=0;k<5;k++)
      out[(size_t)(n*5+k)*HWp + pix] = acc[k];
  }
}

// ---------------- launch ----------------
extern "C" void kernel_launch(void* const* d_in, const int* in_sizes, int n_in,
                              void* d_out, int out_size){
  (void)in_sizes; (void)n_in; (void)out_size;
  const float* x       = (const float*)d_in[0];
  const float* w_ext1  = (const float*)d_in[1];
  const float* b_ext1  = (const float*)d_in[2];
  const float* g_ebn1  = (const float*)d_in[3];
  const float* be_ebn1 = (const float*)d_in[4];
  const float* w_ext2  = (const float*)d_in[5];
  const float* b_ext2  = (const float*)d_in[6];
  const float* g_ebn2  = (const float*)d_in[7];
  const float* be_ebn2 = (const float*)d_in[8];
  const float* w_c1    = (const float*)d_in[9];
  const float* b_c1    = (const float*)d_in[10];
  const float* w_c2    = (const float*)d_in[11];
  const float* b_c2    = (const float*)d_in[12];
  const float* g_bn1   = (const float*)d_in[13];
  const float* be_bn1  = (const float*)d_in[14];
  const float* g_bn2   = (const float*)d_in[15];
  const float* be_bn2  = (const float*)d_in[16];
  const float* w_1k    = (const float*)d_in[17];
  const float* b_1k    = (const float*)d_in[18];
  float* out = (float*)d_out;

  const int GS = 1184;

  k_zero<<<1,256>>>();
  k_conv1<<<GS,256>>>(x, w_ext1, b_ext1);
  k_fin<<<1,16>>>(g_ebn1, be_ebn1, 0);
  k_stage2<<<GS,256>>>(w_ext2, b_ext2);
  k_fin<<<1,16>>>(g_ebn2, be_ebn2, 1);
  k_varstats<<<16*64,256>>>();
  k_topk<<<1,16>>>();
  k_conv3a<<<dim3(16,16,16),256>>>(w_c1, b_c1);
  k_conv3b<<<dim3(8,8,16),256>>>(w_c2, b_c2);
  k_up2stats<<<GS,256>>>();
  k_up4stats<<<GS,256>>>();
  k_finup<<<1,24>>>(g_bn1, be_bn1, g_bn2, be_bn2);
  k_final<<<GS,256>>>(w_1k, b_1k, out);
}

// round 10
// speedup vs baseline: 1.7483x; 1.0003x over previous
#include <cuda_runtime.h>
#include <math.h>

// Problem constants
#define NB   16          // batch
#define HH   512
#define WW   512
#define HWp  (HH*WW)     // 262144
#define HW2  (HWp/2)     // 131072 (float2 units)
#define NHWp (NB*HWp)    // 4194304
#define NHW2 (NB*HW2)    // 2097152

// ---------------- device scratch (static, no allocation) ----------------
static __device__ float  g_t [67108864];   // [16,16,512,512] main scratch (268 MB)
static __device__ float  g_x1[ 8388608];   // [16, 8,256,256]
static __device__ float  g_x2[ 4194304];   // [16,16,128,128]
static __device__ double g_sum1[16], g_sq1[16], g_sum2[16], g_sq2[16];
static __device__ double g_vsum[NB*16], g_vsq[NB*16];
static __device__ double g_usum[24], g_usq[24];
static __device__ float  g_a1[16], g_b1[16], g_a2[16], g_b2[16];
static __device__ float  g_au[24], g_bu[24];
static __device__ int    g_idx[NB*3];

// fast sigmoid: FMUL+MUFU.EX2+FADD+MUFU.RCP+FMUL (rel err ~1e-6 in our range)
__device__ __forceinline__ float sigm(float x){
  return __fdividef(1.0f, 1.0f + __expf(-x));
}

// ---------------- K0: zero stat accumulators ----------------
__global__ void k_zero(){
  int t = threadIdx.x;
  if (t < 16){ g_sum1[t]=0.0; g_sq1[t]=0.0; g_sum2[t]=0.0; g_sq2[t]=0.0; }
  if (t < 24){ g_usum[t]=0.0; g_usq[t]=0.0; }
  if (t < 256){ g_vsum[t]=0.0; g_vsq[t]=0.0; }
}

// ---------------- K1: 1x1 conv (10->16) + BN1 stats (float2) ----------------
__global__ void __launch_bounds__(256,2) k_conv1(const float* __restrict__ x,
                                                 const float* __restrict__ w,
                                                 const float* __restrict__ bias){
  __shared__ float sw[160], sb[16];
  __shared__ double ssum[16], ssq[16];
  int t = threadIdx.x;
  if (t < 160) sw[t] = w[t];
  if (t < 16){ sb[t] = bias[t]; ssum[t]=0.0; ssq[t]=0.0; }
  __syncthreads();

  float s[16], q[16];
#pragma unroll
  for (int c=0;c<16;c++){ s[c]=0.f; q[c]=0.f; }

  const float2* X = (const float2*)x;
  float2* T = (float2*)g_t;
  int stride = gridDim.x * blockDim.x;
  for (int p = blockIdx.x*blockDim.x + t; p < NHW2; p += stride){
    int n = p >> 17;
    int pix = p & (HW2-1);
    const float2* xp = X + (size_t)n*10*HW2 + pix;
    float2 in[10];
#pragma unroll
    for (int i=0;i<10;i++) in[i] = xp[(size_t)i*HW2];
    float2* op = T + (size_t)n*16*HW2 + pix;
#pragma unroll
    for (int c=0;c<16;c++){
      float vx = sb[c], vy = sb[c];
#pragma unroll
      for (int i=0;i<10;i++){ float wv = sw[c*10+i]; vx = fmaf(wv, in[i].x, vx); vy = fmaf(wv, in[i].y, vy); }
      float2 v; v.x = vx; v.y = vy;
      op[(size_t)c*HW2] = v;
      s[c] += vx + vy; q[c] += vx*vx + vy*vy;
    }
  }
#pragma unroll
  for (int c=0;c<16;c++){
    float a=s[c], b=q[c];
#pragma unroll
    for (int o=16;o>0;o>>=1){ a += __shfl_down_sync(0xffffffffu,a,o); b += __shfl_down_sync(0xffffffffu,b,o); }
    if ((t&31)==0){ atomicAdd(&ssum[c],(double)a); atomicAdd(&ssq[c],(double)b); }
  }
  __syncthreads();
  if (t<16){ atomicAdd(&g_sum1[t], ssum[t]); atomicAdd(&g_sq1[t], ssq[t]); }
}

// ---------------- K2/K4: finalize BN scale/shift ----------------
__global__ void k_fin(const float* __restrict__ gamma, const float* __restrict__ beta, int which){
  int c = threadIdx.x; if (c >= 16) return;
  double su = (which==0) ? g_sum1[c] : g_sum2[c];
  double sq = (which==0) ? g_sq1[c]  : g_sq2[c];
  double m  = su / (double)NHWp;
  double v  = sq / (double)NHWp - m*m;
  double a  = (double)gamma[c] / sqrt(v + 1e-5);
  float af = (float)a;
  float bf = (float)((double)beta[c] - a*m);
  if (which==0){ g_a1[c]=af; g_b1[c]=bf; } else { g_a2[c]=af; g_b2[c]=bf; }
}

// ---------------- K3: BN1+sigmoid -> 1x1 conv (16->16) in place + BN2 stats (float2) ----------------
__global__ void __launch_bounds__(256,2) k_stage2(const float* __restrict__ w2,
                                                  const float* __restrict__ b2){
  __shared__ float sw[256], sbias[16], sa[16], sb[16];
  __shared__ double ssum[16], ssq[16];
  int t = threadIdx.x;
  if (t < 256) sw[t] = w2[t];
  if (t < 16){ sbias[t]=b2[t]; sa[t]=g_a1[t]; sb[t]=g_b1[t]; ssum[t]=0.0; ssq[t]=0.0; }
  __syncthreads();

  float s[16], q[16];
#pragma unroll
  for (int c=0;c<16;c++){ s[c]=0.f; q[c]=0.f; }

  float2* T = (float2*)g_t;
  int stride = gridDim.x * blockDim.x;
  for (int p = blockIdx.x*blockDim.x + t; p < NHW2; p += stride){
    int n = p >> 17;
    int pix = p & (HW2-1);
    float2* bp = T + (size_t)n*16*HW2 + pix;
    float2 y[16];
#pragma unroll
    for (int c=0;c<16;c++){
      float2 v = bp[(size_t)c*HW2];
      y[c].x = sigm(fmaf(sa[c], v.x, sb[c]));
      y[c].y = sigm(fmaf(sa[c], v.y, sb[c]));
    }
#pragma unroll
    for (int o=0;o<16;o++){
      float zx = sbias[o], zy = sbias[o];
#pragma unroll
      for (int c=0;c<16;c++){ float wv = sw[o*16+c]; zx = fmaf(wv, y[c].x, zx); zy = fmaf(wv, y[c].y, zy); }
      float2 z; z.x = zx; z.y = zy;
      bp[(size_t)o*HW2] = z;
      s[o] += zx + zy; q[o] += zx*zx + zy*zy;
    }
  }
#pragma unroll
  for (int c=0;c<16;c++){
    float a=s[c], b=q[c];
#pragma unroll
    for (int o=16;o>0;o>>=1){ a += __shfl_down_sync(0xffffffffu,a,o); b += __shfl_down_sync(0xffffffffu,b,o); }
    if ((t&31)==0){ atomicAdd(&ssum[c],(double)a); atomicAdd(&ssq[c],(double)b); }
  }
  __syncthreads();
  if (t<16){ atomicAdd(&g_sum2[t], ssum[t]); atomicAdd(&g_sq2[t], ssq[t]); }
}

// ---------------- K5: per-(n,c) variance stats of h2 = sigmoid(BN2(z)) (float2) ----------------
__global__ void __launch_bounds__(256,2) k_varstats(){
  const int BPS = 64;                 // blocks per sample
  int n   = blockIdx.x / BPS;
  int blk = blockIdx.x % BPS;
  __shared__ float sa[16], sb[16];
  __shared__ double ssum[16], ssq[16];
  int t = threadIdx.x;
  if (t < 16){ sa[t]=g_a2[t]; sb[t]=g_b2[t]; ssum[t]=0.0; ssq[t]=0.0; }
  __syncthreads();

  float s[16], q[16];
#pragma unroll
  for (int c=0;c<16;c++){ s[c]=0.f; q[c]=0.f; }

  const int per = HW2 / BPS;          // 2048 float2 per block
  const float2* base = (const float2*)g_t + (size_t)n*16*HW2;
  for (int pix = blk*per + t; pix < (blk+1)*per; pix += 256){
#pragma unroll
    for (int c=0;c<16;c++){
      float2 v = base[(size_t)c*HW2 + pix];
      float hx = sigm(fmaf(sa[c], v.x, sb[c]));
      float hy = sigm(fmaf(sa[c], v.y, sb[c]));
      s[c] += hx + hy; q[c] += hx*hx + hy*hy;
    }
  }
#pragma unroll
  for (int c=0;c<16;c++){
    float a=s[c], b=q[c];
#pragma unroll
    for (int o=16;o>0;o>>=1){ a += __shfl_down_sync(0xffffffffu,a,o); b += __shfl_down_sync(0xffffffffu,b,o); }
    if ((t&31)==0){ atomicAdd(&ssum[c],(double)a); atomicAdd(&ssq[c],(double)b); }
  }
  __syncthreads();
  if (t<16){ atomicAdd(&g_vsum[n*16+t], ssum[t]); atomicAdd(&g_vsq[n*16+t], ssq[t]); }
}

// ---------------- K6: top-3 variance channels ----------------
__global__ void k_topk(){
  int n = threadIdx.x; if (n >= NB) return;
  double var[16];
  for (int c=0;c<16;c++){
    double s = g_vsum[n*16+c], qq = g_vsq[n*16+c];
    double m = s / (double)HWp;
    var[c] = (qq - s*m) / (double)(HWp - 1);   // ddof=1
  }
  int mask = 0;
  for (int k=0;k<3;k++){
    int best = 0; double bv = -1e300;
    for (int c=0;c<16;c++)
      if (!((mask>>c)&1) && var[c] > bv){ bv = var[c]; best = c; }
    mask |= 1<<best;
    g_idx[n*3+k] = best;
  }
}

// ---------------- K7: conv3x3 (3 selected -> 8) + sigmoid + maxpool2 ----------------
__global__ void __launch_bounds__(256,2) k_conv3a(const float* __restrict__ wc,
                                                  const float* __restrict__ bc){
  __shared__ float sp[3][34][36];
  __shared__ float sw[216], sbias[8];
  __shared__ float sa[3], sbb[3];
  __shared__ int   sch[3];
  int n = blockIdx.z;
  int t = threadIdx.x;
  if (t < 216) sw[t] = wc[t];
  if (t < 8)   sbias[t] = bc[t];
  if (t < 3){ int ch = g_idx[n*3+t]; sch[t]=ch; sa[t]=g_a2[ch]; sbb[t]=g_b2[ch]; }
  __syncthreads();

  int gy0 = blockIdx.y*32 - 1, gx0 = blockIdx.x*32 - 1;
  for (int i=t; i < 3*34*34; i += 256){
    int c = i / 1156, rem = i % 1156;
    int r = rem / 34, col = rem % 34;
    int gy = gy0 + r, gx = gx0 + col;
    float v = 0.f;
    if (gy >= 0 && gy < HH && gx >= 0 && gx < WW)
      v = sigm(fmaf(sa[c], g_t[(size_t)(n*16+sch[c])*HWp + gy*WW + gx], sbb[c]));
    sp[c][r][col] = v;
  }
  __syncthreads();

  int tx = t & 15, ty = t >> 4;
  int by = 2*ty, bx = 2*tx;
  float a00[8], a01[8], a10[8], a11[8];
#pragma unroll
  for (int oc=0;oc<8;oc++){ a00[oc]=a01[oc]=a10[oc]=a11[oc]=sbias[oc]; }
#pragma unroll
  for (int c=0;c<3;c++)
#pragma unroll
    for (int ky=0;ky<3;ky++)
#pragma unroll
      for (int kx=0;kx<3;kx++){
        float v00 = sp[c][by+ky  ][bx+kx  ];
        float v01 = sp[c][by+ky  ][bx+kx+1];
        float v10 = sp[c][by+ky+1][bx+kx  ];
        float v11 = sp[c][by+ky+1][bx+kx+1];
#pragma unroll
        for (int oc=0;oc<8;oc++){
          float wv = sw[oc*27 + c*9 + ky*3 + kx];
          a00[oc]=fmaf(v00,wv,a00[oc]); a01[oc]=fmaf(v01,wv,a01[oc]);
          a10[oc]=fmaf(v10,wv,a10[oc]); a11[oc]=fmaf(v11,wv,a11[oc]);
        }
      }
  int py = blockIdx.y*16 + ty, px = blockIdx.x*16 + tx;
#pragma unroll
  for (int oc=0;oc<8;oc++){
    float mx = fmaxf(fmaxf(a00[oc],a01[oc]), fmaxf(a10[oc],a11[oc]));
    g_x1[(size_t)(n*8+oc)*65536 + py*256 + px] = sigm(mx);  // sigmoid monotone: pool-then-sigmoid
  }
}

// ---------------- K8: conv3x3 (8 -> 16) + sigmoid + maxpool2 ----------------
__global__ void __launch_bounds__(256,2) k_conv3b(const float* __restrict__ wc,
                                                  const float* __restrict__ bc){
  __shared__ float sp[8][34][36];    // 39168 B
  __shared__ float sw[1152], sbias[16];
  int n = blockIdx.z;
  int t = threadIdx.x;
  for (int i=t; i<1152; i+=256) sw[i] = wc[i];
  if (t < 16) sbias[t] = bc[t];
  __syncthreads();

  int gy0 = blockIdx.y*32 - 1, gx0 = blockIdx.x*32 - 1;
  for (int i=t; i < 8*34*34; i += 256){
    int c = i / 1156, rem = i % 1156;
    int r = rem / 34, col = rem % 34;
    int gy = gy0 + r, gx = gx0 + col;
    float v = 0.f;
    if (gy >= 0 && gy < 256 && gx >= 0 && gx < 256)
      v = g_x1[(size_t)(n*8+c)*65536 + gy*256 + gx];
    sp[c][r][col] = v;
  }
  __syncthreads();

  int tx = t & 15, ty = t >> 4;
  int by = 2*ty, bx = 2*tx;
  float a00[16], a01[16], a10[16], a11[16];
#pragma unroll
  for (int oc=0;oc<16;oc++){ a00[oc]=a01[oc]=a10[oc]=a11[oc]=sbias[oc]; }
#pragma unroll
  for (int c=0;c<8;c++)
#pragma unroll
    for (int ky=0;ky<3;ky++)
#pragma unroll
      for (int kx=0;kx<3;kx++){
        float v00 = sp[c][by+ky  ][bx+kx  ];
        float v01 = sp[c][by+ky  ][bx+kx+1];
        float v10 = sp[c][by+ky+1][bx+kx  ];
        float v11 = sp[c][by+ky+1][bx+kx+1];
#pragma unroll
        for (int oc=0;oc<16;oc++){
          float wv = sw[oc*72 + c*9 + ky*3 + kx];
          a00[oc]=fmaf(v00,wv,a00[oc]); a01[oc]=fmaf(v01,wv,a01[oc]);
          a10[oc]=fmaf(v10,wv,a10[oc]); a11[oc]=fmaf(v11,wv,a11[oc]);
        }
      }
  int py = blockIdx.y*16 + ty, px = blockIdx.x*16 + tx;
#pragma unroll
  for (int oc=0;oc<16;oc++){
    float mx = fmaxf(fmaxf(a00[oc],a01[oc]), fmaxf(a10[oc],a11[oc]));
    g_x2[(size_t)(n*16+oc)*16384 + py*128 + px] = sigm(mx);
  }
}

// ---- bilinear helpers (jax.image.resize half-pixel centers, edge-normalized == clamp) ----
__device__ __forceinline__ void idx_up2(int h, int Hin, int& y0, int& y1, float& f){
  y0 = (h >> 1) - ((h & 1) ^ 1);
  f  = (h & 1) ? 0.25f : 0.75f;
  y1 = min(y0 + 1, Hin - 1);
  y0 = max(y0, 0);
}
__device__ __forceinline__ void idx_up4(int h, int Hin, int& y0, int& y1, float& f){
  int m = h & 3;
  y0 = (h >> 2) - (m < 2 ? 1 : 0);
  f  = (m==0) ? 0.625f : (m==1) ? 0.875f : (m==2) ? 0.125f : 0.375f;
  y1 = min(y0 + 1, Hin - 1);
  y0 = max(y0, 0);
}

// ---------------- K9a: stats of relu(up2(x1)) -> g_usum[0..7] ----------------
__global__ void __launch_bounds__(256,2) k_up2stats(){
  __shared__ double ssum[8], ssq[8];
  int t = threadIdx.x;
  if (t < 8){ ssum[t]=0.0; ssq[t]=0.0; }
  __syncthreads();

  float s[8], q[8];
#pragma unroll
  for (int c=0;c<8;c++){ s[c]=0.f; q[c]=0.f; }

  int stride = gridDim.x * blockDim.x;
  for (int p = blockIdx.x*blockDim.x + t; p < NHWp; p += stride){
    int n = p >> 18, pix = p & (HWp-1);
    int h = pix >> 9, w = pix & 511;
    int y0,y1,x0,x1; float fy,fx;
    idx_up2(h,256,y0,y1,fy); idx_up2(w,256,x0,x1,fx);
    int o00=y0*256+x0, o01=y0*256+x1, o10=y1*256+x0, o11=y1*256+x1;
    const float* bp = g_x1 + (size_t)n*8*65536;
#pragma unroll
    for (int c=0;c<8;c++){
      const float* pc = bp + (size_t)c*65536;
      float v0 = pc[o00] + fx*(pc[o01]-pc[o00]);
      float v1 = pc[o10] + fx*(pc[o11]-pc[o10]);
      float r  = fmaxf(v0 + fy*(v1-v0), 0.f);
      s[c] += r; q[c] += r*r;
    }
  }
#pragma unroll
  for (int c=0;c<8;c++){
    float a=s[c], b=q[c];
#pragma unroll
    for (int o=16;o>0;o>>=1){ a += __shfl_down_sync(0xffffffffu,a,o); b += __shfl_down_sync(0xffffffffu,b,o); }
    if ((t&31)==0){ atomicAdd(&ssum[c],(double)a); atomicAdd(&ssq[c],(double)b); }
  }
  __syncthreads();
  if (t<8){ atomicAdd(&g_usum[t], ssum[t]); atomicAdd(&g_usq[t], ssq[t]); }
}

// ---------------- K9b: stats of relu(up4(x2)) -> g_usum[8..23] ----------------
__global__ void __launch_bounds__(256,2) k_up4stats(){
  __shared__ double ssum[16], ssq[16];
  int t = threadIdx.x;
  if (t < 16){ ssum[t]=0.0; ssq[t]=0.0; }
  __syncthreads();

  float s[16], q[16];
#pragma unroll
  for (int c=0;c<16;c++){ s[c]=0.f; q[c]=0.f; }

  int stride = gridDim.x * blockDim.x;
  for (int p = blockIdx.x*blockDim.x + t; p < NHWp; p += stride){
    int n = p >> 18, pix = p & (HWp-1);
    int h = pix >> 9, w = pix & 511;
    int y0,y1,x0,x1; float fy,fx;
    idx_up4(h,128,y0,y1,fy); idx_up4(w,128,x0,x1,fx);
    int o00=y0*128+x0, o01=y0*128+x1, o10=y1*128+x0, o11=y1*128+x1;
    const float* bp = g_x2 + (size_t)n*16*16384;
#pragma unroll
    for (int c=0;c<16;c++){
      const float* pc = bp + (size_t)c*16384;
      float v0 = pc[o00] + fx*(pc[o01]-pc[o00]);
      float v1 = pc[o10] + fx*(pc[o11]-pc[o10]);
      float r  = fmaxf(v0 + fy*(v1-v0), 0.f);
      s[c] += r; q[c] += r*r;
    }
  }
#pragma unroll
  for (int c=0;c<16;c++){
    float a=s[c], b=q[c];
#pragma unroll
    for (int o=16;o>0;o>>=1){ a += __shfl_down_sync(0xffffffffu,a,o); b += __shfl_down_sync(0xffffffffu,b,o); }
    if ((t&31)==0){ atomicAdd(&ssum[c],(double)a); atomicAdd(&ssq[c],(double)b); }
  }
  __syncthreads();
  if (t<16){ atomicAdd(&g_usum[8+t], ssum[t]); atomicAdd(&g_usq[8+t], ssq[t]); }
}

// ---------------- K10: finalize upsample BNs (ch 0-7: bn2, ch 8-23: bn1) ----------------
__global__ void k_finup(const float* __restrict__ gbn1, const float* __restrict__ bbn1,
                        const float* __restrict__ gbn2, const float* __restrict__ bbn2){
  int c = threadIdx.x; if (c >= 24) return;
  double m = g_usum[c] / (double)NHWp;
  double v = g_usq[c]  / (double)NHWp - m*m;
  double gamma = (c < 8) ? (double)gbn2[c] : (double)gbn1[c-8];
  double beta  = (c < 8) ? (double)bbn2[c] : (double)bbn1[c-8];
  double a = gamma / sqrt(v + 1e-5);
  g_au[c] = (float)a;
  g_bu[c] = (float)(beta - a*m);
}

// ---------------- K11: up2/up4 + relu + BN + concat + 1x1 conv (24->5) ----------------
__global__ void __launch_bounds__(256,2) k_final(const float* __restrict__ w1k,
                                                 const float* __restrict__ b1k,
                                                 float* __restrict__ out){
  __shared__ float sw[120], sb5[5], sa[24], sbb[24];
  int t = threadIdx.x;
  if (t < 120) sw[t] = w1k[t];
  if (t < 5)   sb5[t] = b1k[t];
  if (t < 24){ sa[t] = g_au[t]; sbb[t] = g_bu[t]; }
  __syncthreads();

  int stride = gridDim.x * blockDim.x;
  for (int p = blockIdx.x*blockDim.x + t; p < NHWp; p += stride){
    int n = p >> 18, pix = p & (HWp-1);
    int h = pix >> 9, w = pix & 511;
    float acc[5];
#pragma unroll
    for (int k=0;k<5;k++) acc[k] = sb5[k];
    {
      int y0,y1,x0,x1; float fy,fx;
      idx_up2(h,256,y0,y1,fy); idx_up2(w,256,x0,x1,fx);
      int o00=y0*256+x0, o01=y0*256+x1, o10=y1*256+x0, o11=y1*256+x1;
      const float* bp = g_x1 + (size_t)n*8*65536;
#pragma unroll
      for (int c=0;c<8;c++){
        const float* pc = bp + (size_t)c*65536;
        float v0 = pc[o00] + fx*(pc[o01]-pc[o00]);
        float v1 = pc[o10] + fx*(pc[o11]-pc[o10]);
        float v  = v0 + fy*(v1-v0);
        float r  = fmaf(sa[c], fmaxf(v,0.f), sbb[c]);
#pragma unroll
        for (int k=0;k<5;k++) acc[k] = fmaf(sw[k*24+c], r, acc[k]);
      }
    }
    {
      int y0,y1,x0,x1; float fy,fx;
      idx_up4(h,128,y0,y1,fy); idx_up4(w,128,x0,x1,fx);
      int o00=y0*128+x0, o01=y0*128+x1, o10=y1*128+x0, o11=y1*128+x1;
      const float* bp = g_x2 + (size_t)n*16*16384;
#pragma unroll
      for (int c=0;c<16;c++){
        const float* pc = bp + (size_t)c*16384;
        float v0 = pc[o00] + fx*(pc[o01]-pc[o00]);
        float v1 = pc[o10] + fx*(pc[o11]-pc[o10]);
        float v  = v0 + fy*(v1-v0);
        float r  = fmaf(sa[8+c], fmaxf(v,0.f), sbb[8+c]);
#pragma unroll
        for (int k=0;k<5;k++) acc[k] = fmaf(sw[k*24+8+c], r, acc[k]);
      }
    }
#pragma unroll
    for (int k=0;k<5;k++)
      out[(size_t)(n*5+k)*HWp + pix] = acc[k];
  }
}

// ---------------- launch ----------------
extern "C" void kernel_launch(void* const* d_in, const int* in_sizes, int n_in,
                              void* d_out, int out_size){
  (void)in_sizes; (void)n_in; (void)out_size;
  const float* x       = (const float*)d_in[0];
  const float* w_ext1  = (const float*)d_in[1];
  const float* b_ext1  = (const float*)d_in[2];
  const float* g_ebn1  = (const float*)d_in[3];
  const float* be_ebn1 = (const float*)d_in[4];
  const float* w_ext2  = (const float*)d_in[5];
  const float* b_ext2  = (const float*)d_in[6];
  const float* g_ebn2  = (const float*)d_in[7];
  const float* be_ebn2 = (const float*)d_in[8];
  const float* w_c1    = (const float*)d_in[9];
  const float* b_c1    = (const float*)d_in[10];
  const float* w_c2    = (const float*)d_in[11];
  const float* b_c2    = (const float*)d_in[12];
  const float* g_bn1   = (const float*)d_in[13];
  const float* be_bn1  = (const float*)d_in[14];
  const float* g_bn2   = (const float*)d_in[15];
  const float* be_bn2  = (const float*)d_in[16];
  const float* w_1k    = (const float*)d_in[17];
  const float* b_1k    = (const float*)d_in[18];
  float* out = (float*)d_out;

  const int GS = 1184;

  k_zero<<<1,256>>>();
  k_conv1<<<GS,256>>>(x, w_ext1, b_ext1);
  k_fin<<<1,16>>>(g_ebn1, be_ebn1, 0);
  k_stage2<<<GS,256>>>(w_ext2, b_ext2);
  k_fin<<<1,16>>>(g_ebn2, be_ebn2, 1);
  k_varstats<<<16*64,256>>>();
  k_topk<<<1,16>>>();
  k_conv3a<<<dim3(16,16,16),256>>>(w_c1, b_c1);
  k_conv3b<<<dim3(8,8,16),256>>>(w_c2, b_c2);
  k_up2stats<<<GS,256>>>();
  k_up4stats<<<GS,256>>>();
  k_finup<<<1,24>>>(g_bn1, be_bn1, g_bn2, be_bn2);
  k_final<<<GS,256>>>(w_1k, b_1k, out);
}

// round 11
// speedup vs baseline: 3.0160x; 1.7251x over previous
#include <cuda_runtime.h>
#include <math.h>

// Problem constants
#define NB   16
#define HH   512
#define WW   512
#define HWp  (HH*WW)     // 262144
#define HW2  (HWp/2)     // 131072
#define NHWp (NB*HWp)    // 4194304
#define NHW2 (NB*HW2)    // 2097152

// ---------------- constant weights (copied at capture start, D2D) ----------------
__constant__ float c_w1[160];    // w_ext1 [16][10]
__constant__ float c_b1[16];
__constant__ float c_w2[256];    // w_ext2 [16][16]
__constant__ float c_b2[16];
__constant__ float c_wc1[216];   // w_c1 [8][3][3][3]
__constant__ float c_bc1[8];
__constant__ float c_wc2[1152];  // w_c2 [16][8][3][3]
__constant__ float c_bc2[16];
__constant__ float c_w1k[120];   // w_1k [5][24]
__constant__ float c_b1k[5];

// ---------------- device scratch ----------------
static __device__ float  g_t [67108864];   // z2: [16,16,512,512]
static __device__ float  g_x1[ 8388608];   // [16, 8,256,256]
static __device__ float  g_x2[ 4194304];   // [16,16,128,128]
static __device__ double g_cov[75];        // [0..9] sums, [10..74] upper-tri products
static __device__ double g_sum2[16], g_sq2[16];
static __device__ double g_vsum[NB*16], g_vsq[NB*16];
static __device__ double g_usum[24], g_usq[24];
static __device__ float  g_a1[16], g_b1[16], g_a2[16], g_b2[16];
static __device__ float  g_au[24], g_bu[24];
static __device__ int    g_idx[NB*3];

__device__ __forceinline__ float sigm(float x){
  return __fdividef(1.0f, 1.0f + __expf(-x));
}

// ---------------- K0: zero accumulators ----------------
__global__ void k_zero(){
  int t = threadIdx.x;
  if (t < 16){ g_sum2[t]=0.0; g_sq2[t]=0.0; }
  if (t < 24){ g_usum[t]=0.0; g_usq[t]=0.0; }
  if (t < 75){ g_cov[t]=0.0; }
  if (t < 256){ g_vsum[t]=0.0; g_vsq[t]=0.0; }
}

// ---------------- K1: covariance stats of x (10 sums + 55 products) ----------------
__global__ void __launch_bounds__(256,2) k_cov(const float* __restrict__ x){
  __shared__ double sred[75];
  int t = threadIdx.x;
  if (t < 75) sred[t] = 0.0;
  __syncthreads();

  float s[10], pp[55];
#pragma unroll
  for (int i=0;i<10;i++) s[i]=0.f;
#pragma unroll
  for (int k=0;k<55;k++) pp[k]=0.f;

  const float2* X = (const float2*)x;
  int stride = gridDim.x * blockDim.x;
  for (int p = blockIdx.x*blockDim.x + t; p < NHW2; p += stride){
    int n = p >> 17, pix = p & (HW2-1);
    const float2* xp = X + (size_t)n*10*HW2 + pix;
    float2 in[10];
#pragma unroll
    for (int i=0;i<10;i++) in[i] = xp[(size_t)i*HW2];
    int k = 0;
#pragma unroll
    for (int i=0;i<10;i++){
      s[i] += in[i].x + in[i].y;
#pragma unroll
      for (int j=i;j<10;j++){
        pp[k] = fmaf(in[i].x, in[j].x, fmaf(in[i].y, in[j].y, pp[k]));
        k++;
      }
    }
  }
  // reduce
#pragma unroll
  for (int i=0;i<10;i++){
    float a = s[i];
#pragma unroll
    for (int o=16;o>0;o>>=1) a += __shfl_down_sync(0xffffffffu,a,o);
    if ((t&31)==0) atomicAdd(&sred[i], (double)a);
  }
#pragma unroll
  for (int k=0;k<55;k++){
    float a = pp[k];
#pragma unroll
    for (int o=16;o>0;o>>=1) a += __shfl_down_sync(0xffffffffu,a,o);
    if ((t&31)==0) atomicAdd(&sred[10+k], (double)a);
  }
  __syncthreads();
  if (t < 75) atomicAdd(&g_cov[t], sred[t]);
}

// ---------------- K2: BN1 coefficients from covariance ----------------
__global__ void k_fin1cov(const float* __restrict__ gamma, const float* __restrict__ beta){
  int c = threadIdx.x; if (c >= 16) return;
  double m[10];
  for (int i=0;i<10;i++) m[i] = g_cov[i] / (double)NHWp;
  double mean = (double)c_b1[c];
  for (int i=0;i<10;i++) mean += (double)c_w1[c*10+i] * m[i];
  double var = 0.0;
  int k = 10;
  for (int i=0;i<10;i++){
    for (int j=i;j<10;j++){
      double cov = g_cov[k] / (double)NHWp - m[i]*m[j];
      double wp  = (double)c_w1[c*10+i] * (double)c_w1[c*10+j];
      var += (i==j ? 1.0 : 2.0) * wp * cov;
      k++;
    }
  }
  double a = (double)gamma[c] / sqrt(var + 1e-5);
  g_a1[c] = (float)a;
  g_b1[c] = (float)((double)beta[c] - a*mean);
}

// ---------------- K3: fused conv1+BN1+sigm+conv2 -> z2, BN2 stats ----------------
__global__ void __launch_bounds__(256,2) k_fused(const float* __restrict__ x){
  __shared__ float sa[16], sb[16];
  __shared__ double ssum[16], ssq[16];
  int t = threadIdx.x;
  if (t < 16){ sa[t]=g_a1[t]; sb[t]=g_b1[t]; ssum[t]=0.0; ssq[t]=0.0; }
  __syncthreads();

  float s[16], q[16];
#pragma unroll
  for (int c=0;c<16;c++){ s[c]=0.f; q[c]=0.f; }

  const float2* X = (const float2*)x;
  float2* T = (float2*)g_t;
  int stride = gridDim.x * blockDim.x;
  for (int p = blockIdx.x*blockDim.x + t; p < NHW2; p += stride){
    int n = p >> 17, pix = p & (HW2-1);
    const float2* xp = X + (size_t)n*10*HW2 + pix;
    float2 in[10];
#pragma unroll
    for (int i=0;i<10;i++) in[i] = xp[(size_t)i*HW2];

    float2 acc[16];
#pragma unroll
    for (int o=0;o<16;o++){ acc[o].x = c_b2[o]; acc[o].y = c_b2[o]; }

#pragma unroll
    for (int c=0;c<16;c++){
      float zx = c_b1[c], zy = c_b1[c];
#pragma unroll
      for (int i=0;i<10;i++){
        float wv = c_w1[c*10+i];
        zx = fmaf(wv, in[i].x, zx);
        zy = fmaf(wv, in[i].y, zy);
      }
      float ac = sa[c], bc = sb[c];
      float yx = sigm(fmaf(ac, zx, bc));
      float yy = sigm(fmaf(ac, zy, bc));
#pragma unroll
      for (int o=0;o<16;o++){
        float wv = c_w2[o*16+c];
        acc[o].x = fmaf(wv, yx, acc[o].x);
        acc[o].y = fmaf(wv, yy, acc[o].y);
      }
    }
    float2* op = T + (size_t)n*16*HW2 + pix;
#pragma unroll
    for (int o=0;o<16;o++){
      op[(size_t)o*HW2] = acc[o];
      s[o] += acc[o].x + acc[o].y;
      q[o] = fmaf(acc[o].x, acc[o].x, fmaf(acc[o].y, acc[o].y, q[o]));
    }
  }
#pragma unroll
  for (int c=0;c<16;c++){
    float a=s[c], b=q[c];
#pragma unroll
    for (int o=16;o>0;o>>=1){ a += __shfl_down_sync(0xffffffffu,a,o); b += __shfl_down_sync(0xffffffffu,b,o); }
    if ((t&31)==0){ atomicAdd(&ssum[c],(double)a); atomicAdd(&ssq[c],(double)b); }
  }
  __syncthreads();
  if (t<16){ atomicAdd(&g_sum2[t], ssum[t]); atomicAdd(&g_sq2[t], ssq[t]); }
}

// ---------------- K4: finalize BN2 ----------------
__global__ void k_fin2(const float* __restrict__ gamma, const float* __restrict__ beta){
  int c = threadIdx.x; if (c >= 16) return;
  double m = g_sum2[c] / (double)NHWp;
  double v = g_sq2[c]  / (double)NHWp - m*m;
  double a = (double)gamma[c] / sqrt(v + 1e-5);
  g_a2[c] = (float)a;
  g_b2[c] = (float)((double)beta[c] - a*m);
}

// ---------------- K5: per-(n,c) variance stats of h2 = sigm(BN2(z2)) ----------------
__global__ void __launch_bounds__(256,3) k_varstats(){
  const int BPS = 64;
  int n   = blockIdx.x / BPS;
  int blk = blockIdx.x % BPS;
  __shared__ float sa[16], sb[16];
  __shared__ double ssum[16], ssq[16];
  int t = threadIdx.x;
  if (t < 16){ sa[t]=g_a2[t]; sb[t]=g_b2[t]; ssum[t]=0.0; ssq[t]=0.0; }
  __syncthreads();

  float s[16], q[16];
#pragma unroll
  for (int c=0;c<16;c++){ s[c]=0.f; q[c]=0.f; }

  const int per = HW2 / BPS;
  const float2* base = (const float2*)g_t + (size_t)n*16*HW2;
  for (int pix = blk*per + t; pix < (blk+1)*per; pix += 256){
#pragma unroll
    for (int c=0;c<16;c++){
      float2 v = base[(size_t)c*HW2 + pix];
      float hx = sigm(fmaf(sa[c], v.x, sb[c]));
      float hy = sigm(fmaf(sa[c], v.y, sb[c]));
      s[c] += hx + hy;
      q[c] = fmaf(hx,hx, fmaf(hy,hy,q[c]));
    }
  }
#pragma unroll
  for (int c=0;c<16;c++){
    float a=s[c], b=q[c];
#pragma unroll
    for (int o=16;o>0;o>>=1){ a += __shfl_down_sync(0xffffffffu,a,o); b += __shfl_down_sync(0xffffffffu,b,o); }
    if ((t&31)==0){ atomicAdd(&ssum[c],(double)a); atomicAdd(&ssq[c],(double)b); }
  }
  __syncthreads();
  if (t<16){ atomicAdd(&g_vsum[n*16+t], ssum[t]); atomicAdd(&g_vsq[n*16+t], ssq[t]); }
}

// ---------------- K6: top-3 variance channels ----------------
__global__ void k_topk(){
  int n = threadIdx.x; if (n >= NB) return;
  double var[16];
  for (int c=0;c<16;c++){
    double s = g_vsum[n*16+c], qq = g_vsq[n*16+c];
    double m = s / (double)HWp;
    var[c] = (qq - s*m) / (double)(HWp - 1);
  }
  int mask = 0;
  for (int k=0;k<3;k++){
    int best = 0; double bv = -1e300;
    for (int c=0;c<16;c++)
      if (!((mask>>c)&1) && var[c] > bv){ bv = var[c]; best = c; }
    mask |= 1<<best;
    g_idx[n*3+k] = best;
  }
}

// ---------------- K7: conv3x3 (3 sel -> 8) + sigm + maxpool2 ----------------
__global__ void __launch_bounds__(256,2) k_conv3a(){
  __shared__ float sp[3][34][36];
  __shared__ float sa[3], sbb[3];
  __shared__ int   sch[3];
  int n = blockIdx.z;
  int t = threadIdx.x;
  if (t < 3){ int ch = g_idx[n*3+t]; sch[t]=ch; sa[t]=g_a2[ch]; sbb[t]=g_b2[ch]; }
  __syncthreads();

  int gy0 = blockIdx.y*32 - 1, gx0 = blockIdx.x*32 - 1;
  for (int i=t; i < 3*34*34; i += 256){
    int c = i / 1156, rem = i % 1156;
    int r = rem / 34, col = rem % 34;
    int gy = gy0 + r, gx = gx0 + col;
    float v = 0.f;
    if (gy >= 0 && gy < HH && gx >= 0 && gx < WW)
      v = sigm(fmaf(sa[c], g_t[(size_t)(n*16+sch[c])*HWp + gy*WW + gx], sbb[c]));
    sp[c][r][col] = v;
  }
  __syncthreads();

  int tx = t & 15, ty = t >> 4;
  int by = 2*ty, bx = 2*tx;
  float a00[8], a01[8], a10[8], a11[8];
#pragma unroll
  for (int oc=0;oc<8;oc++){ a00[oc]=a01[oc]=a10[oc]=a11[oc]=c_bc1[oc]; }
#pragma unroll
  for (int c=0;c<3;c++)
#pragma unroll
    for (int ky=0;ky<3;ky++)
#pragma unroll
      for (int kx=0;kx<3;kx++){
        float v00 = sp[c][by+ky  ][bx+kx  ];
        float v01 = sp[c][by+ky  ][bx+kx+1];
        float v10 = sp[c][by+ky+1][bx+kx  ];
        float v11 = sp[c][by+ky+1][bx+kx+1];
#pragma unroll
        for (int oc=0;oc<8;oc++){
          float wv = c_wc1[oc*27 + c*9 + ky*3 + kx];
          a00[oc]=fmaf(v00,wv,a00[oc]); a01[oc]=fmaf(v01,wv,a01[oc]);
          a10[oc]=fmaf(v10,wv,a10[oc]); a11[oc]=fmaf(v11,wv,a11[oc]);
        }
      }
  int py = blockIdx.y*16 + ty, px = blockIdx.x*16 + tx;
#pragma unroll
  for (int oc=0;oc<8;oc++){
    float mx = fmaxf(fmaxf(a00[oc],a01[oc]), fmaxf(a10[oc],a11[oc]));
    g_x1[(size_t)(n*8+oc)*65536 + py*256 + px] = sigm(mx);   // sigmoid monotone
  }
}

// ---------------- K8: conv3x3 (8 -> 16) + sigm + maxpool2 ----------------
__global__ void __launch_bounds__(256,2) k_conv3b(){
  __shared__ float sp[8][34][36];
  int n = blockIdx.z;
  int t = threadIdx.x;

  int gy0 = blockIdx.y*32 - 1, gx0 = blockIdx.x*32 - 1;
  for (int i=t; i < 8*34*34; i += 256){
    int c = i / 1156, rem = i % 1156;
    int r = rem / 34, col = rem % 34;
    int gy = gy0 + r, gx = gx0 + col;
    float v = 0.f;
    if (gy >= 0 && gy < 256 && gx >= 0 && gx < 256)
      v = g_x1[(size_t)(n*8+c)*65536 + gy*256 + gx];
    sp[c][r][col] = v;
  }
  __syncthreads();

  int tx = t & 15, ty = t >> 4;
  int by = 2*ty, bx = 2*tx;
  float a00[16], a01[16], a10[16], a11[16];
#pragma unroll
  for (int oc=0;oc<16;oc++){ a00[oc]=a01[oc]=a10[oc]=a11[oc]=c_bc2[oc]; }
#pragma unroll
  for (int c=0;c<8;c++)
#pragma unroll
    for (int ky=0;ky<3;ky++)
#pragma unroll
      for (int kx=0;kx<3;kx++){
        float v00 = sp[c][by+ky  ][bx+kx  ];
        float v01 = sp[c][by+ky  ][bx+kx+1];
        float v10 = sp[c][by+ky+1][bx+kx  ];
        float v11 = sp[c][by+ky+1][bx+kx+1];
#pragma unroll
        for (int oc=0;oc<16;oc++){
          float wv = c_wc2[oc*72 + c*9 + ky*3 + kx];
          a00[oc]=fmaf(v00,wv,a00[oc]); a01[oc]=fmaf(v01,wv,a01[oc]);
          a10[oc]=fmaf(v10,wv,a10[oc]); a11[oc]=fmaf(v11,wv,a11[oc]);
        }
      }
  int py = blockIdx.y*16 + ty, px = blockIdx.x*16 + tx;
#pragma unroll
  for (int oc=0;oc<16;oc++){
    float mx = fmaxf(fmaxf(a00[oc],a01[oc]), fmaxf(a10[oc],a11[oc]));
    g_x2[(size_t)(n*16+oc)*16384 + py*128 + px] = sigm(mx);
  }
}

// ---- vertical index helpers (jax half-pixel bilinear, clamped) ----
__device__ __forceinline__ void idx_up2(int h, int Hin, int& y0, int& y1, float& f){
  y0 = (h >> 1) - ((h & 1) ^ 1);
  f  = (h & 1) ? 0.25f : 0.75f;
  y1 = min(y0 + 1, Hin - 1);
  y0 = max(y0, 0);
}
__device__ __forceinline__ void idx_up4(int h, int Hin, int& y0, int& y1, float& f){
  int m = h & 3;
  y0 = (h >> 2) - (m < 2 ? 1 : 0);
  f  = (m==0) ? 0.625f : (m==1) ? 0.875f : (m==2) ? 0.125f : 0.375f;
  y1 = min(y0 + 1, Hin - 1);
  y0 = max(y0, 0);
}
#define LERP(a,b,f) ((a) + (f)*((b)-(a)))

// NOTE: x1/x2 are sigmoid outputs (>0); bilinear weights are nonneg => relu is identity.

// ---------------- K9a: stats of up2(x1) -> g_usum[0..7] (quad per thread) ----------------
__global__ void __launch_bounds__(256,3) k_up2stats(){
  __shared__ double ssum[8], ssq[8];
  int t = threadIdx.x;
  if (t < 8){ ssum[t]=0.0; ssq[t]=0.0; }
  __syncthreads();

  float s[8], q[8];
#pragma unroll
  for (int c=0;c<8;c++){ s[c]=0.f; q[c]=0.f; }

  const int NQ = NHWp/4;           // 1048576; per sample 512*128 = 65536
  int stride = gridDim.x * blockDim.x;
  for (int p = blockIdx.x*blockDim.x + t; p < NQ; p += stride){
    int n = p >> 16, r = p & 65535;
    int h = r >> 7, w = r & 127;
    int y0,y1; float fy; idx_up2(h,256,y0,y1,fy);
    int c0 = max(2*w-1,0), c1 = 2*w, c2 = 2*w+1, c3 = min(2*w+2,255);
    const float* bp = g_x1 + (size_t)n*8*65536;
#pragma unroll
    for (int c=0;c<8;c++){
      const float* p0 = bp + (size_t)c*65536 + y0*256;
      const float* p1 = bp + (size_t)c*65536 + y1*256;
      float vv0 = LERP(p0[c0], p1[c0], fy);
      float vv1 = LERP(p0[c1], p1[c1], fy);
      float vv2 = LERP(p0[c2], p1[c2], fy);
      float vv3 = LERP(p0[c3], p1[c3], fy);
      float o0 = LERP(vv0, vv1, 0.75f);
      float o1 = LERP(vv1, vv2, 0.25f);
      float o2 = LERP(vv1, vv2, 0.75f);
      float o3 = LERP(vv2, vv3, 0.25f);
      s[c] += (o0+o1) + (o2+o3);
      q[c] = fmaf(o0,o0, fmaf(o1,o1, fmaf(o2,o2, fmaf(o3,o3, q[c]))));
    }
  }
#pragma unroll
  for (int c=0;c<8;c++){
    float a=s[c], b=q[c];
#pragma unroll
    for (int o=16;o>0;o>>=1){ a += __shfl_down_sync(0xffffffffu,a,o); b += __shfl_down_sync(0xffffffffu,b,o); }
    if ((t&31)==0){ atomicAdd(&ssum[c],(double)a); atomicAdd(&ssq[c],(double)b); }
  }
  __syncthreads();
  if (t<8){ atomicAdd(&g_usum[t], ssum[t]); atomicAdd(&g_usq[t], ssq[t]); }
}

// ---------------- K9b: stats of up4(x2) -> g_usum[8..23] (quad per thread) ----------------
__global__ void __launch_bounds__(256,3) k_up4stats(){
  __shared__ double ssum[16], ssq[16];
  int t = threadIdx.x;
  if (t < 16){ ssum[t]=0.0; ssq[t]=0.0; }
  __syncthreads();

  float s[16], q[16];
#pragma unroll
  for (int c=0;c<16;c++){ s[c]=0.f; q[c]=0.f; }

  const int NQ = NHWp/4;
  int stride = gridDim.x * blockDim.x;
  for (int p = blockIdx.x*blockDim.x + t; p < NQ; p += stride){
    int n = p >> 16, r = p & 65535;
    int h = r >> 7, w = r & 127;
    int y0,y1; float fy; idx_up4(h,128,y0,y1,fy);
    int cm = max(w-1,0), cc = w, cp = min(w+1,127);
    const float* bp = g_x2 + (size_t)n*16*16384;
#pragma unroll
    for (int c=0;c<16;c++){
      const float* p0 = bp + (size_t)c*16384 + y0*128;
      const float* p1 = bp + (size_t)c*16384 + y1*128;
      float vv0 = LERP(p0[cm], p1[cm], fy);
      float vv1 = LERP(p0[cc], p1[cc], fy);
      float vv2 = LERP(p0[cp], p1[cp], fy);
      float o0 = LERP(vv0, vv1, 0.625f);
      float o1 = LERP(vv0, vv1, 0.875f);
      float o2 = LERP(vv1, vv2, 0.125f);
      float o3 = LERP(vv1, vv2, 0.375f);
      s[c] += (o0+o1) + (o2+o3);
      q[c] = fmaf(o0,o0, fmaf(o1,o1, fmaf(o2,o2, fmaf(o3,o3, q[c]))));
    }
  }
#pragma unroll
  for (int c=0;c<16;c++){
    float a=s[c], b=q[c];
#pragma unroll
    for (int o=16;o>0;o>>=1){ a += __shfl_down_sync(0xffffffffu,a,o); b += __shfl_down_sync(0xffffffffu,b,o); }
    if ((t&31)==0){ atomicAdd(&ssum[c],(double)a); atomicAdd(&ssq[c],(double)b); }
  }
  __syncthreads();
  if (t<16){ atomicAdd(&g_usum[8+t], ssum[t]); atomicAdd(&g_usq[8+t], ssq[t]); }
}

// ---------------- K10: finalize upsample BNs ----------------
__global__ void k_finup(const float* __restrict__ gbn1, const float* __restrict__ bbn1,
                        const float* __restrict__ gbn2, const float* __restrict__ bbn2){
  int c = threadIdx.x; if (c >= 24) return;
  double m = g_usum[c] / (double)NHWp;
  double v = g_usq[c]  / (double)NHWp - m*m;
  double gamma = (c < 8) ? (double)gbn2[c] : (double)gbn1[c-8];
  double beta  = (c < 8) ? (double)bbn2[c] : (double)bbn1[c-8];
  double a = gamma / sqrt(v + 1e-5);
  g_au[c] = (float)a;
  g_bu[c] = (float)(beta - a*m);
}

// ---------------- K11: up2/up4 + BN + concat + 1x1 conv (24->5), quad per thread ----------------
__global__ void __launch_bounds__(256,3) k_final(float* __restrict__ out){
  __shared__ float sa[24], sbb[24];
  int t = threadIdx.x;
  if (t < 24){ sa[t] = g_au[t]; sbb[t] = g_bu[t]; }
  __syncthreads();

  const int NQ = NHWp/4;
  int stride = gridDim.x * blockDim.x;
  for (int p = blockIdx.x*blockDim.x + t; p < NQ; p += stride){
    int n = p >> 16, r = p & 65535;
    int h = r >> 7, w = r & 127;

    float a0[5], a1[5], a2[5], a3[5];
#pragma unroll
    for (int k=0;k<5;k++){ a0[k]=a1[k]=a2[k]=a3[k]=c_b1k[k]; }

    {   // up2 path: channels 0..7
      int y0,y1; float fy; idx_up2(h,256,y0,y1,fy);
      int c0 = max(2*w-1,0), c1 = 2*w, c2 = 2*w+1, c3 = min(2*w+2,255);
      const float* bp = g_x1 + (size_t)n*8*65536;
#pragma unroll
      for (int c=0;c<8;c++){
        const float* p0 = bp + (size_t)c*65536 + y0*256;
        const float* p1 = bp + (size_t)c*65536 + y1*256;
        float vv0 = LERP(p0[c0], p1[c0], fy);
        float vv1 = LERP(p0[c1], p1[c1], fy);
        float vv2 = LERP(p0[c2], p1[c2], fy);
        float vv3 = LERP(p0[c3], p1[c3], fy);
        float sc = sa[c], sh = sbb[c];
        float r0 = fmaf(sc, LERP(vv0, vv1, 0.75f), sh);
        float r1 = fmaf(sc, LERP(vv1, vv2, 0.25f), sh);
        float r2 = fmaf(sc, LERP(vv1, vv2, 0.75f), sh);
        float r3 = fmaf(sc, LERP(vv2, vv3, 0.25f), sh);
#pragma unroll
        for (int k=0;k<5;k++){
          float wv = c_w1k[k*24+c];
          a0[k]=fmaf(wv,r0,a0[k]); a1[k]=fmaf(wv,r1,a1[k]);
          a2[k]=fmaf(wv,r2,a2[k]); a3[k]=fmaf(wv,r3,a3[k]);
        }
      }
    }
    {   // up4 path: channels 8..23
      int y0,y1; float fy; idx_up4(h,128,y0,y1,fy);
      int cm = max(w-1,0), cc = w, cp = min(w+1,127);
      const float* bp = g_x2 + (size_t)n*16*16384;
#pragma unroll
      for (int c=0;c<16;c++){
        const float* p0 = bp + (size_t)c*16384 + y0*128;
        const float* p1 = bp + (size_t)c*16384 + y1*128;
        float vv0 = LERP(p0[cm], p1[cm], fy);
        float vv1 = LERP(p0[cc], p1[cc], fy);
        float vv2 = LERP(p0[cp], p1[cp], fy);
        float sc = sa[8+c], sh = sbb[8+c];
        float r0 = fmaf(sc, LERP(vv0, vv1, 0.625f), sh);
        float r1 = fmaf(sc, LERP(vv0, vv1, 0.875f), sh);
        float r2 = fmaf(sc, LERP(vv1, vv2, 0.125f), sh);
        float r3 = fmaf(sc, LERP(vv1, vv2, 0.375f), sh);
#pragma unroll
        for (int k=0;k<5;k++){
          float wv = c_w1k[k*24+8+c];
          a0[k]=fmaf(wv,r0,a0[k]); a1[k]=fmaf(wv,r1,a1[k]);
          a2[k]=fmaf(wv,r2,a2[k]); a3[k]=fmaf(wv,r3,a3[k]);
        }
      }
    }
#pragma unroll
    for (int k=0;k<5;k++){
      float4 v; v.x=a0[k]; v.y=a1[k]; v.z=a2[k]; v.w=a3[k];
      *(float4*)(out + (size_t)(n*5+k)*HWp + h*512 + 4*w) = v;
    }
  }
}

// ---------------- launch ----------------
extern "C" void kernel_launch(void* const* d_in, const int* in_sizes, int n_in,
                              void* d_out, int out_size){
  (void)in_sizes; (void)n_in; (void)out_size;
  const float* x       = (const float*)d_in[0];
  const float* g_ebn1  = (const float*)d_in[3];
  const float* be_ebn1 = (const float*)d_in[4];
  const float* g_ebn2  = (const float*)d_in[7];
  const float* be_ebn2 = (const float*)d_in[8];
  const float* g_bn1   = (const float*)d_in[13];
  const float* be_bn1  = (const float*)d_in[14];
  const float* g_bn2   = (const float*)d_in[15];
  const float* be_bn2  = (const float*)d_in[16];
  float* out = (float*)d_out;

  // weights -> constant memory (D2D memcpy nodes, capture-legal)
  cudaMemcpyToSymbolAsync(c_w1,  d_in[1],  160*sizeof(float), 0, cudaMemcpyDeviceToDevice, 0);
  cudaMemcpyToSymbolAsync(c_b1,  d_in[2],   16*sizeof(float), 0, cudaMemcpyDeviceToDevice, 0);
  cudaMemcpyToSymbolAsync(c_w2,  d_in[5],  256*sizeof(float), 0, cudaMemcpyDeviceToDevice, 0);
  cudaMemcpyToSymbolAsync(c_b2,  d_in[6],   16*sizeof(float), 0, cudaMemcpyDeviceToDevice, 0);
  cudaMemcpyToSymbolAsync(c_wc1, d_in[9],  216*sizeof(float), 0, cudaMemcpyDeviceToDevice, 0);
  cudaMemcpyToSymbolAsync(c_bc1, d_in[10],   8*sizeof(float), 0, cudaMemcpyDeviceToDevice, 0);
  cudaMemcpyToSymbolAsync(c_wc2, d_in[11],1152*sizeof(float), 0, cudaMemcpyDeviceToDevice, 0);
  cudaMemcpyToSymbolAsync(c_bc2, d_in[12],  16*sizeof(float), 0, cudaMemcpyDeviceToDevice, 0);
  cudaMemcpyToSymbolAsync(c_w1k, d_in[17], 120*sizeof(float), 0, cudaMemcpyDeviceToDevice, 0);
  cudaMemcpyToSymbolAsync(c_b1k, d_in[18],   5*sizeof(float), 0, cudaMemcpyDeviceToDevice, 0);

  const int GS = 1184;

  k_zero<<<1,256>>>();
  k_cov<<<GS,256>>>(x);
  k_fin1cov<<<1,16>>>(g_ebn1, be_ebn1);
  k_fused<<<GS,256>>>(x);
  k_fin2<<<1,16>>>(g_ebn2, be_ebn2);
  k_varstats<<<16*64,256>>>();
  k_topk<<<1,16>>>();
  k_conv3a<<<dim3(16,16,16),256>>>();
  k_conv3b<<<dim3(8,8,16),256>>>();
  k_up2stats<<<GS,256>>>();
  k_up4stats<<<GS,256>>>();
  k_finup<<<1,24>>>(g_bn1, be_bn1, g_bn2, be_bn2);
  k_final<<<GS,256>>>(out);
}

// round 12
// speedup vs baseline: 3.0412x; 1.0084x over previous
#include <cuda_runtime.h>
#include <math.h>

// Problem constants
#define NB   16
#define HH   512
#define WW   512
#define HWp  (HH*WW)     // 262144
#define HW2  (HWp/2)     // 131072
#define NHWp (NB*HWp)    // 4194304
#define NHW2 (NB*HW2)    // 2097152

typedef unsigned long long u64t;

// ---------------- packed f32x2 helpers (sm_103a FFMA2 path) ----------------
__device__ __forceinline__ u64t pk2(float lo, float hi){
  u64t r; asm("mov.b64 %0,{%1,%2};" : "=l"(r) : "f"(lo), "f"(hi)); return r;
}
__device__ __forceinline__ void upk2(u64t v, float& lo, float& hi){
  asm("mov.b64 {%0,%1},%2;" : "=f"(lo), "=f"(hi) : "l"(v));
}
__device__ __forceinline__ u64t fma2(u64t a, u64t b, u64t c){
  u64t d; asm("fma.rn.f32x2 %0,%1,%2,%3;" : "=l"(d) : "l"(a), "l"(b), "l"(c)); return d;
}

// ---------------- constant weights ----------------
__constant__ float c_w1[160];    // scalar (for fin1cov)
__constant__ float c_b1[16];
// duplicated {w,w} packed weights, one flat array
// layout: W1[0..159] B1[160..175] W2[176..431] B2[432..447] WC1[448..663]
//         BC1[664..671] WC2[672..1823] BC2[1824..1839] W1K[1840..1959] B1K[1960..1964]
#define NDUP 1965
__constant__ u64t c_dup[NDUP];
#define DW1(i)  c_dup[(i)]
#define DB1(i)  c_dup[160+(i)]
#define DW2(i)  c_dup[176+(i)]
#define DB2(i)  c_dup[432+(i)]
#define DWC1(i) c_dup[448+(i)]
#define DBC1(i) c_dup[664+(i)]
#define DWC2(i) c_dup[672+(i)]
#define DBC2(i) c_dup[1824+(i)]
#define DW1K(i) c_dup[1840+(i)]
#define DB1K(i) c_dup[1960+(i)]

// ---------------- device scratch ----------------
static __device__ float  g_t [67108864];   // z2: [16,16,512,512]
static __device__ float  g_x1[ 8388608];   // [16, 8,256,256]
static __device__ float  g_x2[ 4194304];   // [16,16,128,128]
static __device__ u64t   g_dup[NDUP];
static __device__ double g_cov[75];
static __device__ double g_sum2[16], g_sq2[16];
static __device__ double g_vsum[NB*16], g_vsq[NB*16];
static __device__ double g_usum[24], g_usq[24];
static __device__ float  g_a1[16], g_b1[16], g_a2[16], g_b2[16];
static __device__ float  g_au[24], g_bu[24];
static __device__ int    g_idx[NB*3];

__device__ __forceinline__ float sigm(float x){
  return __fdividef(1.0f, 1.0f + __expf(-x));
}

// ---------------- Kdup: duplicate weights into packed pairs ----------------
__global__ void k_dup(const float* __restrict__ w1,  const float* __restrict__ b1,
                      const float* __restrict__ w2,  const float* __restrict__ b2,
                      const float* __restrict__ wc1, const float* __restrict__ bc1,
                      const float* __restrict__ wc2, const float* __restrict__ bc2,
                      const float* __restrict__ w1k, const float* __restrict__ b1k){
  int t = blockIdx.x*blockDim.x + threadIdx.x;
  float v; int ok = 1;
  if      (t < 160)  v = w1[t];
  else if (t < 176)  v = b1[t-160];
  else if (t < 432)  v = w2[t-176];
  else if (t < 448)  v = b2[t-432];
  else if (t < 664)  v = wc1[t-448];
  else if (t < 672)  v = bc1[t-664];
  else if (t < 1824) v = wc2[t-672];
  else if (t < 1840) v = bc2[t-1824];
  else if (t < 1960) v = w1k[t-1840];
  else if (t < 1965) v = b1k[t-1960];
  else ok = 0;
  if (ok) g_dup[t] = pk2(v, v);
}

// ---------------- K0: zero accumulators ----------------
__global__ void k_zero(){
  int t = threadIdx.x;
  if (t < 16){ g_sum2[t]=0.0; g_sq2[t]=0.0; }
  if (t < 24){ g_usum[t]=0.0; g_usq[t]=0.0; }
  if (t < 75){ g_cov[t]=0.0; }
  if (t < 256){ g_vsum[t]=0.0; g_vsq[t]=0.0; }
}

// ---------------- K1: covariance stats of x ----------------
__global__ void __launch_bounds__(256,2) k_cov(const float* __restrict__ x){
  __shared__ double sred[75];
  int t = threadIdx.x;
  if (t < 75) sred[t] = 0.0;
  __syncthreads();

  float s[10], pp[55];
#pragma unroll
  for (int i=0;i<10;i++) s[i]=0.f;
#pragma unroll
  for (int k=0;k<55;k++) pp[k]=0.f;

  const float2* X = (const float2*)x;
  int stride = gridDim.x * blockDim.x;
  for (int p = blockIdx.x*blockDim.x + t; p < NHW2; p += stride){
    int n = p >> 17, pix = p & (HW2-1);
    const float2* xp = X + (size_t)n*10*HW2 + pix;
    float2 in[10];
#pragma unroll
    for (int i=0;i<10;i++) in[i] = xp[(size_t)i*HW2];
    int k = 0;
#pragma unroll
    for (int i=0;i<10;i++){
      s[i] += in[i].x + in[i].y;
#pragma unroll
      for (int j=i;j<10;j++){
        pp[k] = fmaf(in[i].x, in[j].x, fmaf(in[i].y, in[j].y, pp[k]));
        k++;
      }
    }
  }
#pragma unroll
  for (int i=0;i<10;i++){
    float a = s[i];
#pragma unroll
    for (int o=16;o>0;o>>=1) a += __shfl_down_sync(0xffffffffu,a,o);
    if ((t&31)==0) atomicAdd(&sred[i], (double)a);
  }
#pragma unroll
  for (int k=0;k<55;k++){
    float a = pp[k];
#pragma unroll
    for (int o=16;o>0;o>>=1) a += __shfl_down_sync(0xffffffffu,a,o);
    if ((t&31)==0) atomicAdd(&sred[10+k], (double)a);
  }
  __syncthreads();
  if (t < 75) atomicAdd(&g_cov[t], sred[t]);
}

// ---------------- K2: BN1 coefficients from covariance ----------------
__global__ void k_fin1cov(const float* __restrict__ gamma, const float* __restrict__ beta){
  int c = threadIdx.x; if (c >= 16) return;
  double m[10];
  for (int i=0;i<10;i++) m[i] = g_cov[i] / (double)NHWp;
  double mean = (double)c_b1[c];
  for (int i=0;i<10;i++) mean += (double)c_w1[c*10+i] * m[i];
  double var = 0.0;
  int k = 10;
  for (int i=0;i<10;i++){
    for (int j=i;j<10;j++){
      double cov = g_cov[k] / (double)NHWp - m[i]*m[j];
      double wp  = (double)c_w1[c*10+i] * (double)c_w1[c*10+j];
      var += (i==j ? 1.0 : 2.0) * wp * cov;
      k++;
    }
  }
  double a = (double)gamma[c] / sqrt(var + 1e-5);
  g_a1[c] = (float)a;
  g_b1[c] = (float)((double)beta[c] - a*mean);
}

// ---------------- K3: fused conv1+BN1+sigm+conv2 -> z2, BN2 stats (FFMA2) ----------------
__global__ void __launch_bounds__(256,2) k_fused(const float* __restrict__ x){
  __shared__ float sa[16], sb[16];
  __shared__ double ssum[16], ssq[16];
  int t = threadIdx.x;
  if (t < 16){ sa[t]=g_a1[t]; sb[t]=g_b1[t]; ssum[t]=0.0; ssq[t]=0.0; }
  __syncthreads();

  float s[16], q[16];
#pragma unroll
  for (int c=0;c<16;c++){ s[c]=0.f; q[c]=0.f; }

  const u64t* X = (const u64t*)x;
  u64t* T = (u64t*)g_t;
  int stride = gridDim.x * blockDim.x;
  for (int p = blockIdx.x*blockDim.x + t; p < NHW2; p += stride){
    int n = p >> 17, pix = p & (HW2-1);
    const u64t* xp = X + (size_t)n*10*HW2 + pix;
    u64t in[10];
#pragma unroll
    for (int i=0;i<10;i++) in[i] = xp[(size_t)i*HW2];

    u64t acc[16];
#pragma unroll
    for (int o=0;o<16;o++) acc[o] = DB2(o);

#pragma unroll
    for (int c=0;c<16;c++){
      u64t z = DB1(c);
#pragma unroll
      for (int i=0;i<10;i++) z = fma2(DW1(c*10+i), in[i], z);
      float zx, zy; upk2(z, zx, zy);
      float ac = sa[c], bc = sb[c];
      float yx = sigm(fmaf(ac, zx, bc));
      float yy = sigm(fmaf(ac, zy, bc));
      u64t y = pk2(yx, yy);
#pragma unroll
      for (int o=0;o<16;o++) acc[o] = fma2(DW2(o*16+c), y, acc[o]);
    }
    u64t* op = T + (size_t)n*16*HW2 + pix;
#pragma unroll
    for (int o=0;o<16;o++){
      op[(size_t)o*HW2] = acc[o];
      float ax, ay; upk2(acc[o], ax, ay);
      s[o] += ax + ay;
      q[o] = fmaf(ax, ax, fmaf(ay, ay, q[o]));
    }
  }
#pragma unroll
  for (int c=0;c<16;c++){
    float a=s[c], b=q[c];
#pragma unroll
    for (int o=16;o>0;o>>=1){ a += __shfl_down_sync(0xffffffffu,a,o); b += __shfl_down_sync(0xffffffffu,b,o); }
    if ((t&31)==0){ atomicAdd(&ssum[c],(double)a); atomicAdd(&ssq[c],(double)b); }
  }
  __syncthreads();
  if (t<16){ atomicAdd(&g_sum2[t], ssum[t]); atomicAdd(&g_sq2[t], ssq[t]); }
}

// ---------------- K4: finalize BN2 ----------------
__global__ void k_fin2(const float* __restrict__ gamma, const float* __restrict__ beta){
  int c = threadIdx.x; if (c >= 16) return;
  double m = g_sum2[c] / (double)NHWp;
  double v = g_sq2[c]  / (double)NHWp - m*m;
  double a = (double)gamma[c] / sqrt(v + 1e-5);
  g_a2[c] = (float)a;
  g_b2[c] = (float)((double)beta[c] - a*m);
}

// ---------------- K5: per-(n,c) variance stats of h2 ----------------
__global__ void __launch_bounds__(256,3) k_varstats(){
  const int BPS = 64;
  int n   = blockIdx.x / BPS;
  int blk = blockIdx.x % BPS;
  __shared__ float sa[16], sb[16];
  __shared__ double ssum[16], ssq[16];
  int t = threadIdx.x;
  if (t < 16){ sa[t]=g_a2[t]; sb[t]=g_b2[t]; ssum[t]=0.0; ssq[t]=0.0; }
  __syncthreads();

  float s[16], q[16];
#pragma unroll
  for (int c=0;c<16;c++){ s[c]=0.f; q[c]=0.f; }

  const int per = HW2 / BPS;
  const float2* base = (const float2*)g_t + (size_t)n*16*HW2;
  for (int pix = blk*per + t; pix < (blk+1)*per; pix += 256){
#pragma unroll
    for (int c=0;c<16;c++){
      float2 v = base[(size_t)c*HW2 + pix];
      float hx = sigm(fmaf(sa[c], v.x, sb[c]));
      float hy = sigm(fmaf(sa[c], v.y, sb[c]));
      s[c] += hx + hy;
      q[c] = fmaf(hx,hx, fmaf(hy,hy,q[c]));
    }
  }
#pragma unroll
  for (int c=0;c<16;c++){
    float a=s[c], b=q[c];
#pragma unroll
    for (int o=16;o>0;o>>=1){ a += __shfl_down_sync(0xffffffffu,a,o); b += __shfl_down_sync(0xffffffffu,b,o); }
    if ((t&31)==0){ atomicAdd(&ssum[c],(double)a); atomicAdd(&ssq[c],(double)b); }
  }
  __syncthreads();
  if (t<16){ atomicAdd(&g_vsum[n*16+t], ssum[t]); atomicAdd(&g_vsq[n*16+t], ssq[t]); }
}

// ---------------- K6: top-3 variance channels ----------------
__global__ void k_topk(){
  int n = threadIdx.x; if (n >= NB) return;
  double var[16];
  for (int c=0;c<16;c++){
    double s = g_vsum[n*16+c], qq = g_vsq[n*16+c];
    double m = s / (double)HWp;
    var[c] = (qq - s*m) / (double)(HWp - 1);
  }
  int mask = 0;
  for (int k=0;k<3;k++){
    int best = 0; double bv = -1e300;
    for (int c=0;c<16;c++)
      if (!((mask>>c)&1) && var[c] > bv){ bv = var[c]; best = c; }
    mask |= 1<<best;
    g_idx[n*3+k] = best;
  }
}

// ---------------- K7: conv3x3 (3 sel -> 8) + sigm + maxpool2 (FFMA2) ----------------
__global__ void __launch_bounds__(256,2) k_conv3a(){
  __shared__ float sp[3][34][36];
  __shared__ float sa[3], sbb[3];
  __shared__ int   sch[3];
  int n = blockIdx.z;
  int t = threadIdx.x;
  if (t < 3){ int ch = g_idx[n*3+t]; sch[t]=ch; sa[t]=g_a2[ch]; sbb[t]=g_b2[ch]; }
  __syncthreads();

  int gy0 = blockIdx.y*32 - 1, gx0 = blockIdx.x*32 - 1;
  for (int i=t; i < 3*34*34; i += 256){
    int c = i / 1156, rem = i % 1156;
    int r = rem / 34, col = rem % 34;
    int gy = gy0 + r, gx = gx0 + col;
    float v = 0.f;
    if (gy >= 0 && gy < HH && gx >= 0 && gx < WW)
      v = sigm(fmaf(sa[c], g_t[(size_t)(n*16+sch[c])*HWp + gy*WW + gx], sbb[c]));
    sp[c][r][col] = v;
  }
  __syncthreads();

  int tx = t & 15, ty = t >> 4;
  int by = 2*ty, bx = 2*tx;
  u64t aA[8], aB[8];        // aA = {out(row0,col0), out(row0,col1)}, aB = row1
#pragma unroll
  for (int oc=0;oc<8;oc++){ aA[oc]=DBC1(oc); aB[oc]=DBC1(oc); }
#pragma unroll
  for (int c=0;c<3;c++)
#pragma unroll
    for (int ky=0;ky<3;ky++)
#pragma unroll
      for (int kx=0;kx<3;kx++){
        u64t vA = pk2(sp[c][by+ky  ][bx+kx], sp[c][by+ky  ][bx+kx+1]);
        u64t vB = pk2(sp[c][by+ky+1][bx+kx], sp[c][by+ky+1][bx+kx+1]);
#pragma unroll
        for (int oc=0;oc<8;oc++){
          u64t wv = DWC1(oc*27 + c*9 + ky*3 + kx);
          aA[oc] = fma2(wv, vA, aA[oc]);
          aB[oc] = fma2(wv, vB, aB[oc]);
        }
      }
  int py = blockIdx.y*16 + ty, px = blockIdx.x*16 + tx;
#pragma unroll
  for (int oc=0;oc<8;oc++){
    float a00,a01,a10,a11;
    upk2(aA[oc],a00,a01); upk2(aB[oc],a10,a11);
    float mx = fmaxf(fmaxf(a00,a01), fmaxf(a10,a11));
    g_x1[(size_t)(n*8+oc)*65536 + py*256 + px] = sigm(mx);
  }
}

// ---------------- K8: conv3x3 (8 -> 16) + sigm + maxpool2 (FFMA2) ----------------
__global__ void __launch_bounds__(256,2) k_conv3b(){
  __shared__ float sp[8][34][36];
  int n = blockIdx.z;
  int t = threadIdx.x;

  int gy0 = blockIdx.y*32 - 1, gx0 = blockIdx.x*32 - 1;
  for (int i=t; i < 8*34*34; i += 256){
    int c = i / 1156, rem = i % 1156;
    int r = rem / 34, col = rem % 34;
    int gy = gy0 + r, gx = gx0 + col;
    float v = 0.f;
    if (gy >= 0 && gy < 256 && gx >= 0 && gx < 256)
      v = g_x1[(size_t)(n*8+c)*65536 + gy*256 + gx];
    sp[c][r][col] = v;
  }
  __syncthreads();

  int tx = t & 15, ty = t >> 4;
  int by = 2*ty, bx = 2*tx;
  u64t aA[16], aB[16];
#pragma unroll
  for (int oc=0;oc<16;oc++){ aA[oc]=DBC2(oc); aB[oc]=DBC2(oc); }
#pragma unroll
  for (int c=0;c<8;c++)
#pragma unroll
    for (int ky=0;ky<3;ky++)
#pragma unroll
      for (int kx=0;kx<3;kx++){
        u64t vA = pk2(sp[c][by+ky  ][bx+kx], sp[c][by+ky  ][bx+kx+1]);
        u64t vB = pk2(sp[c][by+ky+1][bx+kx], sp[c][by+ky+1][bx+kx+1]);
#pragma unroll
        for (int oc=0;oc<16;oc++){
          u64t wv = DWC2(oc*72 + c*9 + ky*3 + kx);
          aA[oc] = fma2(wv, vA, aA[oc]);
          aB[oc] = fma2(wv, vB, aB[oc]);
        }
      }
  int py = blockIdx.y*16 + ty, px = blockIdx.x*16 + tx;
#pragma unroll
  for (int oc=0;oc<16;oc++){
    float a00,a01,a10,a11;
    upk2(aA[oc],a00,a01); upk2(aB[oc],a10,a11);
    float mx = fmaxf(fmaxf(a00,a01), fmaxf(a10,a11));
    g_x2[(size_t)(n*16+oc)*16384 + py*128 + px] = sigm(mx);
  }
}

// ---- vertical index helpers (jax half-pixel bilinear, clamped) ----
__device__ __forceinline__ void idx_up2(int h, int Hin, int& y0, int& y1, float& f){
  y0 = (h >> 1) - ((h & 1) ^ 1);
  f  = (h & 1) ? 0.25f : 0.75f;
  y1 = min(y0 + 1, Hin - 1);
  y0 = max(y0, 0);
}
__device__ __forceinline__ void idx_up4(int h, int Hin, int& y0, int& y1, float& f){
  int m = h & 3;
  y0 = (h >> 2) - (m < 2 ? 1 : 0);
  f  = (m==0) ? 0.625f : (m==1) ? 0.875f : (m==2) ? 0.125f : 0.375f;
  y1 = min(y0 + 1, Hin - 1);
  y0 = max(y0, 0);
}
#define LERP(a,b,f) ((a) + (f)*((b)-(a)))

// sigmoid outputs > 0 and bilinear weights nonneg => relu identity on up paths.

// ---------------- K9a: stats of up2(x1) -> g_usum[0..7] ----------------
__global__ void __launch_bounds__(256,3) k_up2stats(){
  __shared__ double ssum[8], ssq[8];
  int t = threadIdx.x;
  if (t < 8){ ssum[t]=0.0; ssq[t]=0.0; }
  __syncthreads();

  float s[8], q[8];
#pragma unroll
  for (int c=0;c<8;c++){ s[c]=0.f; q[c]=0.f; }

  const int NQ = NHWp/4;
  int stride = gridDim.x * blockDim.x;
  for (int p = blockIdx.x*blockDim.x + t; p < NQ; p += stride){
    int n = p >> 16, r = p & 65535;
    int h = r >> 7, w = r & 127;
    int y0,y1; float fy; idx_up2(h,256,y0,y1,fy);
    int c0 = max(2*w-1,0), c1 = 2*w, c2 = 2*w+1, c3 = min(2*w+2,255);
    const float* bp = g_x1 + (size_t)n*8*65536;
#pragma unroll
    for (int c=0;c<8;c++){
      const float* p0 = bp + (size_t)c*65536 + y0*256;
      const float* p1 = bp + (size_t)c*65536 + y1*256;
      float vv0 = LERP(p0[c0], p1[c0], fy);
      float vv1 = LERP(p0[c1], p1[c1], fy);
      float vv2 = LERP(p0[c2], p1[c2], fy);
      float vv3 = LERP(p0[c3], p1[c3], fy);
      float o0 = LERP(vv0, vv1, 0.75f);
      float o1 = LERP(vv1, vv2, 0.25f);
      float o2 = LERP(vv1, vv2, 0.75f);
      float o3 = LERP(vv2, vv3, 0.25f);
      s[c] += (o0+o1) + (o2+o3);
      q[c] = fmaf(o0,o0, fmaf(o1,o1, fmaf(o2,o2, fmaf(o3,o3, q[c]))));
    }
  }
#pragma unroll
  for (int c=0;c<8;c++){
    float a=s[c], b=q[c];
#pragma unroll
    for (int o=16;o>0;o>>=1){ a += __shfl_down_sync(0xffffffffu,a,o); b += __shfl_down_sync(0xffffffffu,b,o); }
    if ((t&31)==0){ atomicAdd(&ssum[c],(double)a); atomicAdd(&ssq[c],(double)b); }
  }
  __syncthreads();
  if (t<8){ atomicAdd(&g_usum[t], ssum[t]); atomicAdd(&g_usq[t], ssq[t]); }
}

// ---------------- K9b: stats of up4(x2) -> g_usum[8..23] ----------------
__global__ void __launch_bounds__(256,3) k_up4stats(){
  __shared__ double ssum[16], ssq[16];
  int t = threadIdx.x;
  if (t < 16){ ssum[t]=0.0; ssq[t]=0.0; }
  __syncthreads();

  float s[16], q[16];
#pragma unroll
  for (int c=0;c<16;c++){ s[c]=0.f; q[c]=0.f; }

  const int NQ = NHWp/4;
  int stride = gridDim.x * blockDim.x;
  for (int p = blockIdx.x*blockDim.x + t; p < NQ; p += stride){
    int n = p >> 16, r = p & 65535;
    int h = r >> 7, w = r & 127;
    int y0,y1; float fy; idx_up4(h,128,y0,y1,fy);
    int cm = max(w-1,0), cc = w, cp = min(w+1,127);
    const float* bp = g_x2 + (size_t)n*16*16384;
#pragma unroll
    for (int c=0;c<16;c++){
      const float* p0 = bp + (size_t)c*16384 + y0*128;
      const float* p1 = bp + (size_t)c*16384 + y1*128;
      float vv0 = LERP(p0[cm], p1[cm], fy);
      float vv1 = LERP(p0[cc], p1[cc], fy);
      float vv2 = LERP(p0[cp], p1[cp], fy);
      float o0 = LERP(vv0, vv1, 0.625f);
      float o1 = LERP(vv0, vv1, 0.875f);
      float o2 = LERP(vv1, vv2, 0.125f);
      float o3 = LERP(vv1, vv2, 0.375f);
      s[c] += (o0+o1) + (o2+o3);
      q[c] = fmaf(o0,o0, fmaf(o1,o1, fmaf(o2,o2, fmaf(o3,o3, q[c]))));
    }
  }
#pragma unroll
  for (int c=0;c<16;c++){
    float a=s[c], b=q[c];
#pragma unroll
    for (int o=16;o>0;o>>=1){ a += __shfl_down_sync(0xffffffffu,a,o); b += __shfl_down_sync(0xffffffffu,b,o); }
    if ((t&31)==0){ atomicAdd(&ssum[c],(double)a); atomicAdd(&ssq[c],(double)b); }
  }
  __syncthreads();
  if (t<16){ atomicAdd(&g_usum[8+t], ssum[t]); atomicAdd(&g_usq[8+t], ssq[t]); }
}

// ---------------- K10: finalize upsample BNs ----------------
__global__ void k_finup(const float* __restrict__ gbn1, const float* __restrict__ bbn1,
                        const float* __restrict__ gbn2, const float* __restrict__ bbn2){
  int c = threadIdx.x; if (c >= 24) return;
  double m = g_usum[c] / (double)NHWp;
  double v = g_usq[c]  / (double)NHWp - m*m;
  double gamma = (c < 8) ? (double)gbn2[c] : (double)gbn1[c-8];
  double beta  = (c < 8) ? (double)bbn2[c] : (double)bbn1[c-8];
  double a = gamma / sqrt(v + 1e-5);
  g_au[c] = (float)a;
  g_bu[c] = (float)(beta - a*m);
}

// ---------------- K11: up2/up4 + BN + concat + 1x1 conv (24->5) (FFMA2) ----------------
__global__ void __launch_bounds__(256,3) k_final(float* __restrict__ out){
  __shared__ float sa[24], sbb[24];
  int t = threadIdx.x;
  if (t < 24){ sa[t] = g_au[t]; sbb[t] = g_bu[t]; }
  __syncthreads();

  const int NQ = NHWp/4;
  int stride = gridDim.x * blockDim.x;
  for (int p = blockIdx.x*blockDim.x + t; p < NQ; p += stride){
    int n = p >> 16, r = p & 65535;
    int h = r >> 7, w = r & 127;

    u64t a01[5], a23[5];
#pragma unroll
    for (int k=0;k<5;k++){ a01[k]=DB1K(k); a23[k]=DB1K(k); }

    {   // up2 path: channels 0..7
      int y0,y1; float fy; idx_up2(h,256,y0,y1,fy);
      int c0 = max(2*w-1,0), c1 = 2*w, c2 = 2*w+1, c3 = min(2*w+2,255);
      const float* bp = g_x1 + (size_t)n*8*65536;
#pragma unroll
      for (int c=0;c<8;c++){
        const float* p0 = bp + (size_t)c*65536 + y0*256;
        const float* p1 = bp + (size_t)c*65536 + y1*256;
        float vv0 = LERP(p0[c0], p1[c0], fy);
        float vv1 = LERP(p0[c1], p1[c1], fy);
        float vv2 = LERP(p0[c2], p1[c2], fy);
        float vv3 = LERP(p0[c3], p1[c3], fy);
        float sc = sa[c], sh = sbb[c];
        float r0 = fmaf(sc, LERP(vv0, vv1, 0.75f), sh);
        float r1 = fmaf(sc, LERP(vv1, vv2, 0.25f), sh);
        float r2 = fmaf(sc, LERP(vv1, vv2, 0.75f), sh);
        float r3 = fmaf(sc, LERP(vv2, vv3, 0.25f), sh);
        u64t r01 = pk2(r0,r1), r23 = pk2(r2,r3);
#pragma unroll
        for (int k=0;k<5;k++){
          u64t wv = DW1K(k*24+c);
          a01[k] = fma2(wv, r01, a01[k]);
          a23[k] = fma2(wv, r23, a23[k]);
        }
      }
    }
    {   // up4 path: channels 8..23
      int y0,y1; float fy; idx_up4(h,128,y0,y1,fy);
      int cm = max(w-1,0), cc = w, cp = min(w+1,127);
      const float* bp = g_x2 + (size_t)n*16*16384;
#pragma unroll
      for (int c=0;c<16;c++){
        const float* p0 = bp + (size_t)c*16384 + y0*128;
        const float* p1 = bp + (size_t)c*16384 + y1*128;
        float vv0 = LERP(p0[cm], p1[cm], fy);
        float vv1 = LERP(p0[cc], p1[cc], fy);
        float vv2 = LERP(p0[cp], p1[cp], fy);
        float sc = sa[8+c], sh = sbb[8+c];
        float r0 = fmaf(sc, LERP(vv0, vv1, 0.625f), sh);
        float r1 = fmaf(sc, LERP(vv0, vv1, 0.875f), sh);
        float r2 = fmaf(sc, LERP(vv1, vv2, 0.125f), sh);
        float r3 = fmaf(sc, LERP(vv1, vv2, 0.375f), sh);
        u64t r01 = pk2(r0,r1), r23 = pk2(r2,r3);
#pragma unroll
        for (int k=0;k<5;k++){
          u64t wv = DW1K(k*24+8+c);
          a01[k] = fma2(wv, r01, a01[k]);
          a23[k] = fma2(wv, r23, a23[k]);
        }
      }
    }
#pragma unroll
    for (int k=0;k<5;k++){
      float4 v;
      upk2(a01[k], v.x, v.y);
      upk2(a23[k], v.z, v.w);
      *(float4*)(out + (size_t)(n*5+k)*HWp + h*512 + 4*w) = v;
    }
  }
}

// ---------------- launch ----------------
extern "C" void kernel_launch(void* const* d_in, const int* in_sizes, int n_in,
                              void* d_out, int out_size){
  (void)in_sizes; (void)n_in; (void)out_size;
  const float* x       = (const float*)d_in[0];
  const float* g_ebn1  = (const float*)d_in[3];
  const float* be_ebn1 = (const float*)d_in[4];
  const float* g_ebn2  = (const float*)d_in[7];
  const float* be_ebn2 = (const float*)d_in[8];
  const float* g_bn1   = (const float*)d_in[13];
  const float* be_bn1  = (const float*)d_in[14];
  const float* g_bn2   = (const float*)d_in[15];
  const float* be_bn2  = (const float*)d_in[16];
  float* out = (float*)d_out;

  // scalar weights for fin1cov
  cudaMemcpyToSymbolAsync(c_w1, d_in[1], 160*sizeof(float), 0, cudaMemcpyDeviceToDevice, 0);
  cudaMemcpyToSymbolAsync(c_b1, d_in[2],  16*sizeof(float), 0, cudaMemcpyDeviceToDevice, 0);

  // duplicated packed weights: device kernel writes pairs, then D2D copy to constant
  void* pdup = nullptr;
  cudaGetSymbolAddress(&pdup, g_dup);
  k_dup<<<8,256>>>((const float*)d_in[1],  (const float*)d_in[2],
                   (const float*)d_in[5],  (const float*)d_in[6],
                   (const float*)d_in[9],  (const float*)d_in[10],
                   (const float*)d_in[11], (const float*)d_in[12],
                   (const float*)d_in[17], (const float*)d_in[18]);
  cudaMemcpyToSymbolAsync(c_dup, pdup, NDUP*sizeof(u64t), 0, cudaMemcpyDeviceToDevice, 0);

  const int GS = 1184;

  k_zero<<<1,256>>>();
  k_cov<<<GS,256>>>(x);
  k_fin1cov<<<1,16>>>(g_ebn1, be_ebn1);
  k_fused<<<GS,256>>>(x);
  k_fin2<<<1,16>>>(g_ebn2, be_ebn2);
  k_varstats<<<16*64,256>>>();
  k_topk<<<1,16>>>();
  k_conv3a<<<dim3(16,16,16),256>>>();
  k_conv3b<<<dim3(8,8,16),256>>>();
  k_up2stats<<<GS,256>>>();
  k_up4stats<<<GS,256>>>();
  k_finup<<<1,24>>>(g_bn1, be_bn1, g_bn2, be_bn2);
  k_final<<<GS,256>>>(out);
}

// round 13
// speedup vs baseline: 3.0439x; 1.0009x over previous
#include <cuda_runtime.h>
#include <cuda_fp16.h>
#include <math.h>

// Problem constants
#define NB   16
#define HH   512
#define WW   512
#define HWp  (HH*WW)     // 262144
#define HW2  (HWp/2)     // 131072
#define NHWp (NB*HWp)    // 4194304
#define NHW2 (NB*HW2)    // 2097152

typedef unsigned long long u64t;

// ---------------- packed f32x2 helpers ----------------
__device__ __forceinline__ u64t pk2(float lo, float hi){
  u64t r; asm("mov.b64 %0,{%1,%2};" : "=l"(r) : "f"(lo), "f"(hi)); return r;
}
__device__ __forceinline__ void upk2(u64t v, float& lo, float& hi){
  asm("mov.b64 {%0,%1},%2;" : "=f"(lo), "=f"(hi) : "l"(v));
}
__device__ __forceinline__ u64t fma2(u64t a, u64t b, u64t c){
  u64t d; asm("fma.rn.f32x2 %0,%1,%2,%3;" : "=l"(d) : "l"(a), "l"(b), "l"(c)); return d;
}

// ---------------- constant weights ----------------
__constant__ float c_w1[160];
__constant__ float c_b1[16];
#define NDUP 1965
__constant__ u64t c_dup[NDUP];
#define DW1(i)  c_dup[(i)]
#define DB1(i)  c_dup[160+(i)]
#define DW2(i)  c_dup[176+(i)]
#define DB2(i)  c_dup[432+(i)]
#define DWC1(i) c_dup[448+(i)]
#define DBC1(i) c_dup[664+(i)]
#define DWC2(i) c_dup[672+(i)]
#define DBC2(i) c_dup[1824+(i)]
#define DW1K(i) c_dup[1840+(i)]
#define DB1K(i) c_dup[1960+(i)]

// ---------------- device scratch ----------------
static __device__ __half2 g_th[33554432];  // z2 fp16: [16,16,512,512] as half2 (134 MB)
static __device__ float   g_x1[ 8388608];  // [16, 8,256,256]
static __device__ float   g_x2[ 4194304];  // [16,16,128,128]
static __device__ u64t    g_dup[NDUP];
static __device__ double  g_cov[75];
static __device__ double  g_sum2[16], g_sq2[16];
static __device__ double  g_vsum[NB*16], g_vsq[NB*16];
static __device__ double  g_usum[24], g_usq[24];

__device__ __forceinline__ float sigm(float x){
  return __fdividef(1.0f, 1.0f + __expf(-x));
}

// ---------------- K_init: dup weights + zero accumulators ----------------
__global__ void k_init(const float* __restrict__ w1,  const float* __restrict__ b1,
                       const float* __restrict__ w2,  const float* __restrict__ b2,
                       const float* __restrict__ wc1, const float* __restrict__ bc1,
                       const float* __restrict__ wc2, const float* __restrict__ bc2,
                       const float* __restrict__ w1k, const float* __restrict__ b1k){
  int t = blockIdx.x*blockDim.x + threadIdx.x;
  // zero stats
  if (t < 16){ g_sum2[t]=0.0; g_sq2[t]=0.0; }
  if (t < 24){ g_usum[t]=0.0; g_usq[t]=0.0; }
  if (t < 75){ g_cov[t]=0.0; }
  if (t < 256){ g_vsum[t]=0.0; g_vsq[t]=0.0; }
  // dup weights
  float v; int ok = 1;
  if      (t < 160)  v = w1[t];
  else if (t < 176)  v = b1[t-160];
  else if (t < 432)  v = w2[t-176];
  else if (t < 448)  v = b2[t-432];
  else if (t < 664)  v = wc1[t-448];
  else if (t < 672)  v = bc1[t-664];
  else if (t < 1824) v = wc2[t-672];
  else if (t < 1840) v = bc2[t-1824];
  else if (t < 1960) v = w1k[t-1840];
  else if (t < 1965) v = b1k[t-1960];
  else ok = 0;
  if (ok) g_dup[t] = pk2(v, v);
}

// ---------------- K_cov: covariance stats of x ----------------
__global__ void __launch_bounds__(256,2) k_cov(const float* __restrict__ x){
  __shared__ double sred[75];
  int t = threadIdx.x;
  if (t < 75) sred[t] = 0.0;
  __syncthreads();

  float s[10], pp[55];
#pragma unroll
  for (int i=0;i<10;i++) s[i]=0.f;
#pragma unroll
  for (int k=0;k<55;k++) pp[k]=0.f;

  const float2* X = (const float2*)x;
  int stride = gridDim.x * blockDim.x;
  for (int p = blockIdx.x*blockDim.x + t; p < NHW2; p += stride){
    int n = p >> 17, pix = p & (HW2-1);
    const float2* xp = X + (size_t)n*10*HW2 + pix;
    float2 in[10];
#pragma unroll
    for (int i=0;i<10;i++) in[i] = xp[(size_t)i*HW2];
    int k = 0;
#pragma unroll
    for (int i=0;i<10;i++){
      s[i] += in[i].x + in[i].y;
#pragma unroll
      for (int j=i;j<10;j++){
        pp[k] = fmaf(in[i].x, in[j].x, fmaf(in[i].y, in[j].y, pp[k]));
        k++;
      }
    }
  }
#pragma unroll
  for (int i=0;i<10;i++){
    float a = s[i];
#pragma unroll
    for (int o=16;o>0;o>>=1) a += __shfl_down_sync(0xffffffffu,a,o);
    if ((t&31)==0) atomicAdd(&sred[i], (double)a);
  }
#pragma unroll
  for (int k=0;k<55;k++){
    float a = pp[k];
#pragma unroll
    for (int o=16;o>0;o>>=1) a += __shfl_down_sync(0xffffffffu,a,o);
    if ((t&31)==0) atomicAdd(&sred[10+k], (double)a);
  }
  __syncthreads();
  if (t < 75) atomicAdd(&g_cov[t], sred[t]);
}

// ---------------- K_fused: (BN1 coeffs) + conv1+BN1+sigm+conv2 -> z2(fp16), BN2 stats ----------------
__global__ void __launch_bounds__(256,2) k_fused(const float* __restrict__ x,
                                                 const float* __restrict__ gamma1,
                                                 const float* __restrict__ beta1){
  __shared__ float sa[16], sb[16];
  __shared__ double ssum[16], ssq[16];
  int t = threadIdx.x;
  if (t < 16){
    // fin1cov fold: BN1 coeffs from covariance (identical across blocks)
    double m[10];
#pragma unroll
    for (int i=0;i<10;i++) m[i] = g_cov[i] / (double)NHWp;
    double mean = (double)c_b1[t];
#pragma unroll
    for (int i=0;i<10;i++) mean += (double)c_w1[t*10+i] * m[i];
    double var = 0.0;
    int k = 10;
#pragma unroll
    for (int i=0;i<10;i++){
#pragma unroll
      for (int j=i;j<10;j++){
        double cov = g_cov[k] / (double)NHWp - m[i]*m[j];
        double wp  = (double)c_w1[t*10+i] * (double)c_w1[t*10+j];
        var += (i==j ? 1.0 : 2.0) * wp * cov;
        k++;
      }
    }
    double a = (double)gamma1[t] / sqrt(var + 1e-5);
    sa[t] = (float)a;
    sb[t] = (float)((double)beta1[t] - a*mean);
    ssum[t]=0.0; ssq[t]=0.0;
  }
  __syncthreads();

  float s[16], q[16];
#pragma unroll
  for (int c=0;c<16;c++){ s[c]=0.f; q[c]=0.f; }

  const u64t* X = (const u64t*)x;
  int stride = gridDim.x * blockDim.x;
  for (int p = blockIdx.x*blockDim.x + t; p < NHW2; p += stride){
    int n = p >> 17, pix = p & (HW2-1);
    const u64t* xp = X + (size_t)n*10*HW2 + pix;
    u64t in[10];
#pragma unroll
    for (int i=0;i<10;i++) in[i] = xp[(size_t)i*HW2];

    u64t acc[16];
#pragma unroll
    for (int o=0;o<16;o++) acc[o] = DB2(o);

#pragma unroll
    for (int c=0;c<16;c++){
      u64t z = DB1(c);
#pragma unroll
      for (int i=0;i<10;i++) z = fma2(DW1(c*10+i), in[i], z);
      float zx, zy; upk2(z, zx, zy);
      float ac = sa[c], bc = sb[c];
      float yx = sigm(fmaf(ac, zx, bc));
      float yy = sigm(fmaf(ac, zy, bc));
      u64t y = pk2(yx, yy);
#pragma unroll
      for (int o=0;o<16;o++) acc[o] = fma2(DW2(o*16+c), y, acc[o]);
    }
    __half2* op = g_th + (size_t)n*16*HW2 + pix;
#pragma unroll
    for (int o=0;o<16;o++){
      float ax, ay; upk2(acc[o], ax, ay);
      op[(size_t)o*HW2] = __float22half2_rn(make_float2(ax, ay));
      s[o] += ax + ay;
      q[o] = fmaf(ax, ax, fmaf(ay, ay, q[o]));
    }
  }
#pragma unroll
  for (int c=0;c<16;c++){
    float a=s[c], b=q[c];
#pragma unroll
    for (int o=16;o>0;o>>=1){ a += __shfl_down_sync(0xffffffffu,a,o); b += __shfl_down_sync(0xffffffffu,b,o); }
    if ((t&31)==0){ atomicAdd(&ssum[c],(double)a); atomicAdd(&ssq[c],(double)b); }
  }
  __syncthreads();
  if (t<16){ atomicAdd(&g_sum2[t], ssum[t]); atomicAdd(&g_sq2[t], ssq[t]); }
}

// ---------------- K_varstats: (BN2 coeffs) + per-(n,c) variance of h2 ----------------
__global__ void __launch_bounds__(256,3) k_varstats(const float* __restrict__ gamma2,
                                                    const float* __restrict__ beta2){
  const int BPS = 64;
  int n   = blockIdx.x / BPS;
  int blk = blockIdx.x % BPS;
  __shared__ float sa[16], sb[16];
  __shared__ double ssum[16], ssq[16];
  int t = threadIdx.x;
  if (t < 16){
    double m = g_sum2[t] / (double)NHWp;
    double v = g_sq2[t]  / (double)NHWp - m*m;
    double a = (double)gamma2[t] / sqrt(v + 1e-5);
    sa[t] = (float)a;
    sb[t] = (float)((double)beta2[t] - a*m);
    ssum[t]=0.0; ssq[t]=0.0;
  }
  __syncthreads();

  float s[16], q[16];
#pragma unroll
  for (int c=0;c<16;c++){ s[c]=0.f; q[c]=0.f; }

  const int per = HW2 / BPS;
  const __half2* base = g_th + (size_t)n*16*HW2;
  for (int pix = blk*per + t; pix < (blk+1)*per; pix += 256){
#pragma unroll
    for (int c=0;c<16;c++){
      float2 v = __half22float2(base[(size_t)c*HW2 + pix]);
      float hx = sigm(fmaf(sa[c], v.x, sb[c]));
      float hy = sigm(fmaf(sa[c], v.y, sb[c]));
      s[c] += hx + hy;
      q[c] = fmaf(hx,hx, fmaf(hy,hy,q[c]));
    }
  }
#pragma unroll
  for (int c=0;c<16;c++){
    float a=s[c], b=q[c];
#pragma unroll
    for (int o=16;o>0;o>>=1){ a += __shfl_down_sync(0xffffffffu,a,o); b += __shfl_down_sync(0xffffffffu,b,o); }
    if ((t&31)==0){ atomicAdd(&ssum[c],(double)a); atomicAdd(&ssq[c],(double)b); }
  }
  __syncthreads();
  if (t<16){ atomicAdd(&g_vsum[n*16+t], ssum[t]); atomicAdd(&g_vsq[n*16+t], ssq[t]); }
}

// ---------------- K_conv3a: (BN2 coeffs + top-3) + conv3x3(3->8)+sigm+pool ----------------
__global__ void __launch_bounds__(256,2) k_conv3a(const float* __restrict__ gamma2,
                                                  const float* __restrict__ beta2){
  __shared__ float sp[3][34][36];
  __shared__ float sa16[16], sb16[16];
  __shared__ double svar[16];
  __shared__ int   sidx[3];
  __shared__ float sa[3], sbb[3];
  __shared__ int   sch[3];
  int n = blockIdx.z;
  int t = threadIdx.x;
  if (t < 16){
    double m = g_sum2[t] / (double)NHWp;
    double v = g_sq2[t]  / (double)NHWp - m*m;
    double a = (double)gamma2[t] / sqrt(v + 1e-5);
    sa16[t] = (float)a;
    sb16[t] = (float)((double)beta2[t] - a*m);
    double su = g_vsum[n*16+t], qq = g_vsq[n*16+t];
    double mm = su / (double)HWp;
    svar[t] = (qq - su*mm) / (double)(HWp - 1);
  }
  __syncthreads();
  if (t == 0){
    int mask = 0;
    for (int k=0;k<3;k++){
      int best = 0; double bv = -1e300;
      for (int c=0;c<16;c++)
        if (!((mask>>c)&1) && svar[c] > bv){ bv = svar[c]; best = c; }
      mask |= 1<<best;
      sidx[k] = best;
    }
  }
  __syncthreads();
  if (t < 3){ int ch = sidx[t]; sch[t]=ch; sa[t]=sa16[ch]; sbb[t]=sb16[ch]; }
  __syncthreads();

  const __half* H = (const __half*)g_th;
  int gy0 = blockIdx.y*32 - 1, gx0 = blockIdx.x*32 - 1;
  for (int i=t; i < 3*34*34; i += 256){
    int c = i / 1156, rem = i % 1156;
    int r = rem / 34, col = rem % 34;
    int gy = gy0 + r, gx = gx0 + col;
    float v = 0.f;
    if (gy >= 0 && gy < HH && gx >= 0 && gx < WW)
      v = sigm(fmaf(sa[c], __half2float(H[(size_t)(n*16+sch[c])*HWp + gy*WW + gx]), sbb[c]));
    sp[c][r][col] = v;
  }
  __syncthreads();

  int tx = t & 15, ty = t >> 4;
  int by = 2*ty, bx = 2*tx;
  u64t aA[8], aB[8];
#pragma unroll
  for (int oc=0;oc<8;oc++){ aA[oc]=DBC1(oc); aB[oc]=DBC1(oc); }
#pragma unroll
  for (int c=0;c<3;c++)
#pragma unroll
    for (int ky=0;ky<3;ky++)
#pragma unroll
      for (int kx=0;kx<3;kx++){
        u64t vA = pk2(sp[c][by+ky  ][bx+kx], sp[c][by+ky  ][bx+kx+1]);
        u64t vB = pk2(sp[c][by+ky+1][bx+kx], sp[c][by+ky+1][bx+kx+1]);
#pragma unroll
        for (int oc=0;oc<8;oc++){
          u64t wv = DWC1(oc*27 + c*9 + ky*3 + kx);
          aA[oc] = fma2(wv, vA, aA[oc]);
          aB[oc] = fma2(wv, vB, aB[oc]);
        }
      }
  int py = blockIdx.y*16 + ty, px = blockIdx.x*16 + tx;
#pragma unroll
  for (int oc=0;oc<8;oc++){
    float a00,a01,a10,a11;
    upk2(aA[oc],a00,a01); upk2(aB[oc],a10,a11);
    float mx = fmaxf(fmaxf(a00,a01), fmaxf(a10,a11));
    g_x1[(size_t)(n*8+oc)*65536 + py*256 + px] = sigm(mx);  // sigmoid monotone
  }
}

// ---------------- K_conv3b: conv3x3(8->16)+sigm+pool ----------------
__global__ void __launch_bounds__(256,2) k_conv3b(){
  __shared__ float sp[8][34][36];
  int n = blockIdx.z;
  int t = threadIdx.x;

  int gy0 = blockIdx.y*32 - 1, gx0 = blockIdx.x*32 - 1;
  for (int i=t; i < 8*34*34; i += 256){
    int c = i / 1156, rem = i % 1156;
    int r = rem / 34, col = rem % 34;
    int gy = gy0 + r, gx = gx0 + col;
    float v = 0.f;
    if (gy >= 0 && gy < 256 && gx >= 0 && gx < 256)
      v = g_x1[(size_t)(n*8+c)*65536 + gy*256 + gx];
    sp[c][r][col] = v;
  }
  __syncthreads();

  int tx = t & 15, ty = t >> 4;
  int by = 2*ty, bx = 2*tx;
  u64t aA[16], aB[16];
#pragma unroll
  for (int oc=0;oc<16;oc++){ aA[oc]=DBC2(oc); aB[oc]=DBC2(oc); }
#pragma unroll
  for (int c=0;c<8;c++)
#pragma unroll
    for (int ky=0;ky<3;ky++)
#pragma unroll
      for (int kx=0;kx<3;kx++){
        u64t vA = pk2(sp[c][by+ky  ][bx+kx], sp[c][by+ky  ][bx+kx+1]);
        u64t vB = pk2(sp[c][by+ky+1][bx+kx], sp[c][by+ky+1][bx+kx+1]);
#pragma unroll
        for (int oc=0;oc<16;oc++){
          u64t wv = DWC2(oc*72 + c*9 + ky*3 + kx);
          aA[oc] = fma2(wv, vA, aA[oc]);
          aB[oc] = fma2(wv, vB, aB[oc]);
        }
      }
  int py = blockIdx.y*16 + ty, px = blockIdx.x*16 + tx;
#pragma unroll
  for (int oc=0;oc<16;oc++){
    float a00,a01,a10,a11;
    upk2(aA[oc],a00,a01); upk2(aB[oc],a10,a11);
    float mx = fmaxf(fmaxf(a00,a01), fmaxf(a10,a11));
    g_x2[(size_t)(n*16+oc)*16384 + py*128 + px] = sigm(mx);
  }
}

// ---- vertical index helpers (jax half-pixel bilinear, clamped) ----
__device__ __forceinline__ void idx_up2(int h, int Hin, int& y0, int& y1, float& f){
  y0 = (h >> 1) - ((h & 1) ^ 1);
  f  = (h & 1) ? 0.25f : 0.75f;
  y1 = min(y0 + 1, Hin - 1);
  y0 = max(y0, 0);
}
__device__ __forceinline__ void idx_up4(int h, int Hin, int& y0, int& y1, float& f){
  int m = h & 3;
  y0 = (h >> 2) - (m < 2 ? 1 : 0);
  f  = (m==0) ? 0.625f : (m==1) ? 0.875f : (m==2) ? 0.125f : 0.375f;
  y1 = min(y0 + 1, Hin - 1);
  y0 = max(y0, 0);
}
#define LERP(a,b,f) ((a) + (f)*((b)-(a)))

// sigmoid outputs > 0 and bilinear weights nonneg => relu identity on up paths.

// ---------------- K_upstats: stats of up2(x1) and up4(x2), merged ----------------
__global__ void __launch_bounds__(256,2) k_upstats(){
  __shared__ double ssum[24], ssq[24];
  int t = threadIdx.x;
  if (t < 24){ ssum[t]=0.0; ssq[t]=0.0; }
  __syncthreads();

  float s[24], q[24];
#pragma unroll
  for (int c=0;c<24;c++){ s[c]=0.f; q[c]=0.f; }

  const int NQ = NHWp/4;
  int stride = gridDim.x * blockDim.x;
  for (int p = blockIdx.x*blockDim.x + t; p < NQ; p += stride){
    int n = p >> 16, r = p & 65535;
    int h = r >> 7, w = r & 127;
    {   // up2 path
      int y0,y1; float fy; idx_up2(h,256,y0,y1,fy);
      int c0 = max(2*w-1,0), c1 = 2*w, c2 = 2*w+1, c3 = min(2*w+2,255);
      const float* bp = g_x1 + (size_t)n*8*65536;
#pragma unroll
      for (int c=0;c<8;c++){
        const float* p0 = bp + (size_t)c*65536 + y0*256;
        const float* p1 = bp + (size_t)c*65536 + y1*256;
        float vv0 = LERP(p0[c0], p1[c0], fy);
        float vv1 = LERP(p0[c1], p1[c1], fy);
        float vv2 = LERP(p0[c2], p1[c2], fy);
        float vv3 = LERP(p0[c3], p1[c3], fy);
        float o0 = LERP(vv0, vv1, 0.75f);
        float o1 = LERP(vv1, vv2, 0.25f);
        float o2 = LERP(vv1, vv2, 0.75f);
        float o3 = LERP(vv2, vv3, 0.25f);
        s[c] += (o0+o1) + (o2+o3);
        q[c] = fmaf(o0,o0, fmaf(o1,o1, fmaf(o2,o2, fmaf(o3,o3, q[c]))));
      }
    }
    {   // up4 path
      int y0,y1; float fy; idx_up4(h,128,y0,y1,fy);
      int cm = max(w-1,0), cc = w, cp = min(w+1,127);
      const float* bp = g_x2 + (size_t)n*16*16384;
#pragma unroll
      for (int c=0;c<16;c++){
        const float* p0 = bp + (size_t)c*16384 + y0*128;
        const float* p1 = bp + (size_t)c*16384 + y1*128;
        float vv0 = LERP(p0[cm], p1[cm], fy);
        float vv1 = LERP(p0[cc], p1[cc], fy);
        float vv2 = LERP(p0[cp], p1[cp], fy);
        float o0 = LERP(vv0, vv1, 0.625f);
        float o1 = LERP(vv0, vv1, 0.875f);
        float o2 = LERP(vv1, vv2, 0.125f);
        float o3 = LERP(vv1, vv2, 0.375f);
        s[8+c] += (o0+o1) + (o2+o3);
        q[8+c] = fmaf(o0,o0, fmaf(o1,o1, fmaf(o2,o2, fmaf(o3,o3, q[8+c]))));
      }
    }
  }
#pragma unroll
  for (int c=0;c<24;c++){
    float a=s[c], b=q[c];
#pragma unroll
    for (int o=16;o>0;o>>=1){ a += __shfl_down_sync(0xffffffffu,a,o); b += __shfl_down_sync(0xffffffffu,b,o); }
    if ((t&31)==0){ atomicAdd(&ssum[c],(double)a); atomicAdd(&ssq[c],(double)b); }
  }
  __syncthreads();
  if (t<24){ atomicAdd(&g_usum[t], ssum[t]); atomicAdd(&g_usq[t], ssq[t]); }
}

// ---------------- K_final: (up BN coeffs) + up2/up4 + BN + concat + 1x1 conv ----------------
__global__ void __launch_bounds__(256,3) k_final(float* __restrict__ out,
                                                 const float* __restrict__ gbn1,
                                                 const float* __restrict__ bbn1,
                                                 const float* __restrict__ gbn2,
                                                 const float* __restrict__ bbn2){
  __shared__ float sa[24], sbb[24];
  int t = threadIdx.x;
  if (t < 24){
    double m = g_usum[t] / (double)NHWp;
    double v = g_usq[t]  / (double)NHWp - m*m;
    double gamma = (t < 8) ? (double)gbn2[t] : (double)gbn1[t-8];
    double beta  = (t < 8) ? (double)bbn2[t] : (double)bbn1[t-8];
    double a = gamma / sqrt(v + 1e-5);
    sa[t]  = (float)a;
    sbb[t] = (float)(beta - a*m);
  }
  __syncthreads();

  const int NQ = NHWp/4;
  int stride = gridDim.x * blockDim.x;
  for (int p = blockIdx.x*blockDim.x + t; p < NQ; p += stride){
    int n = p >> 16, r = p & 65535;
    int h = r >> 7, w = r & 127;

    u64t a01[5], a23[5];
#pragma unroll
    for (int k=0;k<5;k++){ a01[k]=DB1K(k); a23[k]=DB1K(k); }

    {   // up2 path: channels 0..7
      int y0,y1; float fy; idx_up2(h,256,y0,y1,fy);
      int c0 = max(2*w-1,0), c1 = 2*w, c2 = 2*w+1, c3 = min(2*w+2,255);
      const float* bp = g_x1 + (size_t)n*8*65536;
#pragma unroll
      for (int c=0;c<8;c++){
        const float* p0 = bp + (size_t)c*65536 + y0*256;
        const float* p1 = bp + (size_t)c*65536 + y1*256;
        float vv0 = LERP(p0[c0], p1[c0], fy);
        float vv1 = LERP(p0[c1], p1[c1], fy);
        float vv2 = LERP(p0[c2], p1[c2], fy);
        float vv3 = LERP(p0[c3], p1[c3], fy);
        float sc = sa[c], sh = sbb[c];
        float r0 = fmaf(sc, LERP(vv0, vv1, 0.75f), sh);
        float r1 = fmaf(sc, LERP(vv1, vv2, 0.25f), sh);
        float r2 = fmaf(sc, LERP(vv1, vv2, 0.75f), sh);
        float r3 = fmaf(sc, LERP(vv2, vv3, 0.25f), sh);
        u64t r01 = pk2(r0,r1), r23 = pk2(r2,r3);
#pragma unroll
        for (int k=0;k<5;k++){
          u64t wv = DW1K(k*24+c);
          a01[k] = fma2(wv, r01, a01[k]);
          a23[k] = fma2(wv, r23, a23[k]);
        }
      }
    }
    {   // up4 path: channels 8..23
      int y0,y1; float fy; idx_up4(h,128,y0,y1,fy);
      int cm = max(w-1,0), cc = w, cp = min(w+1,127);
      const float* bp = g_x2 + (size_t)n*16*16384;
#pragma unroll
      for (int c=0;c<16;c++){
        const float* p0 = bp + (size_t)c*16384 + y0*128;
        const float* p1 = bp + (size_t)c*16384 + y1*128;
        float vv0 = LERP(p0[cm], p1[cm], fy);
        float vv1 = LERP(p0[cc], p1[cc], fy);
        float vv2 = LERP(p0[cp], p1[cp], fy);
        float sc = sa[8+c], sh = sbb[8+c];
        float r0 = fmaf(sc, LERP(vv0, vv1, 0.625f), sh);
        float r1 = fmaf(sc, LERP(vv0, vv1, 0.875f), sh);
        float r2 = fmaf(sc, LERP(vv1, vv2, 0.125f), sh);
        float r3 = fmaf(sc, LERP(vv1, vv2, 0.375f), sh);
        u64t r01 = pk2(r0,r1), r23 = pk2(r2,r3);
#pragma unroll
        for (int k=0;k<5;k++){
          u64t wv = DW1K(k*24+8+c);
          a01[k] = fma2(wv, r01, a01[k]);
          a23[k] = fma2(wv, r23, a23[k]);
        }
      }
    }
#pragma unroll
    for (int k=0;k<5;k++){
      float4 v;
      upk2(a01[k], v.x, v.y);
      upk2(a23[k], v.z, v.w);
      *(float4*)(out + (size_t)(n*5+k)*HWp + h*512 + 4*w) = v;
    }
  }
}

// ---------------- launch ----------------
extern "C" void kernel_launch(void* const* d_in, const int* in_sizes, int n_in,
                              void* d_out, int out_size){
  (void)in_sizes; (void)n_in; (void)out_size;
  const float* x       = (const float*)d_in[0];
  const float* g_ebn1  = (const float*)d_in[3];
  const float* be_ebn1 = (const float*)d_in[4];
  const float* g_ebn2  = (const float*)d_in[7];
  const float* be_ebn2 = (const float*)d_in[8];
  const float* g_bn1   = (const float*)d_in[13];
  const float* be_bn1  = (const float*)d_in[14];
  const float* g_bn2   = (const float*)d_in[15];
  const float* be_bn2  = (const float*)d_in[16];
  float* out = (float*)d_out;

  // scalar conv1 weights for the fin1cov fold
  cudaMemcpyToSymbolAsync(c_w1, d_in[1], 160*sizeof(float), 0, cudaMemcpyDeviceToDevice, 0);
  cudaMemcpyToSymbolAsync(c_b1, d_in[2],  16*sizeof(float), 0, cudaMemcpyDeviceToDevice, 0);

  // init: zero stats + duplicate packed weights, then D2D into constant
  k_init<<<8,256>>>((const float*)d_in[1],  (const float*)d_in[2],
                    (const float*)d_in[5],  (const float*)d_in[6],
                    (const float*)d_in[9],  (const float*)d_in[10],
                    (const float*)d_in[11], (const float*)d_in[12],
                    (const float*)d_in[17], (const float*)d_in[18]);
  void* pdup = nullptr;
  cudaGetSymbolAddress(&pdup, g_dup);
  cudaMemcpyToSymbolAsync(c_dup, pdup, NDUP*sizeof(u64t), 0, cudaMemcpyDeviceToDevice, 0);

  const int GS2 = 1184;   // occ-2 kernels: 148*8
  const int GS3 = 1332;   // occ-3 kernels: 148*9

  k_cov<<<GS2,256>>>(x);
  k_fused<<<GS2,256>>>(x, g_ebn1, be_ebn1);
  k_varstats<<<16*64,256>>>(g_ebn2, be_ebn2);
  k_conv3a<<<dim3(16,16,16),256>>>(g_ebn2, be_ebn2);
  k_conv3b<<<dim3(8,8,16),256>>>();
  k_upstats<<<GS2,256>>>();
  k_final<<<GS3,256>>>(out, g_bn1, be_bn1, g_bn2, be_bn2);
}

// round 14
// speedup vs baseline: 3.0761x; 1.0106x over previous
#include <cuda_runtime.h>
#include <cuda_fp16.h>
#include <math.h>

// Problem constants
#define NB   16
#define HH   512
#define WW   512
#define HWp  (HH*WW)     // 262144
#define HW2  (HWp/2)     // 131072
#define NHWp (NB*HWp)    // 4194304
#define NHW2 (NB*HW2)    // 2097152

typedef unsigned long long u64t;

// ---------------- packed f32x2 helpers ----------------
__device__ __forceinline__ u64t pk2(float lo, float hi){
  u64t r; asm("mov.b64 %0,{%1,%2};" : "=l"(r) : "f"(lo), "f"(hi)); return r;
}
__device__ __forceinline__ void upk2(u64t v, float& lo, float& hi){
  asm("mov.b64 {%0,%1},%2;" : "=f"(lo), "=f"(hi) : "l"(v));
}
__device__ __forceinline__ u64t fma2(u64t a, u64t b, u64t c){
  u64t d; asm("fma.rn.f32x2 %0,%1,%2,%3;" : "=l"(d) : "l"(a), "l"(b), "l"(c)); return d;
}

// ---------------- constant weights ----------------
__constant__ float c_w1[160];
__constant__ float c_b1[16];
#define NDUP 1965
__constant__ u64t c_dup[NDUP];
#define DW1(i)  c_dup[(i)]
#define DB1(i)  c_dup[160+(i)]
#define DW2(i)  c_dup[176+(i)]
#define DB2(i)  c_dup[432+(i)]
#define DWC1(i) c_dup[448+(i)]
#define DBC1(i) c_dup[664+(i)]
#define DWC2(i) c_dup[672+(i)]
#define DBC2(i) c_dup[1824+(i)]
#define DW1K(i) c_dup[1840+(i)]
#define DB1K(i) c_dup[1960+(i)]

// ---------------- device scratch ----------------
static __device__ __half2 g_th[33554432];  // z2 fp16: [16,16,512,512] as half2 (134 MB)
static __device__ float   g_x1[ 8388608];  // [16, 8,256,256]
static __device__ float   g_x2[ 4194304];  // [16,16,128,128]
static __device__ u64t    g_dup[NDUP];
static __device__ double  g_cov[75];
static __device__ double  g_sum2[16], g_sq2[16];
static __device__ double  g_vsum[NB*16], g_vsq[NB*16];
static __device__ double  g_usum[24], g_usq[24];

__device__ __forceinline__ float sigm(float x){
  return __fdividef(1.0f, 1.0f + __expf(-x));
}

// ---------------- K_init: dup weights + zero accumulators ----------------
__global__ void k_init(const float* __restrict__ w1,  const float* __restrict__ b1,
                       const float* __restrict__ w2,  const float* __restrict__ b2,
                       const float* __restrict__ wc1, const float* __restrict__ bc1,
                       const float* __restrict__ wc2, const float* __restrict__ bc2,
                       const float* __restrict__ w1k, const float* __restrict__ b1k){
  int t = blockIdx.x*blockDim.x + threadIdx.x;
  // zero stats
  if (t < 16){ g_sum2[t]=0.0; g_sq2[t]=0.0; }
  if (t < 24){ g_usum[t]=0.0; g_usq[t]=0.0; }
  if (t < 75){ g_cov[t]=0.0; }
  if (t < 256){ g_vsum[t]=0.0; g_vsq[t]=0.0; }
  // dup weights
  float v; int ok = 1;
  if      (t < 160)  v = w1[t];
  else if (t < 176)  v = b1[t-160];
  else if (t < 432)  v = w2[t-176];
  else if (t < 448)  v = b2[t-432];
  else if (t < 664)  v = wc1[t-448];
  else if (t < 672)  v = bc1[t-664];
  else if (t < 1824) v = wc2[t-672];
  else if (t < 1840) v = bc2[t-1824];
  else if (t < 1960) v = w1k[t-1840];
  else if (t < 1965) v = b1k[t-1960];
  else ok = 0;
  if (ok) g_dup[t] = pk2(v, v);
}

// ---------------- K_cov: covariance stats of x ----------------
__global__ void __launch_bounds__(256,2) k_cov(const float* __restrict__ x){
  __shared__ double sred[75];
  int t = threadIdx.x;
  if (t < 75) sred[t] = 0.0;
  __syncthreads();

  float s[10], pp[55];
#pragma unroll
  for (int i=0;i<10;i++) s[i]=0.f;
#pragma unroll
  for (int k=0;k<55;k++) pp[k]=0.f;

  const float2* X = (const float2*)x;
  int stride = gridDim.x * blockDim.x;
  for (int p = blockIdx.x*blockDim.x + t; p < NHW2; p += stride){
    int n = p >> 17, pix = p & (HW2-1);
    const float2* xp = X + (size_t)n*10*HW2 + pix;
    float2 in[10];
#pragma unroll
    for (int i=0;i<10;i++) in[i] = xp[(size_t)i*HW2];
    int k = 0;
#pragma unroll
    for (int i=0;i<10;i++){
      s[i] += in[i].x + in[i].y;
#pragma unroll
      for (int j=i;j<10;j++){
        pp[k] = fmaf(in[i].x, in[j].x, fmaf(in[i].y, in[j].y, pp[k]));
        k++;
      }
    }
  }
#pragma unroll
  for (int i=0;i<10;i++){
    float a = s[i];
#pragma unroll
    for (int o=16;o>0;o>>=1) a += __shfl_down_sync(0xffffffffu,a,o);
    if ((t&31)==0) atomicAdd(&sred[i], (double)a);
  }
#pragma unroll
  for (int k=0;k<55;k++){
    float a = pp[k];
#pragma unroll
    for (int o=16;o>0;o>>=1) a += __shfl_down_sync(0xffffffffu,a,o);
    if ((t&31)==0) atomicAdd(&sred[10+k], (double)a);
  }
  __syncthreads();
  if (t < 75) atomicAdd(&g_cov[t], sred[t]);
}

// ---------------- K_fused: (BN1 coeffs) + conv1+BN1+sigm+conv2 -> z2(fp16), BN2 stats ----------------
__global__ void __launch_bounds__(256,2) k_fused(const float* __restrict__ x,
                                                 const float* __restrict__ gamma1,
                                                 const float* __restrict__ beta1){
  __shared__ float sa[16], sb[16];
  __shared__ double ssum[16], ssq[16];
  int t = threadIdx.x;
  if (t < 16){
    // fin1cov fold: BN1 coeffs from covariance (identical across blocks)
    double m[10];
#pragma unroll
    for (int i=0;i<10;i++) m[i] = g_cov[i] / (double)NHWp;
    double mean = (double)c_b1[t];
#pragma unroll
    for (int i=0;i<10;i++) mean += (double)c_w1[t*10+i] * m[i];
    double var = 0.0;
    int k = 10;
#pragma unroll
    for (int i=0;i<10;i++){
#pragma unroll
      for (int j=i;j<10;j++){
        double cov = g_cov[k] / (double)NHWp - m[i]*m[j];
        double wp  = (double)c_w1[t*10+i] * (double)c_w1[t*10+j];
        var += (i==j ? 1.0 : 2.0) * wp * cov;
        k++;
      }
    }
    double a = (double)gamma1[t] / sqrt(var + 1e-5);
    sa[t] = (float)a;
    sb[t] = (float)((double)beta1[t] - a*mean);
    ssum[t]=0.0; ssq[t]=0.0;
  }
  __syncthreads();

  float s[16], q[16];
#pragma unroll
  for (int c=0;c<16;c++){ s[c]=0.f; q[c]=0.f; }

  const u64t* X = (const u64t*)x;
  int stride = gridDim.x * blockDim.x;
  for (int p = blockIdx.x*blockDim.x + t; p < NHW2; p += stride){
    int n = p >> 17, pix = p & (HW2-1);
    const u64t* xp = X + (size_t)n*10*HW2 + pix;
    u64t in[10];
#pragma unroll
    for (int i=0;i<10;i++) in[i] = xp[(size_t)i*HW2];

    u64t acc[16];
#pragma unroll
    for (int o=0;o<16;o++) acc[o] = DB2(o);

#pragma unroll
    for (int c=0;c<16;c++){
      u64t z = DB1(c);
#pragma unroll
      for (int i=0;i<10;i++) z = fma2(DW1(c*10+i), in[i], z);
      float zx, zy; upk2(z, zx, zy);
      float ac = sa[c], bc = sb[c];
      float yx = sigm(fmaf(ac, zx, bc));
      float yy = sigm(fmaf(ac, zy, bc));
      u64t y = pk2(yx, yy);
#pragma unroll
      for (int o=0;o<16;o++) acc[o] = fma2(DW2(o*16+c), y, acc[o]);
    }
    __half2* op = g_th + (size_t)n*16*HW2 + pix;
#pragma unroll
    for (int o=0;o<16;o++){
      float ax, ay; upk2(acc[o], ax, ay);
      op[(size_t)o*HW2] = __float22half2_rn(make_float2(ax, ay));
      s[o] += ax + ay;
      q[o] = fmaf(ax, ax, fmaf(ay, ay, q[o]));
    }
  }
#pragma unroll
  for (int c=0;c<16;c++){
    float a=s[c], b=q[c];
#pragma unroll
    for (int o=16;o>0;o>>=1){ a += __shfl_down_sync(0xffffffffu,a,o); b += __shfl_down_sync(0xffffffffu,b,o); }
    if ((t&31)==0){ atomicAdd(&ssum[c],(double)a); atomicAdd(&ssq[c],(double)b); }
  }
  __syncthreads();
  if (t<16){ atomicAdd(&g_sum2[t], ssum[t]); atomicAdd(&g_sq2[t], ssq[t]); }
}

// ---------------- K_varstats: (BN2 coeffs) + per-(n,c) variance of h2 ----------------
__global__ void __launch_bounds__(256,3) k_varstats(const float* __restrict__ gamma2,
                                                    const float* __restrict__ beta2){
  const int BPS = 64;
  int n   = blockIdx.x / BPS;
  int blk = blockIdx.x % BPS;
  __shared__ float sa[16], sb[16];
  __shared__ double ssum[16], ssq[16];
  int t = threadIdx.x;
  if (t < 16){
    double m = g_sum2[t] / (double)NHWp;
    double v = g_sq2[t]  / (double)NHWp - m*m;
    double a = (double)gamma2[t] / sqrt(v + 1e-5);
    sa[t] = (float)a;
    sb[t] = (float)((double)beta2[t] - a*m);
    ssum[t]=0.0; ssq[t]=0.0;
  }
  __syncthreads();

  float s[16], q[16];
#pragma unroll
  for (int c=0;c<16;c++){ s[c]=0.f; q[c]=0.f; }

  const int per = HW2 / BPS;
  const __half2* base = g_th + (size_t)n*16*HW2;
  for (int pix = blk*per + t; pix < (blk+1)*per; pix += 256){
#pragma unroll
    for (int c=0;c<16;c++){
      float2 v = __half22float2(base[(size_t)c*HW2 + pix]);
      float hx = sigm(fmaf(sa[c], v.x, sb[c]));
      float hy = sigm(fmaf(sa[c], v.y, sb[c]));
      s[c] += hx + hy;
      q[c] = fmaf(hx,hx, fmaf(hy,hy,q[c]));
    }
  }
#pragma unroll
  for (int c=0;c<16;c++){
    float a=s[c], b=q[c];
#pragma unroll
    for (int o=16;o>0;o>>=1){ a += __shfl_down_sync(0xffffffffu,a,o); b += __shfl_down_sync(0xffffffffu,b,o); }
    if ((t&31)==0){ atomicAdd(&ssum[c],(double)a); atomicAdd(&ssq[c],(double)b); }
  }
  __syncthreads();
  if (t<16){ atomicAdd(&g_vsum[n*16+t], ssum[t]); atomicAdd(&g_vsq[n*16+t], ssq[t]); }
}

// ---------------- K_conv3a: (BN2 coeffs + top-3) + conv3x3(3->8)+sigm+pool ----------------
__global__ void __launch_bounds__(256,2) k_conv3a(const float* __restrict__ gamma2,
                                                  const float* __restrict__ beta2){
  __shared__ float sp[3][34][36];
  __shared__ float sa16[16], sb16[16];
  __shared__ double svar[16];
  __shared__ int   sidx[3];
  __shared__ float sa[3], sbb[3];
  __shared__ int   sch[3];
  int n = blockIdx.z;
  int t = threadIdx.x;
  if (t < 16){
    double m = g_sum2[t] / (double)NHWp;
    double v = g_sq2[t]  / (double)NHWp - m*m;
    double a = (double)gamma2[t] / sqrt(v + 1e-5);
    sa16[t] = (float)a;
    sb16[t] = (float)((double)beta2[t] - a*m);
    double su = g_vsum[n*16+t], qq = g_vsq[n*16+t];
    double mm = su / (double)HWp;
    svar[t] = (qq - su*mm) / (double)(HWp - 1);
  }
  __syncthreads();
  if (t == 0){
    int mask = 0;
    for (int k=0;k<3;k++){
      int best = 0; double bv = -1e300;
      for (int c=0;c<16;c++)
        if (!((mask>>c)&1) && svar[c] > bv){ bv = svar[c]; best = c; }
      mask |= 1<<best;
      sidx[k] = best;
    }
  }
  __syncthreads();
  if (t < 3){ int ch = sidx[t]; sch[t]=ch; sa[t]=sa16[ch]; sbb[t]=sb16[ch]; }
  __syncthreads();

  const __half* H = (const __half*)g_th;
  int gy0 = blockIdx.y*32 - 1, gx0 = blockIdx.x*32 - 1;
  for (int i=t; i < 3*34*34; i += 256){
    int c = i / 1156, rem = i % 1156;
    int r = rem / 34, col = rem % 34;
    int gy = gy0 + r, gx = gx0 + col;
    float v = 0.f;
    if (gy >= 0 && gy < HH && gx >= 0 && gx < WW)
      v = sigm(fmaf(sa[c], __half2float(H[(size_t)(n*16+sch[c])*HWp + gy*WW + gx]), sbb[c]));
    sp[c][r][col] = v;
  }
  __syncthreads();

  int tx = t & 15, ty = t >> 4;
  int by = 2*ty, bx = 2*tx;
  u64t aA[8], aB[8];
#pragma unroll
  for (int oc=0;oc<8;oc++){ aA[oc]=DBC1(oc); aB[oc]=DBC1(oc); }
#pragma unroll
  for (int c=0;c<3;c++)
#pragma unroll
    for (int ky=0;ky<3;ky++)
#pragma unroll
      for (int kx=0;kx<3;kx++){
        u64t vA = pk2(sp[c][by+ky  ][bx+kx], sp[c][by+ky  ][bx+kx+1]);
        u64t vB = pk2(sp[c][by+ky+1][bx+kx], sp[c][by+ky+1][bx+kx+1]);
#pragma unroll
        for (int oc=0;oc<8;oc++){
          u64t wv = DWC1(oc*27 + c*9 + ky*3 + kx);
          aA[oc] = fma2(wv, vA, aA[oc]);
          aB[oc] = fma2(wv, vB, aB[oc]);
        }
      }
  int py = blockIdx.y*16 + ty, px = blockIdx.x*16 + tx;
#pragma unroll
  for (int oc=0;oc<8;oc++){
    float a00,a01,a10,a11;
    upk2(aA[oc],a00,a01); upk2(aB[oc],a10,a11);
    float mx = fmaxf(fmaxf(a00,a01), fmaxf(a10,a11));
    g_x1[(size_t)(n*8+oc)*65536 + py*256 + px] = sigm(mx);  // sigmoid monotone
  }
}

// ---------------- K_conv3b: conv3x3(8->16)+sigm+pool ----------------
__global__ void __launch_bounds__(256,2) k_conv3b(){
  __shared__ float sp[8][34][36];
  int n = blockIdx.z;
  int t = threadIdx.x;

  int gy0 = blockIdx.y*32 - 1, gx0 = blockIdx.x*32 - 1;
  for (int i=t; i < 8*34*34; i += 256){
    int c = i / 1156, rem = i % 1156;
    int r = rem / 34, col = rem % 34;
    int gy = gy0 + r, gx = gx0 + col;
    float v = 0.f;
    if (gy >= 0 && gy < 256 && gx >= 0 && gx < 256)
      v = g_x1[(size_t)(n*8+c)*65536 + gy*256 + gx];
    sp[c][r][col] = v;
  }
  __syncthreads();

  int tx = t & 15, ty = t >> 4;
  int by = 2*ty, bx = 2*tx;
  u64t aA[16], aB[16];
#pragma unroll
  for (int oc=0;oc<16;oc++){ aA[oc]=DBC2(oc); aB[oc]=DBC2(oc); }
#pragma unroll
  for (int c=0;c<8;c++)
#pragma unroll
    for (int ky=0;ky<3;ky++)
#pragma unroll
      for (int kx=0;kx<3;kx++){
        u64t vA = pk2(sp[c][by+ky  ][bx+kx], sp[c][by+ky  ][bx+kx+1]);
        u64t vB = pk2(sp[c][by+ky+1][bx+kx], sp[c][by+ky+1][bx+kx+1]);
#pragma unroll
        for (int oc=0;oc<16;oc++){
          u64t wv = DWC2(oc*72 + c*9 + ky*3 + kx);
          aA[oc] = fma2(wv, vA, aA[oc]);
          aB[oc] = fma2(wv, vB, aB[oc]);
        }
      }
  int py = blockIdx.y*16 + ty, px = blockIdx.x*16 + tx;
#pragma unroll
  for (int oc=0;oc<16;oc++){
    float a00,a01,a10,a11;
    upk2(aA[oc],a00,a01); upk2(aB[oc],a10,a11);
    float mx = fmaxf(fmaxf(a00,a01), fmaxf(a10,a11));
    g_x2[(size_t)(n*16+oc)*16384 + py*128 + px] = sigm(mx);
  }
}

// ---- vertical index helpers (jax half-pixel bilinear, clamped) ----
__device__ __forceinline__ void idx_up2(int h, int Hin, int& y0, int& y1, float& f){
  y0 = (h >> 1) - ((h & 1) ^ 1);
  f  = (h & 1) ? 0.25f : 0.75f;
  y1 = min(y0 + 1, Hin - 1);
  y0 = max(y0, 0);
}
__device__ __forceinline__ void idx_up4(int h, int Hin, int& y0, int& y1, float& f){
  int m = h & 3;
  y0 = (h >> 2) - (m < 2 ? 1 : 0);
  f  = (m==0) ? 0.625f : (m==1) ? 0.875f : (m==2) ? 0.125f : 0.375f;
  y1 = min(y0 + 1, Hin - 1);
  y0 = max(y0, 0);
}
#define LERP(a,b,f) ((a) + (f)*((b)-(a)))

// sigmoid outputs > 0 and bilinear weights nonneg => relu identity on up paths.

// ---------------- K_upstats: stats of up2(x1) and up4(x2), merged ----------------
__global__ void __launch_bounds__(256,2) k_upstats(){
  __shared__ double ssum[24], ssq[24];
  int t = threadIdx.x;
  if (t < 24){ ssum[t]=0.0; ssq[t]=0.0; }
  __syncthreads();

  float s[24], q[24];
#pragma unroll
  for (int c=0;c<24;c++){ s[c]=0.f; q[c]=0.f; }

  const int NQ = NHWp/4;
  int stride = gridDim.x * blockDim.x;
  for (int p = blockIdx.x*blockDim.x + t; p < NQ; p += stride){
    int n = p >> 16, r = p & 65535;
    int h = r >> 7, w = r & 127;
    {   // up2 path
      int y0,y1; float fy; idx_up2(h,256,y0,y1,fy);
      int c0 = max(2*w-1,0), c1 = 2*w, c2 = 2*w+1, c3 = min(2*w+2,255);
      const float* bp = g_x1 + (size_t)n*8*65536;
#pragma unroll
      for (int c=0;c<8;c++){
        const float* p0 = bp + (size_t)c*65536 + y0*256;
        const float* p1 = bp + (size_t)c*65536 + y1*256;
        float vv0 = LERP(p0[c0], p1[c0], fy);
        float vv1 = LERP(p0[c1], p1[c1], fy);
        float vv2 = LERP(p0[c2], p1[c2], fy);
        float vv3 = LERP(p0[c3], p1[c3], fy);
        float o0 = LERP(vv0, vv1, 0.75f);
        float o1 = LERP(vv1, vv2, 0.25f);
        float o2 = LERP(vv1, vv2, 0.75f);
        float o3 = LERP(vv2, vv3, 0.25f);
        s[c] += (o0+o1) + (o2+o3);
        q[c] = fmaf(o0,o0, fmaf(o1,o1, fmaf(o2,o2, fmaf(o3,o3, q[c]))));
      }
    }
    {   // up4 path
      int y0,y1; float fy; idx_up4(h,128,y0,y1,fy);
      int cm = max(w-1,0), cc = w, cp = min(w+1,127);
      const float* bp = g_x2 + (size_t)n*16*16384;
#pragma unroll
      for (int c=0;c<16;c++){
        const float* p0 = bp + (size_t)c*16384 + y0*128;
        const float* p1 = bp + (size_t)c*16384 + y1*128;
        float vv0 = LERP(p0[cm], p1[cm], fy);
        float vv1 = LERP(p0[cc], p1[cc], fy);
        float vv2 = LERP(p0[cp], p1[cp], fy);
        float o0 = LERP(vv0, vv1, 0.625f);
        float o1 = LERP(vv0, vv1, 0.875f);
        float o2 = LERP(vv1, vv2, 0.125f);
        float o3 = LERP(vv1, vv2, 0.375f);
        s[8+c] += (o0+o1) + (o2+o3);
        q[8+c] = fmaf(o0,o0, fmaf(o1,o1, fmaf(o2,o2, fmaf(o3,o3, q[8+c]))));
      }
    }
  }
#pragma unroll
  for (int c=0;c<24;c++){
    float a=s[c], b=q[c];
#pragma unroll
    for (int o=16;o>0;o>>=1){ a += __shfl_down_sync(0xffffffffu,a,o); b += __shfl_down_sync(0xffffffffu,b,o); }
    if ((t&31)==0){ atomicAdd(&ssum[c],(double)a); atomicAdd(&ssq[c],(double)b); }
  }
  __syncthreads();
  if (t<24){ atomicAdd(&g_usum[t], ssum[t]); atomicAdd(&g_usq[t], ssq[t]); }
}

// ---------------- K_final: (up BN coeffs) + up2/up4 + BN + concat + 1x1 conv ----------------
__global__ void __launch_bounds__(256,3) k_final(float* __restrict__ out,
                                                 const float* __restrict__ gbn1,
                                                 const float* __restrict__ bbn1,
                                                 const float* __restrict__ gbn2,
                                                 const float* __restrict__ bbn2){
  __shared__ float sa[24], sbb[24];
  int t = threadIdx.x;
  if (t < 24){
    double m = g_usum[t] / (double)NHWp;
    double v = g_usq[t]  / (double)NHWp - m*m;
    double gamma = (t < 8) ? (double)gbn2[t] : (double)gbn1[t-8];
    double beta  = (t < 8) ? (double)bbn2[t] : (double)bbn1[t-8];
    double a = gamma / sqrt(v + 1e-5);
    sa[t]  = (float)a;
    sbb[t] = (float)(beta - a*m);
  }
  __syncthreads();

  const int NQ = NHWp/4;
  int stride = gridDim.x * blockDim.x;
  for (int p = blockIdx.x*blockDim.x + t; p < NQ; p += stride){
    int n = p >> 16, r = p & 65535;
    int h = r >> 7, w = r & 127;

    u64t a01[5], a23[5];
#pragma unroll
    for (int k=0;k<5;k++){ a01[k]=DB1K(k); a23[k]=DB1K(k); }

    {   // up2 path: channels 0..7
      int y0,y1; float fy; idx_up2(h,256,y0,y1,fy);
      int c0 = max(2*w-1,0), c1 = 2*w, c2 = 2*w+1, c3 = min(2*w+2,255);
      const float* bp = g_x1 + (size_t)n*8*65536;
#pragma unroll
      for (int c=0;c<8;c++){
        const float* p0 = bp + (size_t)c*65536 + y0*256;
        const float* p1 = bp + (size_t)c*65536 + y1*256;
        float vv0 = LERP(p0[c0], p1[c0], fy);
        float vv1 = LERP(p0[c1], p1[c1], fy);
        float vv2 = LERP(p0[c2], p1[c2], fy);
        float vv3 = LERP(p0[c3], p1[c3], fy);
        float sc = sa[c], sh = sbb[c];
        float r0 = fmaf(sc, LERP(vv0, vv1, 0.75f), sh);
        float r1 = fmaf(sc, LERP(vv1, vv2, 0.25f), sh);
        float r2 = fmaf(sc, LERP(vv1, vv2, 0.75f), sh);
        float r3 = fmaf(sc, LERP(vv2, vv3, 0.25f), sh);
        u64t r01 = pk2(r0,r1), r23 = pk2(r2,r3);
#pragma unroll
        for (int k=0;k<5;k++){
          u64t wv = DW1K(k*24+c);
          a01[k] = fma2(wv, r01, a01[k]);
          a23[k] = fma2(wv, r23, a23[k]);
        }
      }
    }
    {   // up4 path: channels 8..23
      int y0,y1; float fy; idx_up4(h,128,y0,y1,fy);
      int cm = max(w-1,0), cc = w, cp = min(w+1,127);
      const float* bp = g_x2 + (size_t)n*16*16384;
#pragma unroll
      for (int c=0;c<16;c++){
        const float* p0 = bp + (size_t)c*16384 + y0*128;
        const float* p1 = bp + (size_t)c*16384 + y1*128;
        float vv0 = LERP(p0[cm], p1[cm], fy);
        float vv1 = LERP(p0[cc], p1[cc], fy);
        float vv2 = LERP(p0[cp], p1[cp], fy);
        float sc = sa[8+c], sh = sbb[8+c];
        float r0 = fmaf(sc, LERP(vv0, vv1, 0.625f), sh);
        float r1 = fmaf(sc, LERP(vv0, vv1, 0.875f), sh);
        float r2 = fmaf(sc, LERP(vv1, vv2, 0.125f), sh);
        float r3 = fmaf(sc, LERP(vv1, vv2, 0.375f), sh);
        u64t r01 = pk2(r0,r1), r23 = pk2(r2,r3);
#pragma unroll
        for (int k=0;k<5;k++){
          u64t wv = DW1K(k*24+8+c);
          a01[k] = fma2(wv, r01, a01[k]);
          a23[k] = fma2(wv, r23, a23[k]);
        }
      }
    }
#pragma unroll
    for (int k=0;k<5;k++){
      float4 v;
      upk2(a01[k], v.x, v.y);
      upk2(a23[k], v.z, v.w);
      *(float4*)(out + (size_t)(n*5+k)*HWp + h*512 + 4*w) = v;
    }
  }
}

// ---------------- launch ----------------
extern "C" void kernel_launch(void* const* d_in, const int* in_sizes, int n_in,
                              void* d_out, int out_size){
  (void)in_sizes; (void)n_in; (void)out_size;
  const float* x       = (const float*)d_in[0];
  const float* g_ebn1  = (const float*)d_in[3];
  const float* be_ebn1 = (const float*)d_in[4];
  const float* g_ebn2  = (const float*)d_in[7];
  const float* be_ebn2 = (const float*)d_in[8];
  const float* g_bn1   = (const float*)d_in[13];
  const float* be_bn1  = (const float*)d_in[14];
  const float* g_bn2   = (const float*)d_in[15];
  const float* be_bn2  = (const float*)d_in[16];
  float* out = (float*)d_out;

  // scalar conv1 weights for the fin1cov fold
  cudaMemcpyToSymbolAsync(c_w1, d_in[1], 160*sizeof(float), 0, cudaMemcpyDeviceToDevice, 0);
  cudaMemcpyToSymbolAsync(c_b1, d_in[2],  16*sizeof(float), 0, cudaMemcpyDeviceToDevice, 0);

  // init: zero stats + duplicate packed weights, then D2D into constant
  k_init<<<8,256>>>((const float*)d_in[1],  (const float*)d_in[2],
                    (const float*)d_in[5],  (const float*)d_in[6],
                    (const float*)d_in[9],  (const float*)d_in[10],
                    (const float*)d_in[11], (const float*)d_in[12],
                    (const float*)d_in[17], (const float*)d_in[18]);
  void* pdup = nullptr;
  cudaGetSymbolAddress(&pdup, g_dup);
  cudaMemcpyToSymbolAsync(c_dup, pdup, NDUP*sizeof(u64t), 0, cudaMemcpyDeviceToDevice, 0);

  const int GS2 = 1184;   // occ-2 kernels: 148*8
  const int GS3 = 1332;   // occ-3 kernels: 148*9

  k_cov<<<GS2,256>>>(x);
  k_fused<<<GS2,256>>>(x, g_ebn1, be_ebn1);
  k_varstats<<<16*64,256>>>(g_ebn2, be_ebn2);
  k_conv3a<<<dim3(16,16,16),256>>>(g_ebn2, be_ebn2);
  k_conv3b<<<dim3(8,8,16),256>>>();
  k_upstats<<<GS2,256>>>();
  k_final<<<GS3,256>>>(out, g_bn1, be_bn1, g_bn2, be_bn2);
}

// round 15
// speedup vs baseline: 3.5652x; 1.1590x over previous
#include <cuda_runtime.h>
#include <cuda_fp16.h>
#include <math.h>

// Problem constants
#define NB   16
#define HH   512
#define WW   512
#define HWp  (HH*WW)     // 262144
#define HW2  (HWp/2)     // 131072
#define NHWp (NB*HWp)    // 4194304
#define NHW2 (NB*HW2)    // 2097152
#define L2E  1.4426950408889634

typedef unsigned long long u64t;

// ---------------- packed f32x2 helpers ----------------
__device__ __forceinline__ u64t pk2(float lo, float hi){
  u64t r; asm("mov.b64 %0,{%1,%2};" : "=l"(r) : "f"(lo), "f"(hi)); return r;
}
__device__ __forceinline__ void upk2(u64t v, float& lo, float& hi){
  asm("mov.b64 {%0,%1},%2;" : "=f"(lo), "=f"(hi) : "l"(v));
}
__device__ __forceinline__ u64t fma2(u64t a, u64t b, u64t c){
  u64t d; asm("fma.rn.f32x2 %0,%1,%2,%3;" : "=l"(d) : "l"(a), "l"(b), "l"(c)); return d;
}

// ---------------- fast exact-enough sigmoid (EX2 + RCP, constants pre-folded) ----------------
// sigm(x) = 1/(1+exp(-x)) = rcp(1 + ex2(-log2e * x))
__device__ __forceinline__ float sigm(float x){
  float e, r;
  asm("ex2.approx.f32 %0, %1;" : "=f"(e) : "f"(-1.44269504f * x));
  asm("rcp.approx.f32 %0, %1;" : "=f"(r) : "f"(1.0f + e));
  return r;
}
// u already equals -log2e*(a*z+b)
__device__ __forceinline__ float sigm_pre(float u){
  float e, r;
  asm("ex2.approx.f32 %0, %1;" : "=f"(e) : "f"(u));
  asm("rcp.approx.f32 %0, %1;" : "=f"(r) : "f"(1.0f + e));
  return r;
}

// ---------------- constant weights ----------------
__constant__ float c_w1[160];
__constant__ float c_b1[16];
#define NDUP 1965
__constant__ u64t c_dup[NDUP];
#define DW1(i)  c_dup[(i)]
#define DB1(i)  c_dup[160+(i)]
#define DW2(i)  c_dup[176+(i)]
#define DB2(i)  c_dup[432+(i)]
#define DWC1(i) c_dup[448+(i)]
#define DBC1(i) c_dup[664+(i)]
#define DWC2(i) c_dup[672+(i)]
#define DBC2(i) c_dup[1824+(i)]
#define DW1K(i) c_dup[1840+(i)]
#define DB1K(i) c_dup[1960+(i)]

// ---------------- device scratch ----------------
static __device__ __half2 g_th[33554432];  // z2 fp16: [16,16,512,512] as half2 (134 MB)
static __device__ float   g_x1[ 8388608];  // [16, 8,256,256]
static __device__ float   g_x2[ 4194304];  // [16,16,128,128]
static __device__ u64t    g_dup[NDUP];
static __device__ double  g_cov[75];
static __device__ double  g_sum2[16], g_sq2[16];
static __device__ double  g_vsum[NB*16], g_vsq[NB*16];
static __device__ double  g_usum[24], g_usq[24];

// ---------------- K_init: dup weights + zero accumulators ----------------
__global__ void k_init(const float* __restrict__ w1,  const float* __restrict__ b1,
                       const float* __restrict__ w2,  const float* __restrict__ b2,
                       const float* __restrict__ wc1, const float* __restrict__ bc1,
                       const float* __restrict__ wc2, const float* __restrict__ bc2,
                       const float* __restrict__ w1k, const float* __restrict__ b1k){
  int t = blockIdx.x*blockDim.x + threadIdx.x;
  if (t < 16){ g_sum2[t]=0.0; g_sq2[t]=0.0; }
  if (t < 24){ g_usum[t]=0.0; g_usq[t]=0.0; }
  if (t < 75){ g_cov[t]=0.0; }
  float v; int ok = 1;
  if      (t < 160)  v = w1[t];
  else if (t < 176)  v = b1[t-160];
  else if (t < 432)  v = w2[t-176];
  else if (t < 448)  v = b2[t-432];
  else if (t < 664)  v = wc1[t-448];
  else if (t < 672)  v = bc1[t-664];
  else if (t < 1824) v = wc2[t-672];
  else if (t < 1840) v = bc2[t-1824];
  else if (t < 1960) v = w1k[t-1840];
  else if (t < 1965) v = b1k[t-1960];
  else ok = 0;
  if (ok) g_dup[t] = pk2(v, v);
}

// ---------------- K_cov: covariance stats of x ----------------
__global__ void __launch_bounds__(256,2) k_cov(const float* __restrict__ x){
  __shared__ double sred[75];
  int t = threadIdx.x;
  if (t < 75) sred[t] = 0.0;
  __syncthreads();

  float s[10], pp[55];
#pragma unroll
  for (int i=0;i<10;i++) s[i]=0.f;
#pragma unroll
  for (int k=0;k<55;k++) pp[k]=0.f;

  const float2* X = (const float2*)x;
  int stride = gridDim.x * blockDim.x;
  for (int p = blockIdx.x*blockDim.x + t; p < NHW2; p += stride){
    int n = p >> 17, pix = p & (HW2-1);
    const float2* xp = X + (size_t)n*10*HW2 + pix;
    float2 in[10];
#pragma unroll
    for (int i=0;i<10;i++) in[i] = xp[(size_t)i*HW2];
    int k = 0;
#pragma unroll
    for (int i=0;i<10;i++){
      s[i] += in[i].x + in[i].y;
#pragma unroll
      for (int j=i;j<10;j++){
        pp[k] = fmaf(in[i].x, in[j].x, fmaf(in[i].y, in[j].y, pp[k]));
        k++;
      }
    }
  }
#pragma unroll
  for (int i=0;i<10;i++){
    float a = s[i];
#pragma unroll
    for (int o=16;o>0;o>>=1) a += __shfl_down_sync(0xffffffffu,a,o);
    if ((t&31)==0) atomicAdd(&sred[i], (double)a);
  }
#pragma unroll
  for (int k=0;k<55;k++){
    float a = pp[k];
#pragma unroll
    for (int o=16;o>0;o>>=1) a += __shfl_down_sync(0xffffffffu,a,o);
    if ((t&31)==0) atomicAdd(&sred[10+k], (double)a);
  }
  __syncthreads();
  if (t < 75) atomicAdd(&g_cov[t], sred[t]);
}

// ---------------- K_fused: (BN1 coeffs) + conv1+BN1+sigm+conv2 -> z2(fp16), BN2 stats ----------------
__global__ void __launch_bounds__(256,2) k_fused(const float* __restrict__ x,
                                                 const float* __restrict__ gamma1,
                                                 const float* __restrict__ beta1){
  __shared__ float sa[16], sb[16];     // pre-folded: -log2e*a, -log2e*b
  __shared__ double ssum[16], ssq[16];
  int t = threadIdx.x;
  if (t < 16){
    double m[10];
#pragma unroll
    for (int i=0;i<10;i++) m[i] = g_cov[i] / (double)NHWp;
    double mean = (double)c_b1[t];
#pragma unroll
    for (int i=0;i<10;i++) mean += (double)c_w1[t*10+i] * m[i];
    double var = 0.0;
    int k = 10;
#pragma unroll
    for (int i=0;i<10;i++){
#pragma unroll
      for (int j=i;j<10;j++){
        double cov = g_cov[k] / (double)NHWp - m[i]*m[j];
        double wp  = (double)c_w1[t*10+i] * (double)c_w1[t*10+j];
        var += (i==j ? 1.0 : 2.0) * wp * cov;
        k++;
      }
    }
    double a = (double)gamma1[t] / sqrt(var + 1e-5);
    double b = (double)beta1[t] - a*mean;
    sa[t] = (float)(-L2E * a);
    sb[t] = (float)(-L2E * b);
    ssum[t]=0.0; ssq[t]=0.0;
  }
  __syncthreads();

  float s[16], q[16];
#pragma unroll
  for (int c=0;c<16;c++){ s[c]=0.f; q[c]=0.f; }

  const u64t* X = (const u64t*)x;
  int stride = gridDim.x * blockDim.x;
  for (int p = blockIdx.x*blockDim.x + t; p < NHW2; p += stride){
    int n = p >> 17, pix = p & (HW2-1);
    const u64t* xp = X + (size_t)n*10*HW2 + pix;
    u64t in[10];
#pragma unroll
    for (int i=0;i<10;i++) in[i] = xp[(size_t)i*HW2];

    u64t acc[16];
#pragma unroll
    for (int o=0;o<16;o++) acc[o] = DB2(o);

#pragma unroll
    for (int c=0;c<16;c++){
      u64t z = DB1(c);
#pragma unroll
      for (int i=0;i<10;i++) z = fma2(DW1(c*10+i), in[i], z);
      float zx, zy; upk2(z, zx, zy);
      float ac = sa[c], bc = sb[c];
      float yx = sigm_pre(fmaf(ac, zx, bc));
      float yy = sigm_pre(fmaf(ac, zy, bc));
      u64t y = pk2(yx, yy);
#pragma unroll
      for (int o=0;o<16;o++) acc[o] = fma2(DW2(o*16+c), y, acc[o]);
    }
    __half2* op = g_th + (size_t)n*16*HW2 + pix;
#pragma unroll
    for (int o=0;o<16;o++){
      float ax, ay; upk2(acc[o], ax, ay);
      op[(size_t)o*HW2] = __float22half2_rn(make_float2(ax, ay));
      s[o] += ax + ay;
      q[o] = fmaf(ax, ax, fmaf(ay, ay, q[o]));
    }
  }
#pragma unroll
  for (int c=0;c<16;c++){
    float a=s[c], b=q[c];
#pragma unroll
    for (int o=16;o>0;o>>=1){ a += __shfl_down_sync(0xffffffffu,a,o); b += __shfl_down_sync(0xffffffffu,b,o); }
    if ((t&31)==0){ atomicAdd(&ssum[c],(double)a); atomicAdd(&ssq[c],(double)b); }
  }
  __syncthreads();
  if (t<16){ atomicAdd(&g_sum2[t], ssum[t]); atomicAdd(&g_sq2[t], ssq[t]); }
}

// ---------------- K_varstats: one block per (n,c); streaming reduce, no atomics ----------------
__global__ void __launch_bounds__(256) k_varstats(const float* __restrict__ gamma2,
                                                  const float* __restrict__ beta2){
  int bid = blockIdx.x;
  int n = bid >> 4, c = bid & 15;
  int t = threadIdx.x;

  // BN2 coeff for channel c (all threads compute identically; folded for sigm_pre)
  double m = g_sum2[c] / (double)NHWp;
  double v = g_sq2[c]  / (double)NHWp - m*m;
  double a = (double)gamma2[c] / sqrt(v + 1e-5);
  double b = (double)beta2[c] - a*m;
  float ap = (float)(-L2E * a);
  float bp = (float)(-L2E * b);

  const uint2* base = (const uint2*)g_th + (size_t)(n*16+c)*65536;  // 65536 uint2 = 262144 halves
  float s0=0.f,s1=0.f,s2=0.f,s3=0.f, q0=0.f,q1=0.f,q2=0.f,q3=0.f;
#pragma unroll 4
  for (int i = t; i < 65536; i += 256){
    uint2 d = base[i];
    float2 f0 = __half22float2(*(__half2*)&d.x);
    float2 f1 = __half22float2(*(__half2*)&d.y);
    float h0 = sigm_pre(fmaf(ap, f0.x, bp));
    float h1 = sigm_pre(fmaf(ap, f0.y, bp));
    float h2 = sigm_pre(fmaf(ap, f1.x, bp));
    float h3 = sigm_pre(fmaf(ap, f1.y, bp));
    s0 += h0; q0 = fmaf(h0,h0,q0);
    s1 += h1; q1 = fmaf(h1,h1,q1);
    s2 += h2; q2 = fmaf(h2,h2,q2);
    s3 += h3; q3 = fmaf(h3,h3,q3);
  }
  float s = (s0+s1)+(s2+s3);
  float q = (q0+q1)+(q2+q3);
#pragma unroll
  for (int o=16;o>0;o>>=1){ s += __shfl_down_sync(0xffffffffu,s,o); q += __shfl_down_sync(0xffffffffu,q,o); }

  __shared__ double sh_s[8], sh_q[8];
  if ((t&31)==0){ sh_s[t>>5] = (double)s; sh_q[t>>5] = (double)q; }
  __syncthreads();
  if (t==0){
    double S=0.0, Q=0.0;
#pragma unroll
    for (int w=0;w<8;w++){ S += sh_s[w]; Q += sh_q[w]; }
    g_vsum[n*16+c] = S;
    g_vsq [n*16+c] = Q;
  }
}

// ---------------- K_conv3a: (BN2 coeffs + top-3) + conv3x3(3->8)+sigm+pool ----------------
__global__ void __launch_bounds__(256,2) k_conv3a(const float* __restrict__ gamma2,
                                                  const float* __restrict__ beta2){
  __shared__ float sp[3][34][36];
  __shared__ float sa16[16], sb16[16];   // folded -log2e coeffs
  __shared__ double svar[16];
  __shared__ int   sidx[3];
  __shared__ float sa[3], sbb[3];
  __shared__ int   sch[3];
  int n = blockIdx.z;
  int t = threadIdx.x;
  if (t < 16){
    double m = g_sum2[t] / (double)NHWp;
    double v = g_sq2[t]  / (double)NHWp - m*m;
    double a = (double)gamma2[t] / sqrt(v + 1e-5);
    double b = (double)beta2[t] - a*m;
    sa16[t] = (float)(-L2E * a);
    sb16[t] = (float)(-L2E * b);
    double su = g_vsum[n*16+t], qq = g_vsq[n*16+t];
    double mm = su / (double)HWp;
    svar[t] = (qq - su*mm) / (double)(HWp - 1);
  }
  __syncthreads();
  if (t == 0){
    int mask = 0;
    for (int k=0;k<3;k++){
      int best = 0; double bv = -1e300;
      for (int c=0;c<16;c++)
        if (!((mask>>c)&1) && svar[c] > bv){ bv = svar[c]; best = c; }
      mask |= 1<<best;
      sidx[k] = best;
    }
  }
  __syncthreads();
  if (t < 3){ int ch = sidx[t]; sch[t]=ch; sa[t]=sa16[ch]; sbb[t]=sb16[ch]; }
  __syncthreads();

  const __half* H = (const __half*)g_th;
  int gy0 = blockIdx.y*32 - 1, gx0 = blockIdx.x*32 - 1;
  for (int i=t; i < 3*34*34; i += 256){
    int c = i / 1156, rem = i % 1156;
    int r = rem / 34, col = rem % 34;
    int gy = gy0 + r, gx = gx0 + col;
    float v = 0.f;
    if (gy >= 0 && gy < HH && gx >= 0 && gx < WW)
      v = sigm_pre(fmaf(sa[c], __half2float(H[(size_t)(n*16+sch[c])*HWp + gy*WW + gx]), sbb[c]));
    sp[c][r][col] = v;
  }
  __syncthreads();

  int tx = t & 15, ty = t >> 4;
  int by = 2*ty, bx = 2*tx;
  u64t aA[8], aB[8];
#pragma unroll
  for (int oc=0;oc<8;oc++){ aA[oc]=DBC1(oc); aB[oc]=DBC1(oc); }
#pragma unroll
  for (int c=0;c<3;c++)
#pragma unroll
    for (int ky=0;ky<3;ky++)
#pragma unroll
      for (int kx=0;kx<3;kx++){
        u64t vA = pk2(sp[c][by+ky  ][bx+kx], sp[c][by+ky  ][bx+kx+1]);
        u64t vB = pk2(sp[c][by+ky+1][bx+kx], sp[c][by+ky+1][bx+kx+1]);
#pragma unroll
        for (int oc=0;oc<8;oc++){
          u64t wv = DWC1(oc*27 + c*9 + ky*3 + kx);
          aA[oc] = fma2(wv, vA, aA[oc]);
          aB[oc] = fma2(wv, vB, aB[oc]);
        }
      }
  int py = blockIdx.y*16 + ty, px = blockIdx.x*16 + tx;
#pragma unroll
  for (int oc=0;oc<8;oc++){
    float a00,a01,a10,a11;
    upk2(aA[oc],a00,a01); upk2(aB[oc],a10,a11);
    float mx = fmaxf(fmaxf(a00,a01), fmaxf(a10,a11));
    g_x1[(size_t)(n*8+oc)*65536 + py*256 + px] = sigm(mx);  // sigmoid monotone
  }
}

// ---------------- K_conv3b: conv3x3(8->16)+sigm+pool ----------------
__global__ void __launch_bounds__(256,2) k_conv3b(){
  __shared__ float sp[8][34][36];
  int n = blockIdx.z;
  int t = threadIdx.x;

  int gy0 = blockIdx.y*32 - 1, gx0 = blockIdx.x*32 - 1;
  for (int i=t; i < 8*34*34; i += 256){
    int c = i / 1156, rem = i % 1156;
    int r = rem / 34, col = rem % 34;
    int gy = gy0 + r, gx = gx0 + col;
    float v = 0.f;
    if (gy >= 0 && gy < 256 && gx >= 0 && gx < 256)
      v = g_x1[(size_t)(n*8+c)*65536 + gy*256 + gx];
    sp[c][r][col] = v;
  }
  __syncthreads();

  int tx = t & 15, ty = t >> 4;
  int by = 2*ty, bx = 2*tx;
  u64t aA[16], aB[16];
#pragma unroll
  for (int oc=0;oc<16;oc++){ aA[oc]=DBC2(oc); aB[oc]=DBC2(oc); }
#pragma unroll
  for (int c=0;c<8;c++)
#pragma unroll
    for (int ky=0;ky<3;ky++)
#pragma unroll
      for (int kx=0;kx<3;kx++){
        u64t vA = pk2(sp[c][by+ky  ][bx+kx], sp[c][by+ky  ][bx+kx+1]);
        u64t vB = pk2(sp[c][by+ky+1][bx+kx], sp[c][by+ky+1][bx+kx+1]);
#pragma unroll
        for (int oc=0;oc<16;oc++){
          u64t wv = DWC2(oc*72 + c*9 + ky*3 + kx);
          aA[oc] = fma2(wv, vA, aA[oc]);
          aB[oc] = fma2(wv, vB, aB[oc]);
        }
      }
  int py = blockIdx.y*16 + ty, px = blockIdx.x*16 + tx;
#pragma unroll
  for (int oc=0;oc<16;oc++){
    float a00,a01,a10,a11;
    upk2(aA[oc],a00,a01); upk2(aB[oc],a10,a11);
    float mx = fmaxf(fmaxf(a00,a01), fmaxf(a10,a11));
    g_x2[(size_t)(n*16+oc)*16384 + py*128 + px] = sigm(mx);
  }
}

// ---- vertical index helpers (jax half-pixel bilinear, clamped) ----
__device__ __forceinline__ void idx_up2(int h, int Hin, int& y0, int& y1, float& f){
  y0 = (h >> 1) - ((h & 1) ^ 1);
  f  = (h & 1) ? 0.25f : 0.75f;
  y1 = min(y0 + 1, Hin - 1);
  y0 = max(y0, 0);
}
__device__ __forceinline__ void idx_up4(int h, int Hin, int& y0, int& y1, float& f){
  int m = h & 3;
  y0 = (h >> 2) - (m < 2 ? 1 : 0);
  f  = (m==0) ? 0.625f : (m==1) ? 0.875f : (m==2) ? 0.125f : 0.375f;
  y1 = min(y0 + 1, Hin - 1);
  y0 = max(y0, 0);
}
#define LERP(a,b,f) ((a) + (f)*((b)-(a)))

// sigmoid outputs > 0 and bilinear weights nonneg => relu identity on up paths.

// ---------------- K_upstats: stats of up2(x1) and up4(x2), merged ----------------
__global__ void __launch_bounds__(256,2) k_upstats(){
  __shared__ double ssum[24], ssq[24];
  int t = threadIdx.x;
  if (t < 24){ ssum[t]=0.0; ssq[t]=0.0; }
  __syncthreads();

  float s[24], q[24];
#pragma unroll
  for (int c=0;c<24;c++){ s[c]=0.f; q[c]=0.f; }

  const int NQ = NHWp/4;
  int stride = gridDim.x * blockDim.x;
  for (int p = blockIdx.x*blockDim.x + t; p < NQ; p += stride){
    int n = p >> 16, r = p & 65535;
    int h = r >> 7, w = r & 127;
    {   // up2 path
      int y0,y1; float fy; idx_up2(h,256,y0,y1,fy);
      int c0 = max(2*w-1,0), c1 = 2*w, c2 = 2*w+1, c3 = min(2*w+2,255);
      const float* bp = g_x1 + (size_t)n*8*65536;
#pragma unroll
      for (int c=0;c<8;c++){
        const float* p0 = bp + (size_t)c*65536 + y0*256;
        const float* p1 = bp + (size_t)c*65536 + y1*256;
        float vv0 = LERP(p0[c0], p1[c0], fy);
        float vv1 = LERP(p0[c1], p1[c1], fy);
        float vv2 = LERP(p0[c2], p1[c2], fy);
        float vv3 = LERP(p0[c3], p1[c3], fy);
        float o0 = LERP(vv0, vv1, 0.75f);
        float o1 = LERP(vv1, vv2, 0.25f);
        float o2 = LERP(vv1, vv2, 0.75f);
        float o3 = LERP(vv2, vv3, 0.25f);
        s[c] += (o0+o1) + (o2+o3);
        q[c] = fmaf(o0,o0, fmaf(o1,o1, fmaf(o2,o2, fmaf(o3,o3, q[c]))));
      }
    }
    {   // up4 path
      int y0,y1; float fy; idx_up4(h,128,y0,y1,fy);
      int cm = max(w-1,0), cc = w, cp = min(w+1,127);
      const float* bp = g_x2 + (size_t)n*16*16384;
#pragma unroll
      for (int c=0;c<16;c++){
        const float* p0 = bp + (size_t)c*16384 + y0*128;
        const float* p1 = bp + (size_t)c*16384 + y1*128;
        float vv0 = LERP(p0[cm], p1[cm], fy);
        float vv1 = LERP(p0[cc], p1[cc], fy);
        float vv2 = LERP(p0[cp], p1[cp], fy);
        float o0 = LERP(vv0, vv1, 0.625f);
        float o1 = LERP(vv0, vv1, 0.875f);
        float o2 = LERP(vv1, vv2, 0.125f);
        float o3 = LERP(vv1, vv2, 0.375f);
        s[8+c] += (o0+o1) + (o2+o3);
        q[8+c] = fmaf(o0,o0, fmaf(o1,o1, fmaf(o2,o2, fmaf(o3,o3, q[8+c]))));
      }
    }
  }
#pragma unroll
  for (int c=0;c<24;c++){
    float a=s[c], b=q[c];
#pragma unroll
    for (int o=16;o>0;o>>=1){ a += __shfl_down_sync(0xffffffffu,a,o); b += __shfl_down_sync(0xffffffffu,b,o); }
    if ((t&31)==0){ atomicAdd(&ssum[c],(double)a); atomicAdd(&ssq[c],(double)b); }
  }
  __syncthreads();
  if (t<24){ atomicAdd(&g_usum[t], ssum[t]); atomicAdd(&g_usq[t], ssq[t]); }
}

// ---------------- K_final: (up BN coeffs) + up2/up4 + BN + concat + 1x1 conv ----------------
__global__ void __launch_bounds__(256,3) k_final(float* __restrict__ out,
                                                 const float* __restrict__ gbn1,
                                                 const float* __restrict__ bbn1,
                                                 const float* __restrict__ gbn2,
                                                 const float* __restrict__ bbn2){
  __shared__ float sa[24], sbb[24];
  int t = threadIdx.x;
  if (t < 24){
    double m = g_usum[t] / (double)NHWp;
    double v = g_usq[t]  / (double)NHWp - m*m;
    double gamma = (t < 8) ? (double)gbn2[t] : (double)gbn1[t-8];
    double beta  = (t < 8) ? (double)bbn2[t] : (double)bbn1[t-8];
    double a = gamma / sqrt(v + 1e-5);
    sa[t]  = (float)a;
    sbb[t] = (float)(beta - a*m);
  }
  __syncthreads();

  const int NQ = NHWp/4;
  int stride = gridDim.x * blockDim.x;
  for (int p = blockIdx.x*blockDim.x + t; p < NQ; p += stride){
    int n = p >> 16, r = p & 65535;
    int h = r >> 7, w = r & 127;

    u64t a01[5], a23[5];
#pragma unroll
    for (int k=0;k<5;k++){ a01[k]=DB1K(k); a23[k]=DB1K(k); }

    {   // up2 path: channels 0..7
      int y0,y1; float fy; idx_up2(h,256,y0,y1,fy);
      int c0 = max(2*w-1,0), c1 = 2*w, c2 = 2*w+1, c3 = min(2*w+2,255);
      const float* bp = g_x1 + (size_t)n*8*65536;
#pragma unroll
      for (int c=0;c<8;c++){
        const float* p0 = bp + (size_t)c*65536 + y0*256;
        const float* p1 = bp + (size_t)c*65536 + y1*256;
        float vv0 = LERP(p0[c0], p1[c0], fy);
        float vv1 = LERP(p0[c1], p1[c1], fy);
        float vv2 = LERP(p0[c2], p1[c2], fy);
        float vv3 = LERP(p0[c3], p1[c3], fy);
        float sc = sa[c], sh = sbb[c];
        float r0 = fmaf(sc, LERP(vv0, vv1, 0.75f), sh);
        float r1 = fmaf(sc, LERP(vv1, vv2, 0.25f), sh);
        float r2 = fmaf(sc, LERP(vv1, vv2, 0.75f), sh);
        float r3 = fmaf(sc, LERP(vv2, vv3, 0.25f), sh);
        u64t r01 = pk2(r0,r1), r23 = pk2(r2,r3);
#pragma unroll
        for (int k=0;k<5;k++){
          u64t wv = DW1K(k*24+c);
          a01[k] = fma2(wv, r01, a01[k]);
          a23[k] = fma2(wv, r23, a23[k]);
        }
      }
    }
    {   // up4 path: channels 8..23
      int y0,y1; float fy; idx_up4(h,128,y0,y1,fy);
      int cm = max(w-1,0), cc = w, cp = min(w+1,127);
      const float* bp = g_x2 + (size_t)n*16*16384;
#pragma unroll
      for (int c=0;c<16;c++){
        const float* p0 = bp + (size_t)c*16384 + y0*128;
        const float* p1 = bp + (size_t)c*16384 + y1*128;
        float vv0 = LERP(p0[cm], p1[cm], fy);
        float vv1 = LERP(p0[cc], p1[cc], fy);
        float vv2 = LERP(p0[cp], p1[cp], fy);
        float sc = sa[8+c], sh = sbb[8+c];
        float r0 = fmaf(sc, LERP(vv0, vv1, 0.625f), sh);
        float r1 = fmaf(sc, LERP(vv0, vv1, 0.875f), sh);
        float r2 = fmaf(sc, LERP(vv1, vv2, 0.125f), sh);
        float r3 = fmaf(sc, LERP(vv1, vv2, 0.375f), sh);
        u64t r01 = pk2(r0,r1), r23 = pk2(r2,r3);
#pragma unroll
        for (int k=0;k<5;k++){
          u64t wv = DW1K(k*24+8+c);
          a01[k] = fma2(wv, r01, a01[k]);
          a23[k] = fma2(wv, r23, a23[k]);
        }
      }
    }
#pragma unroll
    for (int k=0;k<5;k++){
      float4 v;
      upk2(a01[k], v.x, v.y);
      upk2(a23[k], v.z, v.w);
      *(float4*)(out + (size_t)(n*5+k)*HWp + h*512 + 4*w) = v;
    }
  }
}

// ---------------- launch ----------------
extern "C" void kernel_launch(void* const* d_in, const int* in_sizes, int n_in,
                              void* d_out, int out_size){
  (void)in_sizes; (void)n_in; (void)out_size;
  const float* x       = (const float*)d_in[0];
  const float* g_ebn1  = (const float*)d_in[3];
  const float* be_ebn1 = (const float*)d_in[4];
  const float* g_ebn2  = (const float*)d_in[7];
  const float* be_ebn2 = (const float*)d_in[8];
  const float* g_bn1   = (const float*)d_in[13];
  const float* be_bn1  = (const float*)d_in[14];
  const float* g_bn2   = (const float*)d_in[15];
  const float* be_bn2  = (const float*)d_in[16];
  float* out = (float*)d_out;

  cudaMemcpyToSymbolAsync(c_w1, d_in[1], 160*sizeof(float), 0, cudaMemcpyDeviceToDevice, 0);
  cudaMemcpyToSymbolAsync(c_b1, d_in[2],  16*sizeof(float), 0, cudaMemcpyDeviceToDevice, 0);

  k_init<<<8,256>>>((const float*)d_in[1],  (const float*)d_in[2],
                    (const float*)d_in[5],  (const float*)d_in[6],
                    (const float*)d_in[9],  (const float*)d_in[10],
                    (const float*)d_in[11], (const float*)d_in[12],
                    (const float*)d_in[17], (const float*)d_in[18]);
  void* pdup = nullptr;
  cudaGetSymbolAddress(&pdup, g_dup);
  cudaMemcpyToSymbolAsync(c_dup, pdup, NDUP*sizeof(u64t), 0, cudaMemcpyDeviceToDevice, 0);

  const int GS2 = 1184;   // occ-2 kernels: 148*8
  const int GS3 = 1332;   // occ-3 kernels: 148*9

  k_cov<<<GS2,256>>>(x);
  k_fused<<<GS2,256>>>(x, g_ebn1, be_ebn1);
  k_varstats<<<256,256>>>(g_ebn2, be_ebn2);
  k_conv3a<<<dim3(16,16,16),256>>>(g_ebn2, be_ebn2);
  k_conv3b<<<dim3(8,8,16),256>>>();
  k_upstats<<<GS2,256>>>();
  k_final<<<GS3,256>>>(out, g_bn1, be_bn1, g_bn2, be_bn2);
}